// round 2
// baseline (speedup 1.0000x reference)
#include <cuda_runtime.h>
#include <cuda_bf16.h>
#include <math_constants.h>

// Problem constants
#define NN   256    // actors
#define CC   512    // channels
#define TT   4
#define HH   8
#define WW   8
#define HWW  64
#define THW  256    // T*H*W locations
#define NCTHW 33554432   // N*C*T*H*W

// ---------------------------------------------------------------------------
// Scratch (static __device__ arrays — no allocation allowed)
// q/k/v in loc-major layout: [(loc*256 + n)*512 + c]  (loc = t*64 + h*8 + w)
// att in loc-major:          [(loc*256 + i)*256 + j]
// virt / virt_act standard:  [(n*512 + c)*256 + loc]
// ---------------------------------------------------------------------------
__device__ float g_qA[NCTHW];
__device__ float g_kA[NCTHW];
__device__ float g_vA[NCTHW];
__device__ float g_att[THW * NN * NN];
__device__ float g_virt[NCTHW];
__device__ float g_vact[NCTHW];

// ---------------------------------------------------------------------------
// Kernel 1: fused q/k/v 1x3x3 conv.
// grid.x = n*t (1024), grid.y = 12 (4 co-tiles x {q,k,v})
// Block 256 threads computes out[128 co x 64 positions] for one (n,t).
// K loop over ci in chunks of 8 (x-slice + weight chunk staged in smem).
// Thread = (pg 0..15 position-group of 4, cog 0..15), regs: 8 co x 4 pos.
// ---------------------------------------------------------------------------
__global__ __launch_bounds__(256) void conv_qkv_kernel(
    const float* __restrict__ x,
    const float* __restrict__ Wq,
    const float* __restrict__ Wk,
    const float* __restrict__ Wv)
{
    __shared__ float xs[8][10][10];   // padded input slice chunk
    __shared__ float ws[128][73];     // 8 ci * 9 taps = 72, pad to 73 (bank-safe)

    const int nt = blockIdx.x;
    const int n  = nt >> 2;
    const int t  = nt & 3;
    const int cob   = blockIdx.y;        // 0..11
    const int which = cob >> 2;          // 0=q 1=k 2=v
    const int co_base = (cob & 3) * 128;

    const float* __restrict__ Wp = (which == 0) ? Wq : (which == 1) ? Wk : Wv;
    float* __restrict__ outp     = (which == 0) ? g_qA : (which == 1) ? g_kA : g_vA;

    const int tid = threadIdx.x;
    const int pg  = tid >> 4;            // 0..15
    const int cog = tid & 15;            // 0..15
    const int h     = pg >> 1;           // 0..7
    const int wbase = (pg & 1) * 4;      // 0 or 4

    float acc[8][4];
#pragma unroll
    for (int j = 0; j < 8; j++)
#pragma unroll
        for (int pp = 0; pp < 4; pp++) acc[j][pp] = 0.f;

    const float* __restrict__ xbase = x + (size_t)n * CC * THW + t * HWW;
    const float* __restrict__ wbase_p = Wp + (size_t)co_base * (CC * 9);

    for (int ci0 = 0; ci0 < CC; ci0 += 8) {
        // stage padded x slice chunk [8][10][10]
        for (int idx = tid; idx < 800; idx += 256) {
            int i = idx / 100;
            int r = (idx % 100) / 10;
            int c = idx % 10;
            int hh = r - 1, ww = c - 1;
            float v = 0.f;
            if (hh >= 0 && hh < 8 && ww >= 0 && ww < 8)
                v = xbase[(size_t)(ci0 + i) * THW + hh * 8 + ww];
            xs[i][r][c] = v;
        }
        // stage weight chunk [128 co][72]
        for (int idx = tid; idx < 128 * 72; idx += 256) {
            int co = idx / 72;
            int q  = idx % 72;   // ii*9 + k9
            ws[co][q] = wbase_p[(size_t)co * (CC * 9) + (size_t)ci0 * 9 + q];
        }
        __syncthreads();

#pragma unroll
        for (int i = 0; i < 8; i++) {
#pragma unroll
            for (int k9 = 0; k9 < 9; k9++) {
                const int kh = k9 / 3, kw = k9 % 3;
                float xv0 = xs[i][h + kh][wbase + 0 + kw];
                float xv1 = xs[i][h + kh][wbase + 1 + kw];
                float xv2 = xs[i][h + kh][wbase + 2 + kw];
                float xv3 = xs[i][h + kh][wbase + 3 + kw];
#pragma unroll
                for (int j = 0; j < 8; j++) {
                    float wv = ws[cog + 16 * j][i * 9 + k9];
                    acc[j][0] += wv * xv0;
                    acc[j][1] += wv * xv1;
                    acc[j][2] += wv * xv2;
                    acc[j][3] += wv * xv3;
                }
            }
        }
        __syncthreads();
    }

    // write loc-major layout
#pragma unroll
    for (int j = 0; j < 8; j++) {
        const int co = co_base + cog + 16 * j;
#pragma unroll
        for (int pp = 0; pp < 4; pp++) {
            const int p   = pg * 4 + pp;
            const int loc = t * HWW + p;
            outp[((size_t)loc * NN + n) * CC + co] = acc[j][pp];
        }
    }
}

// ---------------------------------------------------------------------------
// Kernel 2: attention scores + group mask + softmax.
// grid.x = loc (256), grid.y = i-tile (4, 64 rows each). Block 256.
// Thread = (ig 0..7, jg 0..31); regs acc[8 ii][8 jj]; i = ib+ig+8*ii, j = jg+32*jj.
// Row softmax is warp-local (warp ig owns its 8 rows fully).
// ---------------------------------------------------------------------------
__global__ __launch_bounds__(256) void att_scores_kernel(const int* __restrict__ roi)
{
    __shared__ float qs[64][33];
    __shared__ float ks[256][33];
    __shared__ int   roi_s[256];

    const int loc = blockIdx.x;
    const int ib  = blockIdx.y * 64;
    const int tid = threadIdx.x;
    const int ig  = tid >> 5;   // 0..7
    const int jg  = tid & 31;   // 0..31

    if (tid < 256) roi_s[tid] = roi[tid];

    float acc[8][8];
#pragma unroll
    for (int ii = 0; ii < 8; ii++)
#pragma unroll
        for (int jj = 0; jj < 8; jj++) acc[ii][jj] = 0.f;

    for (int c0 = 0; c0 < CC; c0 += 32) {
        for (int idx = tid; idx < 64 * 32; idx += 256) {
            int i = idx >> 5, c = idx & 31;
            qs[i][c] = g_qA[((size_t)loc * NN + ib + i) * CC + c0 + c];
        }
        for (int idx = tid; idx < 256 * 32; idx += 256) {
            int j = idx >> 5, c = idx & 31;
            ks[j][c] = g_kA[((size_t)loc * NN + j) * CC + c0 + c];
        }
        __syncthreads();

#pragma unroll 4
        for (int c = 0; c < 32; c++) {
            float kv[8];
#pragma unroll
            for (int jj = 0; jj < 8; jj++) kv[jj] = ks[jg + 32 * jj][c];
#pragma unroll
            for (int ii = 0; ii < 8; ii++) {
                float qv = qs[ig + 8 * ii][c];
#pragma unroll
                for (int jj = 0; jj < 8; jj++) acc[ii][jj] += qv * kv[jj];
            }
        }
        __syncthreads();
    }

    const float scale = 0.044194173824159216f;   // 1/sqrt(512)

#pragma unroll
    for (int ii = 0; ii < 8; ii++) {
        const int i  = ib + ig + 8 * ii;
        const int ri = roi_s[i];
        float e[8];
        float m = -CUDART_INF_F;
#pragma unroll
        for (int jj = 0; jj < 8; jj++) {
            const int j = jg + 32 * jj;
            float v = (roi_s[j] == ri) ? acc[ii][jj] * scale : -CUDART_INF_F;
            e[jj] = v;
            m = fmaxf(m, v);
        }
#pragma unroll
        for (int off = 16; off > 0; off >>= 1)
            m = fmaxf(m, __shfl_xor_sync(0xffffffffu, m, off));
        float s = 0.f;
#pragma unroll
        for (int jj = 0; jj < 8; jj++) { float t_ = __expf(e[jj] - m); e[jj] = t_; s += t_; }
#pragma unroll
        for (int off = 16; off > 0; off >>= 1)
            s += __shfl_xor_sync(0xffffffffu, s, off);
        const float inv = 1.f / s;
#pragma unroll
        for (int jj = 0; jj < 8; jj++)
            g_att[((size_t)loc * NN + i) * NN + jg + 32 * jj] = e[jj] * inv;
    }
}

// ---------------------------------------------------------------------------
// Kernel 3: virt = att @ v per location.
// grid.x = loc (256), grid.y = 16 (8 i-tiles of 32 x 2 c-tiles of 256). Block 256.
// Thread = (ig 0..7, cg 0..31); regs acc[4 ii][8 cc]; i = ib+ig+8*ii, c = cb+cg+32*cc.
// Writes virt in standard [n,c,loc] layout (scattered 4B — ~0.15 ms penalty, accepted).
// ---------------------------------------------------------------------------
__global__ __launch_bounds__(256) void att_apply_kernel()
{
    __shared__ float as[32][33];
    __shared__ float vs[32][256];

    const int loc = blockIdx.x;
    const int it  = blockIdx.y >> 1;     // 0..7
    const int ct  = blockIdx.y & 1;      // 0..1
    const int ib  = it * 32;
    const int cb  = ct * 256;
    const int tid = threadIdx.x;
    const int ig  = tid >> 5;
    const int cg  = tid & 31;

    float acc[4][8];
#pragma unroll
    for (int ii = 0; ii < 4; ii++)
#pragma unroll
        for (int cc = 0; cc < 8; cc++) acc[ii][cc] = 0.f;

    for (int j0 = 0; j0 < NN; j0 += 32) {
        for (int idx = tid; idx < 32 * 32; idx += 256) {
            int i = idx >> 5, j = idx & 31;
            as[i][j] = g_att[((size_t)loc * NN + ib + i) * NN + j0 + j];
        }
        for (int idx = tid; idx < 32 * 256; idx += 256) {
            int j = idx >> 8, c = idx & 255;
            vs[j][c] = g_vA[((size_t)loc * NN + j0 + j) * CC + cb + c];
        }
        __syncthreads();

#pragma unroll 4
        for (int j = 0; j < 32; j++) {
            float vv[8];
#pragma unroll
            for (int cc = 0; cc < 8; cc++) vv[cc] = vs[j][cg + 32 * cc];
#pragma unroll
            for (int ii = 0; ii < 4; ii++) {
                float av = as[ig + 8 * ii][j];
#pragma unroll
                for (int cc = 0; cc < 8; cc++) acc[ii][cc] += av * vv[cc];
            }
        }
        __syncthreads();
    }

#pragma unroll
    for (int ii = 0; ii < 4; ii++) {
        const int i = ib + ig + 8 * ii;
#pragma unroll
        for (int cc = 0; cc < 8; cc++) {
            const int c = cb + cg + 32 * cc;
            g_virt[((size_t)i * CC + c) * THW + loc] = acc[ii][cc];
        }
    }
}

// ---------------------------------------------------------------------------
// Kernel 4: GroupNorm(num_groups=1) + affine + ReLU per sample.
// grid = 256 samples, block 256.
// ---------------------------------------------------------------------------
__global__ __launch_bounds__(256) void gn_relu_kernel(
    const float* __restrict__ gamma, const float* __restrict__ beta)
{
    __shared__ float red[18];
    const int n   = blockIdx.x;
    const int tid = threadIdx.x;
    const float* __restrict__ src = g_virt + (size_t)n * CC * THW;
    float* __restrict__ dst       = g_vact + (size_t)n * CC * THW;

    float s = 0.f, s2 = 0.f;
    for (int idx = tid; idx < CC * THW; idx += 256) {
        float v = src[idx];
        s += v; s2 += v * v;
    }
#pragma unroll
    for (int off = 16; off > 0; off >>= 1) {
        s  += __shfl_xor_sync(0xffffffffu, s,  off);
        s2 += __shfl_xor_sync(0xffffffffu, s2, off);
    }
    const int wid = tid >> 5, lane = tid & 31;
    if (lane == 0) { red[wid] = s; red[8 + wid] = s2; }
    __syncthreads();
    if (tid == 0) {
        float S = 0.f, S2 = 0.f;
#pragma unroll
        for (int w = 0; w < 8; w++) { S += red[w]; S2 += red[8 + w]; }
        const float M   = (float)(CC * THW);
        float mu  = S / M;
        float var = S2 / M - mu * mu;
        red[16] = mu;
        red[17] = rsqrtf(var + 1e-5f);
    }
    __syncthreads();
    const float mu = red[16], rinv = red[17];

    for (int idx = tid; idx < CC * THW; idx += 256) {
        const int c = idx >> 8;   // idx = c*256 + loc
        float v = (src[idx] - mu) * rinv * gamma[c] + beta[c];
        dst[idx] = fmaxf(v, 0.f);
    }
}

// ---------------------------------------------------------------------------
// Kernel 5: final conv (Wc) on virt_act + residual add -> d_out (standard layout).
// Same structure as conv_qkv but single weight set, 4 co-tiles.
// ---------------------------------------------------------------------------
__global__ __launch_bounds__(256) void conv_c_kernel(
    const float* __restrict__ x,
    const float* __restrict__ Wc,
    float* __restrict__ out)
{
    __shared__ float xs[8][10][10];
    __shared__ float ws[128][73];

    const int nt = blockIdx.x;
    const int n  = nt >> 2;
    const int t  = nt & 3;
    const int co_base = blockIdx.y * 128;

    const int tid = threadIdx.x;
    const int pg  = tid >> 4;
    const int cog = tid & 15;
    const int h     = pg >> 1;
    const int wbase = (pg & 1) * 4;

    float acc[8][4];
#pragma unroll
    for (int j = 0; j < 8; j++)
#pragma unroll
        for (int pp = 0; pp < 4; pp++) acc[j][pp] = 0.f;

    const float* __restrict__ vbase  = g_vact + (size_t)n * CC * THW + t * HWW;
    const float* __restrict__ wb     = Wc + (size_t)co_base * (CC * 9);

    for (int ci0 = 0; ci0 < CC; ci0 += 8) {
        for (int idx = tid; idx < 800; idx += 256) {
            int i = idx / 100;
            int r = (idx % 100) / 10;
            int c = idx % 10;
            int hh = r - 1, ww = c - 1;
            float v = 0.f;
            if (hh >= 0 && hh < 8 && ww >= 0 && ww < 8)
                v = vbase[(size_t)(ci0 + i) * THW + hh * 8 + ww];
            xs[i][r][c] = v;
        }
        for (int idx = tid; idx < 128 * 72; idx += 256) {
            int co = idx / 72;
            int q  = idx % 72;
            ws[co][q] = wb[(size_t)co * (CC * 9) + (size_t)ci0 * 9 + q];
        }
        __syncthreads();

#pragma unroll
        for (int i = 0; i < 8; i++) {
#pragma unroll
            for (int k9 = 0; k9 < 9; k9++) {
                const int kh = k9 / 3, kw = k9 % 3;
                float xv0 = xs[i][h + kh][wbase + 0 + kw];
                float xv1 = xs[i][h + kh][wbase + 1 + kw];
                float xv2 = xs[i][h + kh][wbase + 2 + kw];
                float xv3 = xs[i][h + kh][wbase + 3 + kw];
#pragma unroll
                for (int j = 0; j < 8; j++) {
                    float wv = ws[cog + 16 * j][i * 9 + k9];
                    acc[j][0] += wv * xv0;
                    acc[j][1] += wv * xv1;
                    acc[j][2] += wv * xv2;
                    acc[j][3] += wv * xv3;
                }
            }
        }
        __syncthreads();
    }

#pragma unroll
    for (int j = 0; j < 8; j++) {
        const int co = co_base + cog + 16 * j;
#pragma unroll
        for (int pp = 0; pp < 4; pp++) {
            const int p = pg * 4 + pp;
            const size_t idx = ((size_t)n * CC + co) * THW + t * HWW + p;
            out[idx] = x[idx] + acc[j][pp];
        }
    }
}

// ---------------------------------------------------------------------------
extern "C" void kernel_launch(void* const* d_in, const int* in_sizes, int n_in,
                              void* d_out, int out_size)
{
    const float* x     = (const float*)d_in[0];
    const int*   roi   = (const int*)  d_in[1];
    const float* Wq    = (const float*)d_in[2];
    const float* Wk    = (const float*)d_in[3];
    const float* Wv    = (const float*)d_in[4];
    const float* Wc    = (const float*)d_in[5];
    const float* gamma = (const float*)d_in[6];
    const float* beta  = (const float*)d_in[7];
    float* out = (float*)d_out;

    conv_qkv_kernel<<<dim3(1024, 12), 256>>>(x, Wq, Wk, Wv);
    att_scores_kernel<<<dim3(256, 4), 256>>>(roi);
    att_apply_kernel<<<dim3(256, 16), 256>>>();
    gn_relu_kernel<<<256, 256>>>(gamma, beta);
    conv_c_kernel<<<dim3(1024, 4), 256>>>(x, Wc, out);
}

// round 5
// speedup vs baseline: 2.4360x; 2.4360x over previous
#include <cuda_runtime.h>
#include <cuda_bf16.h>
#include <math_constants.h>
#include <cstdint>

// Problem constants
#define NN    256
#define CC    512
#define THW   256
#define KK    4608           // C * 9
#define NLOC  65536          // im2col rows
#define NCTHW 33554432

// ---------------------------------------------------------------------------
// Scratch (static __device__ arrays — allocation is forbidden)
// ---------------------------------------------------------------------------
__device__ float g_qA[NCTHW];                 // [(loc*256+n)*512+c]
__device__ float g_kA[NCTHW];
__device__ float g_vA[NCTHW];
__device__ float g_att[THW * NN * NN];
__device__ float g_virt[NCTHW];               // [n][c][loc]
__device__ float g_mu[NN];
__device__ float g_rinv[NN];

__device__ __nv_bfloat16 g_imx_hi[(size_t)NLOC * KK];   // rows r = loc*256+n
__device__ __nv_bfloat16 g_imx_lo[(size_t)NLOC * KK];
__device__ __nv_bfloat16 g_imc_hi[(size_t)NLOC * KK];   // rows r = n*256+loc
__device__ __nv_bfloat16 g_imc_lo[(size_t)NLOC * KK];
__device__ __nv_bfloat16 g_wA_hi[(size_t)1536 * KK];    // q | k | v
__device__ __nv_bfloat16 g_wA_lo[(size_t)1536 * KK];
__device__ __nv_bfloat16 g_wC_hi[(size_t)512 * KK];
__device__ __nv_bfloat16 g_wC_lo[(size_t)512 * KK];

// ---------------------------------------------------------------------------
// Portable-ISA helpers (compute_103-safe: cp.async + mma.sync only)
// ---------------------------------------------------------------------------
__device__ __forceinline__ uint32_t smem_u32(const void* p) {
    uint32_t a;
    asm("{ .reg .u64 t; cvta.to.shared.u64 t, %1; cvt.u32.u64 %0, t; }"
        : "=r"(a) : "l"(p));
    return a;
}
__device__ __forceinline__ void cp16(uint32_t dst, const void* src) {
    asm volatile("cp.async.cg.shared.global [%0], [%1], 16;" :: "r"(dst), "l"(src));
}
__device__ __forceinline__ void cp_commit() { asm volatile("cp.async.commit_group;"); }
__device__ __forceinline__ void cp_wait1()  { asm volatile("cp.async.wait_group 1;" ::: "memory"); }

__device__ __forceinline__ uint32_t lds32(uint32_t a) {
    uint32_t v; asm volatile("ld.shared.b32 %0, [%1];" : "=r"(v) : "r"(a)); return v;
}
__device__ __forceinline__ void sts32f(uint32_t a, float v) {
    asm volatile("st.shared.f32 [%0], %1;" :: "r"(a), "f"(v));
}
__device__ __forceinline__ float lds32f(uint32_t a) {
    float v; asm volatile("ld.shared.f32 %0, [%1];" : "=f"(v) : "r"(a)); return v;
}
__device__ __forceinline__ void mma16816(float* c,
    uint32_t a0, uint32_t a1, uint32_t a2, uint32_t a3, uint32_t b0, uint32_t b1) {
    asm volatile("mma.sync.aligned.m16n8k16.row.col.f32.bf16.bf16.f32 "
        "{%0,%1,%2,%3}, {%4,%5,%6,%7}, {%8,%9}, {%0,%1,%2,%3};"
        : "+f"(c[0]), "+f"(c[1]), "+f"(c[2]), "+f"(c[3])
        : "r"(a0), "r"(a1), "r"(a2), "r"(a3), "r"(b0), "r"(b1));
}

// ---------------------------------------------------------------------------
// GEMM tiling: block 128m x 128n, K-chunk 32, 2-stage cp.async pipeline.
// SMEM row = 32 bf16 = 64B payload at 80B stride (20 banks: frag LDS
// conflict-free; verified 32 distinct banks for both A and B frag patterns).
// ---------------------------------------------------------------------------
#define ROWB    80
#define MATB    (128 * ROWB)        // 10240 B per matrix per stage
#define STAGEB  (4 * MATB)          // Ah | Al | Bh | Bl
#define SMEM_DYN 81920              // 2 stages; epilogue reuses (needs 67584)
#define KCHUNKS 144                 // 4608 / 32

__device__ __forceinline__ void load_stage(
    uint32_t sb, int s, int chunk,
    const __nv_bfloat16* __restrict__ Ah, const __nv_bfloat16* __restrict__ Al,
    const __nv_bfloat16* __restrict__ Bh, const __nv_bfloat16* __restrict__ Bl,
    int arowbase, size_t browbase, int tid)
{
    const size_t k0 = (size_t)chunk * 32;
    const uint32_t base = sb + s * STAGEB;
#pragma unroll
    for (int it = 0; it < 2; ++it) {
        const int idx = tid + it * 256;
        const int row = idx >> 2, part = idx & 3;
        const uint32_t so = row * ROWB + part * 16;
        const size_t ga = (size_t)(arowbase + row) * KK + k0 + part * 8;
        const size_t gb = (browbase + row) * KK + k0 + part * 8;
        cp16(base + so,            Ah + ga);
        cp16(base + MATB + so,     Al + ga);
        cp16(base + 2 * MATB + so, Bh + gb);
        cp16(base + 3 * MATB + so, Bl + gb);
    }
}

__device__ __forceinline__ void compute_stage(uint32_t sb, int s,
                                              float acc[2][8][4], int tid)
{
    const int wid = tid >> 5, lane = tid & 31;
    const int wm = wid >> 1, wn = wid & 1;     // warps: 4 in m, 2 in n
    const int g = lane >> 2, qb = (lane & 3) * 4;
    const uint32_t stage = sb + s * STAGEB;
#pragma unroll
    for (int ks = 0; ks < 2; ++ks) {
        const uint32_t ko = ks * 32 + qb;
        uint32_t ah[2][4], al[2][4];
#pragma unroll
        for (int mt = 0; mt < 2; ++mt) {
            const uint32_t r0 = stage + (wm * 32 + mt * 16 + g) * ROWB + ko;
            ah[mt][0] = lds32(r0);                 ah[mt][1] = lds32(r0 + 8 * ROWB);
            ah[mt][2] = lds32(r0 + 16);            ah[mt][3] = lds32(r0 + 8 * ROWB + 16);
            al[mt][0] = lds32(r0 + MATB);          al[mt][1] = lds32(r0 + MATB + 8 * ROWB);
            al[mt][2] = lds32(r0 + MATB + 16);     al[mt][3] = lds32(r0 + MATB + 8 * ROWB + 16);
        }
        uint32_t bh[8][2], bl[8][2];
#pragma unroll
        for (int nt = 0; nt < 8; ++nt) {
            const uint32_t r0 = stage + 2 * MATB + (wn * 64 + nt * 8 + g) * ROWB + ko;
            bh[nt][0] = lds32(r0);        bh[nt][1] = lds32(r0 + 16);
            bl[nt][0] = lds32(r0 + MATB); bl[nt][1] = lds32(r0 + MATB + 16);
        }
#pragma unroll
        for (int mt = 0; mt < 2; ++mt)
#pragma unroll
            for (int nt = 0; nt < 8; ++nt) {
                mma16816(acc[mt][nt], ah[mt][0], ah[mt][1], ah[mt][2], ah[mt][3],
                         bh[nt][0], bh[nt][1]);
                mma16816(acc[mt][nt], ah[mt][0], ah[mt][1], ah[mt][2], ah[mt][3],
                         bl[nt][0], bl[nt][1]);
                mma16816(acc[mt][nt], al[mt][0], al[mt][1], al[mt][2], al[mt][3],
                         bh[nt][0], bh[nt][1]);
            }
    }
}

__device__ __forceinline__ void gemm_main(
    const __nv_bfloat16* __restrict__ Ah, const __nv_bfloat16* __restrict__ Al,
    const __nv_bfloat16* __restrict__ Bh, const __nv_bfloat16* __restrict__ Bl,
    int arowbase, size_t browbase, uint32_t sb, float acc[2][8][4])
{
    const int tid = threadIdx.x;
    load_stage(sb, 0, 0, Ah, Al, Bh, Bl, arowbase, browbase, tid); cp_commit();
    load_stage(sb, 1, 1, Ah, Al, Bh, Bl, arowbase, browbase, tid); cp_commit();
    for (int c = 0; c < KCHUNKS; ++c) {
        cp_wait1();
        __syncthreads();
        compute_stage(sb, c & 1, acc, tid);
        __syncthreads();
        if (c + 2 < KCHUNKS)
            load_stage(sb, c & 1, c + 2, Ah, Al, Bh, Bl, arowbase, browbase, tid);
        cp_commit();
    }
}

// qkv GEMM: grid.x = 12 m-tiles ({q,k,v} x 4 co-tiles), grid.y = 512 n-tiles.
// blockIdx.x fastest => the 12 blocks sharing one B n-tile run adjacently (L2 reuse).
__global__ __launch_bounds__(256, 1) void gemm_qkv_kernel()
{
    extern __shared__ char smem[];
    const uint32_t sb = smem_u32(smem);
    const int tid = threadIdx.x;
    const int mt = blockIdx.x;
    const size_t rbase = (size_t)blockIdx.y * 128;

    float acc[2][8][4];
#pragma unroll
    for (int a = 0; a < 2; a++)
#pragma unroll
        for (int b = 0; b < 8; b++)
#pragma unroll
            for (int c = 0; c < 4; c++) acc[a][b][c] = 0.f;

    gemm_main(g_wA_hi, g_wA_lo, g_imx_hi, g_imx_lo, mt * 128, rbase, sb, acc);
    __syncthreads();

    // frag -> smem buf[n 128][stride 132] (transpose), then coalesced global
    const int wid = tid >> 5, lane = tid & 31;
    const int wm = wid >> 1, wn = wid & 1;
    const int g = lane >> 2, q2 = (lane & 3) * 2;
#pragma unroll
    for (int m2 = 0; m2 < 2; m2++)
#pragma unroll
        for (int nt = 0; nt < 8; nt++) {
            const int row = wm * 32 + m2 * 16 + g;         // co
            const int col = wn * 64 + nt * 8 + q2;         // n
            const float* c = acc[m2][nt];
            sts32f(sb + (uint32_t)((col)     * 132 + row)     * 4, c[0]);
            sts32f(sb + (uint32_t)((col + 1) * 132 + row)     * 4, c[1]);
            sts32f(sb + (uint32_t)((col)     * 132 + row + 8) * 4, c[2]);
            sts32f(sb + (uint32_t)((col + 1) * 132 + row + 8) * 4, c[3]);
        }
    __syncthreads();

    float* outp = (mt < 4) ? g_qA : (mt < 8) ? g_kA : g_vA;
    const int cobase = (mt & 3) * 128;
    for (int idx = tid; idx < 16384; idx += 256) {
        const int nn2 = idx >> 7, co = idx & 127;
        outp[(rbase + nn2) * 512 + cobase + co] = lds32f(sb + (uint32_t)(nn2 * 132 + co) * 4);
    }
}

// conv_c GEMM + residual: grid.x = 4 m-tiles, grid.y = 512 n-tiles.
__global__ __launch_bounds__(256, 1) void gemm_c_kernel(
    const float* __restrict__ x, float* __restrict__ out)
{
    extern __shared__ char smem[];
    const uint32_t sb = smem_u32(smem);
    const int tid = threadIdx.x;
    const int mt = blockIdx.x;
    const size_t rbase = (size_t)blockIdx.y * 128;

    float acc[2][8][4];
#pragma unroll
    for (int a = 0; a < 2; a++)
#pragma unroll
        for (int b = 0; b < 8; b++)
#pragma unroll
            for (int c = 0; c < 4; c++) acc[a][b][c] = 0.f;

    gemm_main(g_wC_hi, g_wC_lo, g_imc_hi, g_imc_lo, mt * 128, rbase, sb, acc);
    __syncthreads();

    // frag -> smem buf[co 128][stride 132], then coalesced residual write
    const int wid = tid >> 5, lane = tid & 31;
    const int wm = wid >> 1, wn = wid & 1;
    const int g = lane >> 2, q2 = (lane & 3) * 2;
#pragma unroll
    for (int m2 = 0; m2 < 2; m2++)
#pragma unroll
        for (int nt = 0; nt < 8; nt++) {
            const int row = wm * 32 + m2 * 16 + g;         // co
            const int col = wn * 64 + nt * 8 + q2;         // loc within 128
            const float* c = acc[m2][nt];
            sts32f(sb + (uint32_t)((row)     * 132 + col)     * 4, c[0]);
            sts32f(sb + (uint32_t)((row)     * 132 + col + 1) * 4, c[1]);
            sts32f(sb + (uint32_t)((row + 8) * 132 + col)     * 4, c[2]);
            sts32f(sb + (uint32_t)((row + 8) * 132 + col + 1) * 4, c[3]);
        }
    __syncthreads();

    const int n = (int)(rbase >> 8);
    const int locbase = (int)(rbase & 255);
    const int cobase = mt * 128;
    for (int idx = tid; idx < 16384; idx += 256) {
        const int co = idx >> 7, loc = idx & 127;
        const size_t o = ((size_t)(n * 512 + cobase + co)) * 256 + locbase + loc;
        out[o] = x[o] + lds32f(sb + (uint32_t)(co * 132 + loc) * 4);
    }
}

// ---------------------------------------------------------------------------
// Weight conversion: fp32 -> bf16 hi/lo split
// ---------------------------------------------------------------------------
__global__ __launch_bounds__(256) void wconvert_kernel(
    const float* __restrict__ Wq, const float* __restrict__ Wk,
    const float* __restrict__ Wv, const float* __restrict__ Wc)
{
    size_t e = (size_t)blockIdx.x * 256 + threadIdx.x;
    if (e >= (size_t)2048 * KK) return;
    int row = (int)(e / KK);
    int k   = (int)(e % KK);
    float v;
    if (row < 512)       v = Wq[(size_t)row * KK + k];
    else if (row < 1024) v = Wk[(size_t)(row - 512) * KK + k];
    else if (row < 1536) v = Wv[(size_t)(row - 1024) * KK + k];
    else                 v = Wc[(size_t)(row - 1536) * KK + k];
    __nv_bfloat16 hi = __float2bfloat16_rn(v);
    __nv_bfloat16 lo = __float2bfloat16_rn(v - __bfloat162float(hi));
    if (row < 1536) { g_wA_hi[e] = hi; g_wA_lo[e] = lo; }
    else {
        size_t e2 = (size_t)(row - 1536) * KK + k;
        g_wC_hi[e2] = hi; g_wC_lo[e2] = lo;
    }
}

// ---------------------------------------------------------------------------
// im2col of x -> bf16 hi/lo, rows r = loc*256 + n, k = ci*9 + tap
// ---------------------------------------------------------------------------
__global__ __launch_bounds__(256) void im2col_x_kernel(const float* __restrict__ x)
{
    __shared__ float xs[32][65];
    const int nt = blockIdx.x;
    const int n  = nt >> 2;
    const int t  = nt & 3;
    const int ci0 = blockIdx.y * 32;
    const int tid = threadIdx.x;

    for (int idx = tid; idx < 2048; idx += 256) {
        int i = idx >> 6, p = idx & 63;
        xs[i][p] = x[((size_t)(n * 512 + ci0 + i)) * 256 + t * 64 + p];
    }
    __syncthreads();

    const int i  = tid & 31;
    const int pg = tid >> 5;
    for (int pp = 0; pp < 8; ++pp) {
        int p = pg * 8 + pp;
        int h = p >> 3, w = p & 7;
        size_t r = (size_t)(t * 64 + p) * 256 + n;
        __nv_bfloat16* dh = g_imx_hi + r * KK + (size_t)(ci0 + i) * 9;
        __nv_bfloat16* dl = g_imx_lo + r * KK + (size_t)(ci0 + i) * 9;
#pragma unroll
        for (int tap = 0; tap < 9; ++tap) {
            int hh = h + tap / 3 - 1, ww = w + tap % 3 - 1;
            float v = (hh >= 0 && hh < 8 && ww >= 0 && ww < 8) ? xs[i][hh * 8 + ww] : 0.f;
            __nv_bfloat16 hi = __float2bfloat16_rn(v);
            dh[tap] = hi;
            dl[tap] = __float2bfloat16_rn(v - __bfloat162float(hi));
        }
    }
}

// ---------------------------------------------------------------------------
// im2col of GN(virt)+ReLU -> bf16 hi/lo, rows r = n*256 + loc
// ---------------------------------------------------------------------------
__global__ __launch_bounds__(256) void im2col_c_kernel(
    const float* __restrict__ gamma, const float* __restrict__ beta)
{
    __shared__ float xs[32][65];
    const int nt = blockIdx.x;
    const int n  = nt >> 2;
    const int t  = nt & 3;
    const int ci0 = blockIdx.y * 32;
    const int tid = threadIdx.x;
    const float mu = g_mu[n], ri = g_rinv[n];

    for (int idx = tid; idx < 2048; idx += 256) {
        int i = idx >> 6, p = idx & 63;
        float v = g_virt[((size_t)(n * 512 + ci0 + i)) * 256 + t * 64 + p];
        v = (v - mu) * ri * gamma[ci0 + i] + beta[ci0 + i];
        xs[i][p] = fmaxf(v, 0.f);
    }
    __syncthreads();

    const int i  = tid & 31;
    const int pg = tid >> 5;
    for (int pp = 0; pp < 8; ++pp) {
        int p = pg * 8 + pp;
        int h = p >> 3, w = p & 7;
        size_t r = (size_t)n * 256 + t * 64 + p;
        __nv_bfloat16* dh = g_imc_hi + r * KK + (size_t)(ci0 + i) * 9;
        __nv_bfloat16* dl = g_imc_lo + r * KK + (size_t)(ci0 + i) * 9;
#pragma unroll
        for (int tap = 0; tap < 9; ++tap) {
            int hh = h + tap / 3 - 1, ww = w + tap % 3 - 1;
            float v = (hh >= 0 && hh < 8 && ww >= 0 && ww < 8) ? xs[i][hh * 8 + ww] : 0.f;
            __nv_bfloat16 hi = __float2bfloat16_rn(v);
            dh[tap] = hi;
            dl[tap] = __float2bfloat16_rn(v - __bfloat162float(hi));
        }
    }
}

// ---------------------------------------------------------------------------
// Attention scores + mask + softmax (FFMA-roofline-bound, proven in R1)
// ---------------------------------------------------------------------------
__global__ __launch_bounds__(256) void att_scores_kernel(const int* __restrict__ roi)
{
    __shared__ float qs[64][33];
    __shared__ float ks[256][33];
    __shared__ int   roi_s[256];

    const int loc = blockIdx.x;
    const int ib  = blockIdx.y * 64;
    const int tid = threadIdx.x;
    const int ig  = tid >> 5;
    const int jg  = tid & 31;

    if (tid < 256) roi_s[tid] = roi[tid];

    float acc[8][8];
#pragma unroll
    for (int ii = 0; ii < 8; ii++)
#pragma unroll
        for (int jj = 0; jj < 8; jj++) acc[ii][jj] = 0.f;

    for (int c0 = 0; c0 < CC; c0 += 32) {
        for (int idx = tid; idx < 64 * 32; idx += 256) {
            int i = idx >> 5, c = idx & 31;
            qs[i][c] = g_qA[((size_t)loc * NN + ib + i) * CC + c0 + c];
        }
        for (int idx = tid; idx < 256 * 32; idx += 256) {
            int j = idx >> 5, c = idx & 31;
            ks[j][c] = g_kA[((size_t)loc * NN + j) * CC + c0 + c];
        }
        __syncthreads();

#pragma unroll 4
        for (int c = 0; c < 32; c++) {
            float kv[8];
#pragma unroll
            for (int jj = 0; jj < 8; jj++) kv[jj] = ks[jg + 32 * jj][c];
#pragma unroll
            for (int ii = 0; ii < 8; ii++) {
                float qv = qs[ig + 8 * ii][c];
#pragma unroll
                for (int jj = 0; jj < 8; jj++) acc[ii][jj] += qv * kv[jj];
            }
        }
        __syncthreads();
    }

    const float scale = 0.044194173824159216f;

#pragma unroll
    for (int ii = 0; ii < 8; ii++) {
        const int i  = ib + ig + 8 * ii;
        const int ri = roi_s[i];
        float e[8];
        float m = -CUDART_INF_F;
#pragma unroll
        for (int jj = 0; jj < 8; jj++) {
            const int j = jg + 32 * jj;
            float v = (roi_s[j] == ri) ? acc[ii][jj] * scale : -CUDART_INF_F;
            e[jj] = v;
            m = fmaxf(m, v);
        }
#pragma unroll
        for (int off = 16; off > 0; off >>= 1)
            m = fmaxf(m, __shfl_xor_sync(0xffffffffu, m, off));
        float s = 0.f;
#pragma unroll
        for (int jj = 0; jj < 8; jj++) { float t_ = __expf(e[jj] - m); e[jj] = t_; s += t_; }
#pragma unroll
        for (int off = 16; off > 0; off >>= 1)
            s += __shfl_xor_sync(0xffffffffu, s, off);
        const float inv = 1.f / s;
#pragma unroll
        for (int jj = 0; jj < 8; jj++)
            g_att[((size_t)loc * NN + i) * NN + jg + 32 * jj] = e[jj] * inv;
    }
}

// ---------------------------------------------------------------------------
// virt = att @ v (proven in R1)
// ---------------------------------------------------------------------------
__global__ __launch_bounds__(256) void att_apply_kernel()
{
    __shared__ float as[32][33];
    __shared__ float vs[32][256];

    const int loc = blockIdx.x;
    const int it  = blockIdx.y >> 1;
    const int ct  = blockIdx.y & 1;
    const int ib  = it * 32;
    const int cb  = ct * 256;
    const int tid = threadIdx.x;
    const int ig  = tid >> 5;
    const int cg  = tid & 31;

    float acc[4][8];
#pragma unroll
    for (int ii = 0; ii < 4; ii++)
#pragma unroll
        for (int cc = 0; cc < 8; cc++) acc[ii][cc] = 0.f;

    for (int j0 = 0; j0 < NN; j0 += 32) {
        for (int idx = tid; idx < 32 * 32; idx += 256) {
            int i = idx >> 5, j = idx & 31;
            as[i][j] = g_att[((size_t)loc * NN + ib + i) * NN + j0 + j];
        }
        for (int idx = tid; idx < 32 * 256; idx += 256) {
            int j = idx >> 8, c = idx & 255;
            vs[j][c] = g_vA[((size_t)loc * NN + j0 + j) * CC + cb + c];
        }
        __syncthreads();

#pragma unroll 4
        for (int j = 0; j < 32; j++) {
            float vv[8];
#pragma unroll
            for (int cc = 0; cc < 8; cc++) vv[cc] = vs[j][cg + 32 * cc];
#pragma unroll
            for (int ii = 0; ii < 4; ii++) {
                float av = as[ig + 8 * ii][j];
#pragma unroll
                for (int cc = 0; cc < 8; cc++) acc[ii][cc] += av * vv[cc];
            }
        }
        __syncthreads();
    }

#pragma unroll
    for (int ii = 0; ii < 4; ii++) {
        const int i = ib + ig + 8 * ii;
#pragma unroll
        for (int cc = 0; cc < 8; cc++) {
            const int c = cb + cg + 32 * cc;
            g_virt[((size_t)i * CC + c) * THW + loc] = acc[ii][cc];
        }
    }
}

// ---------------------------------------------------------------------------
// GroupNorm reduce: per-sample mu / rsqrt(var+eps)
// ---------------------------------------------------------------------------
__global__ __launch_bounds__(256) void gn_reduce_kernel()
{
    __shared__ float red[16];
    const int n   = blockIdx.x;
    const int tid = threadIdx.x;
    const float* __restrict__ src = g_virt + (size_t)n * CC * THW;

    float s = 0.f, s2 = 0.f;
    for (int idx = tid; idx < CC * THW; idx += 256) {
        float v = src[idx];
        s += v; s2 += v * v;
    }
#pragma unroll
    for (int off = 16; off > 0; off >>= 1) {
        s  += __shfl_xor_sync(0xffffffffu, s,  off);
        s2 += __shfl_xor_sync(0xffffffffu, s2, off);
    }
    const int wid = tid >> 5, lane = tid & 31;
    if (lane == 0) { red[wid] = s; red[8 + wid] = s2; }
    __syncthreads();
    if (tid == 0) {
        float S = 0.f, S2 = 0.f;
#pragma unroll
        for (int w = 0; w < 8; w++) { S += red[w]; S2 += red[8 + w]; }
        const float M = (float)(CC * THW);
        float mu  = S / M;
        float var = S2 / M - mu * mu;
        g_mu[n]   = mu;
        g_rinv[n] = rsqrtf(var + 1e-5f);
    }
}

// ---------------------------------------------------------------------------
extern "C" void kernel_launch(void* const* d_in, const int* in_sizes, int n_in,
                              void* d_out, int out_size)
{
    const float* x     = (const float*)d_in[0];
    const int*   roi   = (const int*)  d_in[1];
    const float* Wq    = (const float*)d_in[2];
    const float* Wk    = (const float*)d_in[3];
    const float* Wv    = (const float*)d_in[4];
    const float* Wc    = (const float*)d_in[5];
    const float* gamma = (const float*)d_in[6];
    const float* beta  = (const float*)d_in[7];
    float* out = (float*)d_out;

    cudaFuncSetAttribute(gemm_qkv_kernel, cudaFuncAttributeMaxDynamicSharedMemorySize, SMEM_DYN);
    cudaFuncSetAttribute(gemm_c_kernel,   cudaFuncAttributeMaxDynamicSharedMemorySize, SMEM_DYN);

    wconvert_kernel<<<36864, 256>>>(Wq, Wk, Wv, Wc);
    im2col_x_kernel<<<dim3(1024, 16), 256>>>(x);
    gemm_qkv_kernel<<<dim3(12, 512), 256, SMEM_DYN>>>();
    att_scores_kernel<<<dim3(256, 4), 256>>>(roi);
    att_apply_kernel<<<dim3(256, 16), 256>>>();
    gn_reduce_kernel<<<256, 256>>>();
    im2col_c_kernel<<<dim3(1024, 16), 256>>>(gamma, beta);
    gemm_c_kernel<<<dim3(4, 512), 256, SMEM_DYN>>>(x, out);
}

// round 6
// speedup vs baseline: 2.6658x; 1.0943x over previous
#include <cuda_runtime.h>
#include <cuda_bf16.h>
#include <math_constants.h>
#include <cstdint>

// Problem constants
#define NN    256
#define CC    512
#define THW   256
#define KK    4608           // C * 9
#define NLOC  65536          // im2col rows
#define NCTHW 33554432

// ---------------------------------------------------------------------------
// Scratch (static __device__ arrays — allocation is forbidden)
// ---------------------------------------------------------------------------
__device__ float g_qA[NCTHW];                 // [(loc*256+n)*512+c]
__device__ float g_kA[NCTHW];
__device__ float g_vA[NCTHW];
__device__ float g_att[THW * NN * NN];
__device__ float g_virt[NCTHW];               // [n][c][loc]
__device__ float g_mu[NN];
__device__ float g_rinv[NN];

__device__ __nv_bfloat16 g_imx_hi[(size_t)NLOC * KK];   // rows r = loc*256+n
__device__ __nv_bfloat16 g_imx_lo[(size_t)NLOC * KK];
__device__ __nv_bfloat16 g_imc_hi[(size_t)NLOC * KK];   // rows r = n*256+loc
__device__ __nv_bfloat16 g_imc_lo[(size_t)NLOC * KK];
__device__ __nv_bfloat16 g_wA_hi[(size_t)1536 * KK];    // q | k | v
__device__ __nv_bfloat16 g_wA_lo[(size_t)1536 * KK];
__device__ __nv_bfloat16 g_wC_hi[(size_t)512 * KK];
__device__ __nv_bfloat16 g_wC_lo[(size_t)512 * KK];

// ---------------------------------------------------------------------------
// Portable-ISA helpers (compute_103-safe: cp.async + ldmatrix + mma.sync)
// ---------------------------------------------------------------------------
__device__ __forceinline__ uint32_t smem_u32(const void* p) {
    uint32_t a;
    asm("{ .reg .u64 t; cvta.to.shared.u64 t, %1; cvt.u32.u64 %0, t; }"
        : "=r"(a) : "l"(p));
    return a;
}
__device__ __forceinline__ void cp16(uint32_t dst, const void* src) {
    asm volatile("cp.async.cg.shared.global [%0], [%1], 16;" :: "r"(dst), "l"(src));
}
__device__ __forceinline__ void cp_commit() { asm volatile("cp.async.commit_group;"); }
__device__ __forceinline__ void cp_wait1()  { asm volatile("cp.async.wait_group 1;" ::: "memory"); }

__device__ __forceinline__ void ldsm4(uint32_t& r0, uint32_t& r1, uint32_t& r2,
                                      uint32_t& r3, uint32_t addr) {
    asm volatile("ldmatrix.sync.aligned.m8n8.x4.shared.b16 {%0,%1,%2,%3}, [%4];"
        : "=r"(r0), "=r"(r1), "=r"(r2), "=r"(r3) : "r"(addr));
}
__device__ __forceinline__ void sts32f(uint32_t a, float v) {
    asm volatile("st.shared.f32 [%0], %1;" :: "r"(a), "f"(v));
}
__device__ __forceinline__ float lds32f(uint32_t a) {
    float v; asm volatile("ld.shared.f32 %0, [%1];" : "=f"(v) : "r"(a)); return v;
}
__device__ __forceinline__ void mma16816(float* c,
    uint32_t a0, uint32_t a1, uint32_t a2, uint32_t a3, uint32_t b0, uint32_t b1) {
    asm volatile("mma.sync.aligned.m16n8k16.row.col.f32.bf16.bf16.f32 "
        "{%0,%1,%2,%3}, {%4,%5,%6,%7}, {%8,%9}, {%0,%1,%2,%3};"
        : "+f"(c[0]), "+f"(c[1]), "+f"(c[2]), "+f"(c[3])
        : "r"(a0), "r"(a1), "r"(a2), "r"(a3), "r"(b0), "r"(b1));
}

// ---------------------------------------------------------------------------
// GEMM tiling: block 128m x 256n, 512 threads (warps 4m x 4n, warp tile 32x64),
// K-chunk 64, 2-stage cp.async pipeline, ldmatrix.x4 frag loads.
// SMEM row = 64 bf16 = 128B payload at 144B stride: ldmatrix rows 0..7 land at
// 0,16,..,112 mod 128 -> every ldmatrix phase conflict-free.
// Stage layout: Ah[128*144] Al[128*144] Bh[256*144] Bl[256*144] = 110592 B.
// ---------------------------------------------------------------------------
#define ROWB    144
#define A_OFF_L 18432                // 128*144
#define B_OFF_H 36864
#define B_OFF_L 110592               // 36864 + 256*144 = 73728 -> wait, see below
#undef  B_OFF_L
#define B_OFF_L 73728                // 36864 + 36864
#define STAGEB  110592               // 73728 + 36864
#define SMEM_DYN 221184              // 2 stages; epilogue reuse needs <= 135168
#define KCHUNKS 72                   // 4608 / 64

__device__ __forceinline__ void load_stage(
    uint32_t sb, int s, int chunk,
    const __nv_bfloat16* __restrict__ Ah, const __nv_bfloat16* __restrict__ Al,
    const __nv_bfloat16* __restrict__ Bh, const __nv_bfloat16* __restrict__ Bl,
    int arowbase, size_t browbase, int tid)
{
    const size_t k0 = (size_t)chunk * 64;
    const uint32_t base = sb + s * STAGEB;
#pragma unroll
    for (int it = 0; it < 2; ++it) {               // A: 128 rows x 8 parts
        const int idx = tid + it * 512;
        const int row = idx >> 3, part = idx & 7;
        const uint32_t so = row * ROWB + part * 16;
        const size_t ga = (size_t)(arowbase + row) * KK + k0 + part * 8;
        cp16(base + so,           Ah + ga);
        cp16(base + A_OFF_L + so, Al + ga);
    }
#pragma unroll
    for (int it = 0; it < 4; ++it) {               // B: 256 rows x 8 parts
        const int idx = tid + it * 512;
        const int row = idx >> 3, part = idx & 7;
        const uint32_t so = row * ROWB + part * 16;
        const size_t gb = (browbase + row) * KK + k0 + part * 8;
        cp16(base + B_OFF_H + so, Bh + gb);
        cp16(base + B_OFF_L + so, Bl + gb);
    }
}

__device__ __forceinline__ void compute_stage(uint32_t sb, int s,
                                              float acc[2][8][4], int tid)
{
    const int wid = tid >> 5, lane = tid & 31;
    const int wm = wid >> 2, wn = wid & 3;         // 4m x 4n warps
    const uint32_t stage = sb + s * STAGEB;

    // ldmatrix lane address components
    const int a_moff = ((lane >> 3) & 1) * 8 + (lane & 7);
    const int a_kb   = ((lane >> 4) & 1) * 16;
    const int b_noff = ((lane >> 4) & 1) * 8 + (lane & 7);
    const int b_kb   = ((lane >> 3) & 1) * 16;

    const uint32_t aBase = stage + (uint32_t)(wm * 32 + a_moff) * ROWB + a_kb;
    const uint32_t bBase = stage + B_OFF_H + (uint32_t)(wn * 64 + b_noff) * ROWB + b_kb;

#pragma unroll
    for (int ks = 0; ks < 4; ++ks) {
        const uint32_t ko = ks * 32;
        uint32_t ah[2][4], al[2][4];
#pragma unroll
        for (int mt = 0; mt < 2; ++mt) {
            const uint32_t a0 = aBase + mt * (16 * ROWB) + ko;
            ldsm4(ah[mt][0], ah[mt][1], ah[mt][2], ah[mt][3], a0);
            ldsm4(al[mt][0], al[mt][1], al[mt][2], al[mt][3], a0 + A_OFF_L);
        }
#pragma unroll
        for (int p = 0; p < 4; ++p) {              // pair of n-tiles 2p, 2p+1
            uint32_t bh0, bh1, bh2, bh3, bl0, bl1, bl2, bl3;
            const uint32_t b0 = bBase + p * (16 * ROWB) + ko;
            ldsm4(bh0, bh1, bh2, bh3, b0);
            ldsm4(bl0, bl1, bl2, bl3, b0 + (B_OFF_L - B_OFF_H));
#pragma unroll
            for (int mt = 0; mt < 2; ++mt) {
                mma16816(acc[mt][2*p],   ah[mt][0], ah[mt][1], ah[mt][2], ah[mt][3], bh0, bh1);
                mma16816(acc[mt][2*p],   ah[mt][0], ah[mt][1], ah[mt][2], ah[mt][3], bl0, bl1);
                mma16816(acc[mt][2*p],   al[mt][0], al[mt][1], al[mt][2], al[mt][3], bh0, bh1);
                mma16816(acc[mt][2*p+1], ah[mt][0], ah[mt][1], ah[mt][2], ah[mt][3], bh2, bh3);
                mma16816(acc[mt][2*p+1], ah[mt][0], ah[mt][1], ah[mt][2], ah[mt][3], bl2, bl3);
                mma16816(acc[mt][2*p+1], al[mt][0], al[mt][1], al[mt][2], al[mt][3], bh2, bh3);
            }
        }
    }
}

__device__ __forceinline__ void gemm_main(
    const __nv_bfloat16* __restrict__ Ah, const __nv_bfloat16* __restrict__ Al,
    const __nv_bfloat16* __restrict__ Bh, const __nv_bfloat16* __restrict__ Bl,
    int arowbase, size_t browbase, uint32_t sb, float acc[2][8][4])
{
    const int tid = threadIdx.x;
    load_stage(sb, 0, 0, Ah, Al, Bh, Bl, arowbase, browbase, tid); cp_commit();
    load_stage(sb, 1, 1, Ah, Al, Bh, Bl, arowbase, browbase, tid); cp_commit();
    for (int c = 0; c < KCHUNKS; ++c) {
        cp_wait1();
        __syncthreads();
        compute_stage(sb, c & 1, acc, tid);
        __syncthreads();
        if (c + 2 < KCHUNKS)
            load_stage(sb, c & 1, c + 2, Ah, Al, Bh, Bl, arowbase, browbase, tid);
        cp_commit();
    }
}

// qkv GEMM: grid.x = 12 m-tiles ({q,k,v} x 4 co-tiles), grid.y = 256 n-tiles.
__global__ __launch_bounds__(512, 1) void gemm_qkv_kernel()
{
    extern __shared__ char smem[];
    const uint32_t sb = smem_u32(smem);
    const int tid = threadIdx.x;
    const int mt = blockIdx.x;
    const size_t rbase = (size_t)blockIdx.y * 256;

    float acc[2][8][4];
#pragma unroll
    for (int a = 0; a < 2; a++)
#pragma unroll
        for (int b = 0; b < 8; b++)
#pragma unroll
            for (int c = 0; c < 4; c++) acc[a][b][c] = 0.f;

    gemm_main(g_wA_hi, g_wA_lo, g_imx_hi, g_imx_lo, mt * 128, rbase, sb, acc);
    __syncthreads();

    // frag -> smem buf[n 256][stride 132] (transpose), then coalesced global
    const int wid = tid >> 5, lane = tid & 31;
    const int wm = wid >> 2, wn = wid & 3;
    const int g = lane >> 2, q2 = (lane & 3) * 2;
#pragma unroll
    for (int m2 = 0; m2 < 2; m2++)
#pragma unroll
        for (int nt = 0; nt < 8; nt++) {
            const int row = wm * 32 + m2 * 16 + g;          // co
            const int col = wn * 64 + nt * 8 + q2;          // n
            const float* c = acc[m2][nt];
            sts32f(sb + (uint32_t)((col)     * 132 + row)     * 4, c[0]);
            sts32f(sb + (uint32_t)((col + 1) * 132 + row)     * 4, c[1]);
            sts32f(sb + (uint32_t)((col)     * 132 + row + 8) * 4, c[2]);
            sts32f(sb + (uint32_t)((col + 1) * 132 + row + 8) * 4, c[3]);
        }
    __syncthreads();

    float* outp = (mt < 4) ? g_qA : (mt < 8) ? g_kA : g_vA;
    const int cobase = (mt & 3) * 128;
    for (int idx = tid; idx < 32768; idx += 512) {
        const int nn2 = idx >> 7, co = idx & 127;
        outp[(rbase + nn2) * 512 + cobase + co] = lds32f(sb + (uint32_t)(nn2 * 132 + co) * 4);
    }
}

// conv_c GEMM + residual: grid.x = 4 m-tiles, grid.y = 256 (one sample each).
__global__ __launch_bounds__(512, 1) void gemm_c_kernel(
    const float* __restrict__ x, float* __restrict__ out)
{
    extern __shared__ char smem[];
    const uint32_t sb = smem_u32(smem);
    const int tid = threadIdx.x;
    const int mt = blockIdx.x;
    const int n  = blockIdx.y;
    const size_t rbase = (size_t)n * 256;

    float acc[2][8][4];
#pragma unroll
    for (int a = 0; a < 2; a++)
#pragma unroll
        for (int b = 0; b < 8; b++)
#pragma unroll
            for (int c = 0; c < 4; c++) acc[a][b][c] = 0.f;

    gemm_main(g_wC_hi, g_wC_lo, g_imc_hi, g_imc_lo, mt * 128, rbase, sb, acc);
    __syncthreads();

    // frag -> smem buf[co 128][stride 260], then coalesced residual write
    const int wid = tid >> 5, lane = tid & 31;
    const int wm = wid >> 2, wn = wid & 3;
    const int g = lane >> 2, q2 = (lane & 3) * 2;
#pragma unroll
    for (int m2 = 0; m2 < 2; m2++)
#pragma unroll
        for (int nt = 0; nt < 8; nt++) {
            const int row = wm * 32 + m2 * 16 + g;          // co
            const int col = wn * 64 + nt * 8 + q2;          // loc
            const float* c = acc[m2][nt];
            sts32f(sb + (uint32_t)((row)     * 260 + col)     * 4, c[0]);
            sts32f(sb + (uint32_t)((row)     * 260 + col + 1) * 4, c[1]);
            sts32f(sb + (uint32_t)((row + 8) * 260 + col)     * 4, c[2]);
            sts32f(sb + (uint32_t)((row + 8) * 260 + col + 1) * 4, c[3]);
        }
    __syncthreads();

    const int cobase = mt * 128;
    for (int idx = tid; idx < 32768; idx += 512) {
        const int co = idx >> 8, loc = idx & 255;
        const size_t o = ((size_t)(n * 512 + cobase + co)) * 256 + loc;
        out[o] = x[o] + lds32f(sb + (uint32_t)(co * 260 + loc) * 4);
    }
}

// ---------------------------------------------------------------------------
// Weight conversion: fp32 -> bf16 hi/lo split
// ---------------------------------------------------------------------------
__global__ __launch_bounds__(256) void wconvert_kernel(
    const float* __restrict__ Wq, const float* __restrict__ Wk,
    const float* __restrict__ Wv, const float* __restrict__ Wc)
{
    size_t e = (size_t)blockIdx.x * 256 + threadIdx.x;
    if (e >= (size_t)2048 * KK) return;
    int row = (int)(e / KK);
    int k   = (int)(e % KK);
    float v;
    if (row < 512)       v = Wq[(size_t)row * KK + k];
    else if (row < 1024) v = Wk[(size_t)(row - 512) * KK + k];
    else if (row < 1536) v = Wv[(size_t)(row - 1024) * KK + k];
    else                 v = Wc[(size_t)(row - 1536) * KK + k];
    __nv_bfloat16 hi = __float2bfloat16_rn(v);
    __nv_bfloat16 lo = __float2bfloat16_rn(v - __bfloat162float(hi));
    if (row < 1536) { g_wA_hi[e] = hi; g_wA_lo[e] = lo; }
    else {
        size_t e2 = (size_t)(row - 1536) * KK + k;
        g_wC_hi[e2] = hi; g_wC_lo[e2] = lo;
    }
}

// ---------------------------------------------------------------------------
// im2col of x -> bf16 hi/lo, rows r = loc*256 + n, k = ci*9 + tap
// ---------------------------------------------------------------------------
__global__ __launch_bounds__(256) void im2col_x_kernel(const float* __restrict__ x)
{
    __shared__ float xs[32][65];
    const int nt = blockIdx.x;
    const int n  = nt >> 2;
    const int t  = nt & 3;
    const int ci0 = blockIdx.y * 32;
    const int tid = threadIdx.x;

    for (int idx = tid; idx < 2048; idx += 256) {
        int i = idx >> 6, p = idx & 63;
        xs[i][p] = x[((size_t)(n * 512 + ci0 + i)) * 256 + t * 64 + p];
    }
    __syncthreads();

    const int i  = tid & 31;
    const int pg = tid >> 5;
    for (int pp = 0; pp < 8; ++pp) {
        int p = pg * 8 + pp;
        int h = p >> 3, w = p & 7;
        size_t r = (size_t)(t * 64 + p) * 256 + n;
        __nv_bfloat16* dh = g_imx_hi + r * KK + (size_t)(ci0 + i) * 9;
        __nv_bfloat16* dl = g_imx_lo + r * KK + (size_t)(ci0 + i) * 9;
#pragma unroll
        for (int tap = 0; tap < 9; ++tap) {
            int hh = h + tap / 3 - 1, ww = w + tap % 3 - 1;
            float v = (hh >= 0 && hh < 8 && ww >= 0 && ww < 8) ? xs[i][hh * 8 + ww] : 0.f;
            __nv_bfloat16 hi = __float2bfloat16_rn(v);
            dh[tap] = hi;
            dl[tap] = __float2bfloat16_rn(v - __bfloat162float(hi));
        }
    }
}

// ---------------------------------------------------------------------------
// im2col of GN(virt)+ReLU -> bf16 hi/lo, rows r = n*256 + loc
// ---------------------------------------------------------------------------
__global__ __launch_bounds__(256) void im2col_c_kernel(
    const float* __restrict__ gamma, const float* __restrict__ beta)
{
    __shared__ float xs[32][65];
    const int nt = blockIdx.x;
    const int n  = nt >> 2;
    const int t  = nt & 3;
    const int ci0 = blockIdx.y * 32;
    const int tid = threadIdx.x;
    const float mu = g_mu[n], ri = g_rinv[n];

    for (int idx = tid; idx < 2048; idx += 256) {
        int i = idx >> 6, p = idx & 63;
        float v = g_virt[((size_t)(n * 512 + ci0 + i)) * 256 + t * 64 + p];
        v = (v - mu) * ri * gamma[ci0 + i] + beta[ci0 + i];
        xs[i][p] = fmaxf(v, 0.f);
    }
    __syncthreads();

    const int i  = tid & 31;
    const int pg = tid >> 5;
    for (int pp = 0; pp < 8; ++pp) {
        int p = pg * 8 + pp;
        int h = p >> 3, w = p & 7;
        size_t r = (size_t)n * 256 + t * 64 + p;
        __nv_bfloat16* dh = g_imc_hi + r * KK + (size_t)(ci0 + i) * 9;
        __nv_bfloat16* dl = g_imc_lo + r * KK + (size_t)(ci0 + i) * 9;
#pragma unroll
        for (int tap = 0; tap < 9; ++tap) {
            int hh = h + tap / 3 - 1, ww = w + tap % 3 - 1;
            float v = (hh >= 0 && hh < 8 && ww >= 0 && ww < 8) ? xs[i][hh * 8 + ww] : 0.f;
            __nv_bfloat16 hi = __float2bfloat16_rn(v);
            dh[tap] = hi;
            dl[tap] = __float2bfloat16_rn(v - __bfloat162float(hi));
        }
    }
}

// ---------------------------------------------------------------------------
// Attention scores + mask + softmax
// ---------------------------------------------------------------------------
__global__ __launch_bounds__(256) void att_scores_kernel(const int* __restrict__ roi)
{
    __shared__ float qs[64][33];
    __shared__ float ks[256][33];
    __shared__ int   roi_s[256];

    const int loc = blockIdx.x;
    const int ib  = blockIdx.y * 64;
    const int tid = threadIdx.x;
    const int ig  = tid >> 5;
    const int jg  = tid & 31;

    if (tid < 256) roi_s[tid] = roi[tid];

    float acc[8][8];
#pragma unroll
    for (int ii = 0; ii < 8; ii++)
#pragma unroll
        for (int jj = 0; jj < 8; jj++) acc[ii][jj] = 0.f;

    for (int c0 = 0; c0 < CC; c0 += 32) {
        for (int idx = tid; idx < 64 * 32; idx += 256) {
            int i = idx >> 5, c = idx & 31;
            qs[i][c] = g_qA[((size_t)loc * NN + ib + i) * CC + c0 + c];
        }
        for (int idx = tid; idx < 256 * 32; idx += 256) {
            int j = idx >> 5, c = idx & 31;
            ks[j][c] = g_kA[((size_t)loc * NN + j) * CC + c0 + c];
        }
        __syncthreads();

#pragma unroll 4
        for (int c = 0; c < 32; c++) {
            float kv[8];
#pragma unroll
            for (int jj = 0; jj < 8; jj++) kv[jj] = ks[jg + 32 * jj][c];
#pragma unroll
            for (int ii = 0; ii < 8; ii++) {
                float qv = qs[ig + 8 * ii][c];
#pragma unroll
                for (int jj = 0; jj < 8; jj++) acc[ii][jj] += qv * kv[jj];
            }
        }
        __syncthreads();
    }

    const float scale = 0.044194173824159216f;

#pragma unroll
    for (int ii = 0; ii < 8; ii++) {
        const int i  = ib + ig + 8 * ii;
        const int ri = roi_s[i];
        float e[8];
        float m = -CUDART_INF_F;
#pragma unroll
        for (int jj = 0; jj < 8; jj++) {
            const int j = jg + 32 * jj;
            float v = (roi_s[j] == ri) ? acc[ii][jj] * scale : -CUDART_INF_F;
            e[jj] = v;
            m = fmaxf(m, v);
        }
#pragma unroll
        for (int off = 16; off > 0; off >>= 1)
            m = fmaxf(m, __shfl_xor_sync(0xffffffffu, m, off));
        float s = 0.f;
#pragma unroll
        for (int jj = 0; jj < 8; jj++) { float t_ = __expf(e[jj] - m); e[jj] = t_; s += t_; }
#pragma unroll
        for (int off = 16; off > 0; off >>= 1)
            s += __shfl_xor_sync(0xffffffffu, s, off);
        const float inv = 1.f / s;
#pragma unroll
        for (int jj = 0; jj < 8; jj++)
            g_att[((size_t)loc * NN + i) * NN + jg + 32 * jj] = e[jj] * inv;
    }
}

// ---------------------------------------------------------------------------
// virt = att @ v
// ---------------------------------------------------------------------------
__global__ __launch_bounds__(256) void att_apply_kernel()
{
    __shared__ float as[32][33];
    __shared__ float vs[32][256];

    const int loc = blockIdx.x;
    const int it  = blockIdx.y >> 1;
    const int ct  = blockIdx.y & 1;
    const int ib  = it * 32;
    const int cb  = ct * 256;
    const int tid = threadIdx.x;
    const int ig  = tid >> 5;
    const int cg  = tid & 31;

    float acc[4][8];
#pragma unroll
    for (int ii = 0; ii < 4; ii++)
#pragma unroll
        for (int cc = 0; cc < 8; cc++) acc[ii][cc] = 0.f;

    for (int j0 = 0; j0 < NN; j0 += 32) {
        for (int idx = tid; idx < 32 * 32; idx += 256) {
            int i = idx >> 5, j = idx & 31;
            as[i][j] = g_att[((size_t)loc * NN + ib + i) * NN + j0 + j];
        }
        for (int idx = tid; idx < 32 * 256; idx += 256) {
            int j = idx >> 8, c = idx & 255;
            vs[j][c] = g_vA[((size_t)loc * NN + j0 + j) * CC + cb + c];
        }
        __syncthreads();

#pragma unroll 4
        for (int j = 0; j < 32; j++) {
            float vv[8];
#pragma unroll
            for (int cc = 0; cc < 8; cc++) vv[cc] = vs[j][cg + 32 * cc];
#pragma unroll
            for (int ii = 0; ii < 4; ii++) {
                float av = as[ig + 8 * ii][j];
#pragma unroll
                for (int cc = 0; cc < 8; cc++) acc[ii][cc] += av * vv[cc];
            }
        }
        __syncthreads();
    }

#pragma unroll
    for (int ii = 0; ii < 4; ii++) {
        const int i = ib + ig + 8 * ii;
#pragma unroll
        for (int cc = 0; cc < 8; cc++) {
            const int c = cb + cg + 32 * cc;
            g_virt[((size_t)i * CC + c) * THW + loc] = acc[ii][cc];
        }
    }
}

// ---------------------------------------------------------------------------
// GroupNorm reduce: per-sample mu / rsqrt(var+eps)
// ---------------------------------------------------------------------------
__global__ __launch_bounds__(256) void gn_reduce_kernel()
{
    __shared__ float red[16];
    const int n   = blockIdx.x;
    const int tid = threadIdx.x;
    const float* __restrict__ src = g_virt + (size_t)n * CC * THW;

    float s = 0.f, s2 = 0.f;
    for (int idx = tid; idx < CC * THW; idx += 256) {
        float v = src[idx];
        s += v; s2 += v * v;
    }
#pragma unroll
    for (int off = 16; off > 0; off >>= 1) {
        s  += __shfl_xor_sync(0xffffffffu, s,  off);
        s2 += __shfl_xor_sync(0xffffffffu, s2, off);
    }
    const int wid = tid >> 5, lane = tid & 31;
    if (lane == 0) { red[wid] = s; red[8 + wid] = s2; }
    __syncthreads();
    if (tid == 0) {
        float S = 0.f, S2 = 0.f;
#pragma unroll
        for (int w = 0; w < 8; w++) { S += red[w]; S2 += red[8 + w]; }
        const float M = (float)(CC * THW);
        float mu  = S / M;
        float var = S2 / M - mu * mu;
        g_mu[n]   = mu;
        g_rinv[n] = rsqrtf(var + 1e-5f);
    }
}

// ---------------------------------------------------------------------------
extern "C" void kernel_launch(void* const* d_in, const int* in_sizes, int n_in,
                              void* d_out, int out_size)
{
    const float* x     = (const float*)d_in[0];
    const int*   roi   = (const int*)  d_in[1];
    const float* Wq    = (const float*)d_in[2];
    const float* Wk    = (const float*)d_in[3];
    const float* Wv    = (const float*)d_in[4];
    const float* Wc    = (const float*)d_in[5];
    const float* gamma = (const float*)d_in[6];
    const float* beta  = (const float*)d_in[7];
    float* out = (float*)d_out;

    cudaFuncSetAttribute(gemm_qkv_kernel, cudaFuncAttributeMaxDynamicSharedMemorySize, SMEM_DYN);
    cudaFuncSetAttribute(gemm_c_kernel,   cudaFuncAttributeMaxDynamicSharedMemorySize, SMEM_DYN);

    wconvert_kernel<<<36864, 256>>>(Wq, Wk, Wv, Wc);
    im2col_x_kernel<<<dim3(1024, 16), 256>>>(x);
    gemm_qkv_kernel<<<dim3(12, 256), 512, SMEM_DYN>>>();
    att_scores_kernel<<<dim3(256, 4), 256>>>(roi);
    att_apply_kernel<<<dim3(256, 16), 256>>>();
    gn_reduce_kernel<<<256, 256>>>();
    im2col_c_kernel<<<dim3(1024, 16), 256>>>(gamma, beta);
    gemm_c_kernel<<<dim3(4, 256), 512, SMEM_DYN>>>(x, out);
}

// round 8
// speedup vs baseline: 5.3246x; 1.9974x over previous
#include <cuda_runtime.h>
#include <cuda_bf16.h>
#include <math_constants.h>
#include <cstdint>

// Problem constants
#define NN     256
#define CC     512
#define THW    256
#define NTILES 16384           // 256 n * 4 t * 16 tiles(2x2)
#define NCTHW  33554432

// ---------------------------------------------------------------------------
// Scratch (static __device__ arrays — allocation is forbidden)
// ---------------------------------------------------------------------------
__device__ float g_qA[NCTHW];                 // [(loc*256+n)*512+c]
__device__ float g_kA[NCTHW];
__device__ float g_vA[NCTHW];
__device__ float g_att[THW * NN * NN];
__device__ float g_virt[NCTHW];               // [n][c][loc]
__device__ float g_mu[NN];
__device__ float g_rinv[NN];

// Winograd operands. U: [pt][co][ci], V: [pt][tile][ci], M: [pt][co][tile]
__device__ __nv_bfloat16 g_Ux_hi[(size_t)16 * 1536 * 512];
__device__ __nv_bfloat16 g_Ux_lo[(size_t)16 * 1536 * 512];
__device__ __nv_bfloat16 g_Uc_hi[(size_t)16 * 512 * 512];
__device__ __nv_bfloat16 g_Uc_lo[(size_t)16 * 512 * 512];
__device__ __nv_bfloat16 g_Vx_hi[(size_t)16 * NTILES * 512];
__device__ __nv_bfloat16 g_Vx_lo[(size_t)16 * NTILES * 512];
__device__ __nv_bfloat16 g_Vc_hi[(size_t)16 * NTILES * 512];
__device__ __nv_bfloat16 g_Vc_lo[(size_t)16 * NTILES * 512];
__device__ float g_M[(size_t)16 * 1536 * NTILES];   // reused for conv_c (512 rows)

// ---------------------------------------------------------------------------
// Portable-ISA helpers
// ---------------------------------------------------------------------------
__device__ __forceinline__ uint32_t smem_u32(const void* p) {
    uint32_t a;
    asm("{ .reg .u64 t; cvta.to.shared.u64 t, %1; cvt.u32.u64 %0, t; }"
        : "=r"(a) : "l"(p));
    return a;
}
__device__ __forceinline__ void cp16(uint32_t dst, const void* src) {
    asm volatile("cp.async.cg.shared.global [%0], [%1], 16;" :: "r"(dst), "l"(src));
}
__device__ __forceinline__ void cp_commit() { asm volatile("cp.async.commit_group;"); }
__device__ __forceinline__ void cp_wait1()  { asm volatile("cp.async.wait_group 1;" ::: "memory"); }

__device__ __forceinline__ void ldsm4(uint32_t& r0, uint32_t& r1, uint32_t& r2,
                                      uint32_t& r3, uint32_t addr) {
    asm volatile("ldmatrix.sync.aligned.m8n8.x4.shared.b16 {%0,%1,%2,%3}, [%4];"
        : "=r"(r0), "=r"(r1), "=r"(r2), "=r"(r3) : "r"(addr));
}
__device__ __forceinline__ void sts32f(uint32_t a, float v) {
    asm volatile("st.shared.f32 [%0], %1;" :: "r"(a), "f"(v));
}
__device__ __forceinline__ float lds32f(uint32_t a) {
    float v; asm volatile("ld.shared.f32 %0, [%1];" : "=f"(v) : "r"(a)); return v;
}
__device__ __forceinline__ void mma16816(float* c,
    uint32_t a0, uint32_t a1, uint32_t a2, uint32_t a3, uint32_t b0, uint32_t b1) {
    asm volatile("mma.sync.aligned.m16n8k16.row.col.f32.bf16.bf16.f32 "
        "{%0,%1,%2,%3}, {%4,%5,%6,%7}, {%8,%9}, {%0,%1,%2,%3};"
        : "+f"(c[0]), "+f"(c[1]), "+f"(c[2]), "+f"(c[3])
        : "r"(a0), "r"(a1), "r"(a2), "r"(a3), "r"(b0), "r"(b1));
}
__device__ __forceinline__ void bfsplit(float v, __nv_bfloat16& hi, __nv_bfloat16& lo) {
    hi = __float2bfloat16_rn(v);
    lo = __float2bfloat16_rn(v - __bfloat162float(hi));
}

// ---------------------------------------------------------------------------
// Weight transform: U = G g G^T per (co2, ci). co2: 0-511 q, 512-1023 k,
// 1024-1535 v (-> Ux), 1536-2047 c (-> Uc).
// ---------------------------------------------------------------------------
__global__ __launch_bounds__(256) void wtrans_kernel(
    const float* __restrict__ Wq, const float* __restrict__ Wk,
    const float* __restrict__ Wv, const float* __restrict__ Wc)
{
    const int idx = blockIdx.x * 256 + threadIdx.x;   // 2048*512
    const int ci  = idx & 511;
    const int co2 = idx >> 9;
    const float* Wp;
    int co;
    if (co2 < 512)       { Wp = Wq; co = co2; }
    else if (co2 < 1024) { Wp = Wk; co = co2 - 512; }
    else if (co2 < 1536) { Wp = Wv; co = co2 - 1024; }
    else                 { Wp = Wc; co = co2 - 1536; }

    float g[3][3];
#pragma unroll
    for (int r = 0; r < 3; r++)
#pragma unroll
        for (int c = 0; c < 3; c++)
            g[r][c] = Wp[((size_t)co * 512 + ci) * 9 + r * 3 + c];

    float gg[4][3];
#pragma unroll
    for (int c = 0; c < 3; c++) {
        gg[0][c] = g[0][c];
        gg[1][c] = 0.5f * (g[0][c] + g[1][c] + g[2][c]);
        gg[2][c] = 0.5f * (g[0][c] - g[1][c] + g[2][c]);
        gg[3][c] = g[2][c];
    }
#pragma unroll
    for (int r = 0; r < 4; r++) {
        float u[4];
        u[0] = gg[r][0];
        u[1] = 0.5f * (gg[r][0] + gg[r][1] + gg[r][2]);
        u[2] = 0.5f * (gg[r][0] - gg[r][1] + gg[r][2]);
        u[3] = gg[r][2];
#pragma unroll
        for (int c = 0; c < 4; c++) {
            const int pt = r * 4 + c;
            __nv_bfloat16 hi, lo;
            bfsplit(u[c], hi, lo);
            if (co2 < 1536) {
                const size_t o = ((size_t)pt * 1536 + co2) * 512 + ci;
                g_Ux_hi[o] = hi; g_Ux_lo[o] = lo;
            } else {
                const size_t o = ((size_t)pt * 512 + co) * 512 + ci;
                g_Uc_hi[o] = hi; g_Uc_lo[o] = lo;
            }
        }
    }
}

// ---------------------------------------------------------------------------
// Input transform core: V = B^T d B -> bf16 hi/lo at V[pt][tile][ci].
// ---------------------------------------------------------------------------
__device__ __forceinline__ void vtrans_body(
    const float* xs, int ci0, int tb,
    __nv_bfloat16* __restrict__ Vh, __nv_bfloat16* __restrict__ Vl)
{
    const int tid = threadIdx.x;
    const int ci = tid & 31;
    const int tg = tid >> 5;
#pragma unroll
    for (int th = 0; th < 2; th++) {
        const int tile = tg + th * 8;
        const int ty = tile >> 2, tx = tile & 3;
        float d[4][4];
#pragma unroll
        for (int r = 0; r < 4; r++)
#pragma unroll
            for (int c = 0; c < 4; c++)
                d[r][c] = xs[ci * 101 + (2 * ty + r) * 10 + (2 * tx + c)];
        float t0[4], t1[4], t2[4], t3[4];
#pragma unroll
        for (int j = 0; j < 4; j++) {
            t0[j] = d[0][j] - d[2][j];
            t1[j] = d[1][j] + d[2][j];
            t2[j] = d[2][j] - d[1][j];
            t3[j] = d[1][j] - d[3][j];
        }
        float v[4][4];
#pragma unroll
        for (int i = 0; i < 4; i++) {
            const float* t = (i == 0) ? t0 : (i == 1) ? t1 : (i == 2) ? t2 : t3;
            v[i][0] = t[0] - t[2];
            v[i][1] = t[1] + t[2];
            v[i][2] = t[2] - t[1];
            v[i][3] = t[1] - t[3];
        }
#pragma unroll
        for (int i = 0; i < 4; i++)
#pragma unroll
            for (int j = 0; j < 4; j++) {
                const int pt = i * 4 + j;
                __nv_bfloat16 hi, lo;
                bfsplit(v[i][j], hi, lo);
                const size_t o = ((size_t)pt * NTILES + tb + tile) * 512 + ci0 + ci;
                Vh[o] = hi; Vl[o] = lo;
            }
    }
}

// Input transform of x. grid (1024 = n*t, 16 ci-chunks), block 256.
__global__ __launch_bounds__(256) void vtransx_kernel(const float* __restrict__ x)
{
    __shared__ float xs[32 * 101];
    const int nt = blockIdx.x;
    const int n  = nt >> 2;
    const int t  = nt & 3;
    const int ci0 = blockIdx.y * 32;
    const int tid = threadIdx.x;

    for (int idx = tid; idx < 3200; idx += 256) {
        const int i = idx / 100;
        const int rc = idx % 100;
        const int r = rc / 10, c = rc % 10;
        const int hh = r - 1, ww = c - 1;
        float v = 0.f;
        if (hh >= 0 && hh < 8 && ww >= 0 && ww < 8)
            v = x[((size_t)(n * 512 + ci0 + i)) * 256 + t * 64 + hh * 8 + ww];
        xs[i * 101 + r * 10 + c] = v;
    }
    __syncthreads();
    vtrans_body(xs, ci0, nt * 16, g_Vx_hi, g_Vx_lo);
}

// Input transform of GN(virt)+ReLU. grid (1024, 16), block 256.
__global__ __launch_bounds__(256) void vtransc_kernel(
    const float* __restrict__ gamma, const float* __restrict__ beta)
{
    __shared__ float xs[32 * 101];
    const int nt = blockIdx.x;
    const int n  = nt >> 2;
    const int t  = nt & 3;
    const int ci0 = blockIdx.y * 32;
    const int tid = threadIdx.x;
    const float mu = g_mu[n], ri = g_rinv[n];

    for (int idx = tid; idx < 3200; idx += 256) {
        const int i = idx / 100;
        const int rc = idx % 100;
        const int r = rc / 10, c = rc % 10;
        const int hh = r - 1, ww = c - 1;
        float v = 0.f;
        if (hh >= 0 && hh < 8 && ww >= 0 && ww < 8) {
            float u = g_virt[((size_t)(n * 512 + ci0 + i)) * 256 + t * 64 + hh * 8 + ww];
            u = (u - mu) * ri * gamma[ci0 + i] + beta[ci0 + i];
            v = fmaxf(u, 0.f);
        }
        xs[i * 101 + r * 10 + c] = v;
    }
    __syncthreads();
    vtrans_body(xs, ci0, nt * 16, g_Vc_hi, g_Vc_lo);
}

// ---------------------------------------------------------------------------
// Winograd point GEMM: M[pt] = U[pt] @ V[pt]^T (K=512).
// Block 128m x 128n, 256 threads (warps 4m x 2n), K-chunk 32, 2-stage
// cp.async, stride-80 rows (ldmatrix conflict-free). 2 CTAs/SM.
// Pointers selected IN DEVICE CODE (host may not pass __device__ symbols).
// ---------------------------------------------------------------------------
#define WROWB   80
#define WA_LO   10240
#define WB_HI   20480
#define WB_LO   30720
#define WSTAGE  40960
#define WSMEM   81920
#define WKCH    16            // 512 / 32

__device__ __forceinline__ void wload_stage(
    uint32_t sb, int s, int chunk,
    const __nv_bfloat16* __restrict__ Ah, const __nv_bfloat16* __restrict__ Al,
    const __nv_bfloat16* __restrict__ Bh, const __nv_bfloat16* __restrict__ Bl,
    int tid)
{
    const int k0 = chunk * 32;
    const uint32_t base = sb + s * WSTAGE;
#pragma unroll
    for (int it = 0; it < 2; ++it) {
        const int idx = tid + it * 256;          // 512 = 128 rows x 4 parts
        const int row = idx >> 2, part = idx & 3;
        const uint32_t so = row * WROWB + part * 16;
        const size_t g = (size_t)row * 512 + k0 + part * 8;
        cp16(base + so,          Ah + g);
        cp16(base + WA_LO + so,  Al + g);
        cp16(base + WB_HI + so,  Bh + g);
        cp16(base + WB_LO + so,  Bl + g);
    }
}

__device__ __forceinline__ void wcompute_stage(uint32_t sb, int s,
                                               float acc[2][8][4], int tid)
{
    const int wid = tid >> 5, lane = tid & 31;
    const int wm = wid >> 1, wn = wid & 1;       // 4m x 2n
    const uint32_t stage = sb + s * WSTAGE;

    const int a_moff = ((lane >> 3) & 1) * 8 + (lane & 7);
    const int a_kb   = ((lane >> 4) & 1) * 16;
    const int b_noff = ((lane >> 4) & 1) * 8 + (lane & 7);
    const int b_kb   = ((lane >> 3) & 1) * 16;

    const uint32_t aBase = stage + (uint32_t)(wm * 32 + a_moff) * WROWB + a_kb;
    const uint32_t bBase = stage + WB_HI + (uint32_t)(wn * 64 + b_noff) * WROWB + b_kb;

#pragma unroll
    for (int ks = 0; ks < 2; ++ks) {
        const uint32_t ko = ks * 32;
        uint32_t ah[2][4], al[2][4];
#pragma unroll
        for (int mt = 0; mt < 2; ++mt) {
            const uint32_t a0 = aBase + mt * (16 * WROWB) + ko;
            ldsm4(ah[mt][0], ah[mt][1], ah[mt][2], ah[mt][3], a0);
            ldsm4(al[mt][0], al[mt][1], al[mt][2], al[mt][3], a0 + WA_LO);
        }
#pragma unroll
        for (int p = 0; p < 4; ++p) {
            uint32_t bh0, bh1, bh2, bh3, bl0, bl1, bl2, bl3;
            const uint32_t b0 = bBase + p * (16 * WROWB) + ko;
            ldsm4(bh0, bh1, bh2, bh3, b0);
            ldsm4(bl0, bl1, bl2, bl3, b0 + (WB_LO - WB_HI));
#pragma unroll
            for (int mt = 0; mt < 2; ++mt) {
                mma16816(acc[mt][2*p],   ah[mt][0], ah[mt][1], ah[mt][2], ah[mt][3], bh0, bh1);
                mma16816(acc[mt][2*p],   ah[mt][0], ah[mt][1], ah[mt][2], ah[mt][3], bl0, bl1);
                mma16816(acc[mt][2*p],   al[mt][0], al[mt][1], al[mt][2], al[mt][3], bh0, bh1);
                mma16816(acc[mt][2*p+1], ah[mt][0], ah[mt][1], ah[mt][2], ah[mt][3], bh2, bh3);
                mma16816(acc[mt][2*p+1], ah[mt][0], ah[mt][1], ah[mt][2], ah[mt][3], bl2, bl3);
                mma16816(acc[mt][2*p+1], al[mt][0], al[mt][1], al[mt][2], al[mt][3], bh2, bh3);
            }
        }
    }
}

__global__ __launch_bounds__(256, 2) void gemm_wino_kernel(int which)
{
    extern __shared__ char smem[];
    const uint32_t sb = smem_u32(smem);
    const int tid = threadIdx.x;
    const int mt = blockIdx.x;
    const int nb = blockIdx.y * 128;
    const int pt = blockIdx.z;

    // Select operand arrays in DEVICE code (device symbols valid here).
    const __nv_bfloat16 *Uh, *Ul, *Vh, *Vl;
    int mrows;
    if (which == 0) {
        Uh = g_Ux_hi; Ul = g_Ux_lo; Vh = g_Vx_hi; Vl = g_Vx_lo; mrows = 1536;
    } else {
        Uh = g_Uc_hi; Ul = g_Uc_lo; Vh = g_Vc_hi; Vl = g_Vc_lo; mrows = 512;
    }

    const __nv_bfloat16* Ah = Uh + ((size_t)pt * mrows + mt * 128) * 512;
    const __nv_bfloat16* Al = Ul + ((size_t)pt * mrows + mt * 128) * 512;
    const __nv_bfloat16* Bh = Vh + ((size_t)pt * NTILES + nb) * 512;
    const __nv_bfloat16* Bl = Vl + ((size_t)pt * NTILES + nb) * 512;

    float acc[2][8][4];
#pragma unroll
    for (int a = 0; a < 2; a++)
#pragma unroll
        for (int b = 0; b < 8; b++)
#pragma unroll
            for (int c = 0; c < 4; c++) acc[a][b][c] = 0.f;

    wload_stage(sb, 0, 0, Ah, Al, Bh, Bl, tid); cp_commit();
    wload_stage(sb, 1, 1, Ah, Al, Bh, Bl, tid); cp_commit();
    for (int c = 0; c < WKCH; ++c) {
        cp_wait1();
        __syncthreads();
        wcompute_stage(sb, c & 1, acc, tid);
        __syncthreads();
        if (c + 2 < WKCH)
            wload_stage(sb, c & 1, c + 2, Ah, Al, Bh, Bl, tid);
        cp_commit();
    }
    __syncthreads();

    // epilogue: stage to smem [128 m][132], then coalesced M write
    const int wid = tid >> 5, lane = tid & 31;
    const int wm = wid >> 1, wn = wid & 1;
    const int g = lane >> 2, q2 = (lane & 3) * 2;
#pragma unroll
    for (int m2 = 0; m2 < 2; m2++)
#pragma unroll
        for (int nt = 0; nt < 8; nt++) {
            const int row = wm * 32 + m2 * 16 + g;
            const int col = wn * 64 + nt * 8 + q2;
            const float* c = acc[m2][nt];
            sts32f(sb + (uint32_t)((row)     * 132 + col)     * 4, c[0]);
            sts32f(sb + (uint32_t)((row)     * 132 + col + 1) * 4, c[1]);
            sts32f(sb + (uint32_t)((row + 8) * 132 + col)     * 4, c[2]);
            sts32f(sb + (uint32_t)((row + 8) * 132 + col + 1) * 4, c[3]);
        }
    __syncthreads();

    for (int idx = tid; idx < 16384; idx += 256) {
        const int m = idx >> 7, col = idx & 127;
        g_M[((size_t)pt * mrows + mt * 128 + m) * NTILES + nb + col] =
            lds32f(sb + (uint32_t)(m * 132 + col) * 4);
    }
}

// ---------------------------------------------------------------------------
// Output transform (qkv): Y = A^T M A -> q/k/v [(loc*256+n)*512+co].
// ---------------------------------------------------------------------------
__global__ __launch_bounds__(256) void outtrans_qkv_kernel()
{
    __shared__ float ms[16][32][17];
    const int nt = blockIdx.x;
    const int n  = nt >> 2;
    const int t  = nt & 3;
    const int cobase = blockIdx.y * 32;
    const int tb = nt * 16;
    const int tid = threadIdx.x;

    for (int idx = tid; idx < 8192; idx += 256) {
        const int pt = idx >> 9;
        const int rem = idx & 511;
        const int co = rem >> 4, i = rem & 15;
        ms[pt][co][i] = g_M[((size_t)pt * 1536 + cobase + co) * NTILES + tb + i];
    }
    __syncthreads();

    const int co = tid & 31;
    const int tg = tid >> 5;
    const int co2 = cobase + co;
    float* arr = (co2 < 512) ? g_qA : (co2 < 1024) ? g_kA : g_vA;
    const int co_in = co2 & 511;

#pragma unroll
    for (int th = 0; th < 2; th++) {
        const int tile = tg + th * 8;
        const int ty = tile >> 2, tx = tile & 3;
        float m[4][4];
#pragma unroll
        for (int i = 0; i < 4; i++)
#pragma unroll
            for (int j = 0; j < 4; j++)
                m[i][j] = ms[i * 4 + j][co][tile];
        float s0[4], s1[4];
#pragma unroll
        for (int j = 0; j < 4; j++) {
            s0[j] = m[0][j] + m[1][j] + m[2][j];
            s1[j] = m[1][j] - m[2][j] - m[3][j];
        }
        const float y00 = s0[0] + s0[1] + s0[2];
        const float y01 = s0[1] - s0[2] - s0[3];
        const float y10 = s1[0] + s1[1] + s1[2];
        const float y11 = s1[1] - s1[2] - s1[3];

        const int l00 = t * 64 + (2 * ty) * 8 + 2 * tx;
        arr[((size_t)(l00)     * 256 + n) * 512 + co_in] = y00;
        arr[((size_t)(l00 + 1) * 256 + n) * 512 + co_in] = y01;
        arr[((size_t)(l00 + 8) * 256 + n) * 512 + co_in] = y10;
        arr[((size_t)(l00 + 9) * 256 + n) * 512 + co_in] = y11;
    }
}

// ---------------------------------------------------------------------------
// Output transform (conv_c) + residual -> d_out [n][co][loc].
// ---------------------------------------------------------------------------
__global__ __launch_bounds__(256) void outtrans_c_kernel(
    const float* __restrict__ x, float* __restrict__ out)
{
    __shared__ float ms[16][32][17];
    __shared__ float ys[32][65];
    const int nt = blockIdx.x;
    const int n  = nt >> 2;
    const int t  = nt & 3;
    const int cobase = blockIdx.y * 32;
    const int tb = nt * 16;
    const int tid = threadIdx.x;

    for (int idx = tid; idx < 8192; idx += 256) {
        const int pt = idx >> 9;
        const int rem = idx & 511;
        const int co = rem >> 4, i = rem & 15;
        ms[pt][co][i] = g_M[((size_t)pt * 512 + cobase + co) * NTILES + tb + i];
    }
    __syncthreads();

    const int co = tid & 31;
    const int tg = tid >> 5;
#pragma unroll
    for (int th = 0; th < 2; th++) {
        const int tile = tg + th * 8;
        const int ty = tile >> 2, tx = tile & 3;
        float m[4][4];
#pragma unroll
        for (int i = 0; i < 4; i++)
#pragma unroll
            for (int j = 0; j < 4; j++)
                m[i][j] = ms[i * 4 + j][co][tile];
        float s0[4], s1[4];
#pragma unroll
        for (int j = 0; j < 4; j++) {
            s0[j] = m[0][j] + m[1][j] + m[2][j];
            s1[j] = m[1][j] - m[2][j] - m[3][j];
        }
        const int p0 = 2 * ty * 8 + 2 * tx;
        ys[co][p0]     = s0[0] + s0[1] + s0[2];
        ys[co][p0 + 1] = s0[1] - s0[2] - s0[3];
        ys[co][p0 + 8] = s1[0] + s1[1] + s1[2];
        ys[co][p0 + 9] = s1[1] - s1[2] - s1[3];
    }
    __syncthreads();

    for (int idx = tid; idx < 2048; idx += 256) {
        const int c = idx >> 6, l = idx & 63;
        const size_t o = ((size_t)(n * 512 + cobase + c)) * 256 + t * 64 + l;
        out[o] = x[o] + ys[c][l];
    }
}

// ---------------------------------------------------------------------------
// Attention scores + mask + softmax (proven)
// ---------------------------------------------------------------------------
__global__ __launch_bounds__(256) void att_scores_kernel(const int* __restrict__ roi)
{
    __shared__ float qs[64][33];
    __shared__ float ks[256][33];
    __shared__ int   roi_s[256];

    const int loc = blockIdx.x;
    const int ib  = blockIdx.y * 64;
    const int tid = threadIdx.x;
    const int ig  = tid >> 5;
    const int jg  = tid & 31;

    if (tid < 256) roi_s[tid] = roi[tid];

    float acc[8][8];
#pragma unroll
    for (int ii = 0; ii < 8; ii++)
#pragma unroll
        for (int jj = 0; jj < 8; jj++) acc[ii][jj] = 0.f;

    for (int c0 = 0; c0 < CC; c0 += 32) {
        for (int idx = tid; idx < 64 * 32; idx += 256) {
            int i = idx >> 5, c = idx & 31;
            qs[i][c] = g_qA[((size_t)loc * NN + ib + i) * CC + c0 + c];
        }
        for (int idx = tid; idx < 256 * 32; idx += 256) {
            int j = idx >> 5, c = idx & 31;
            ks[j][c] = g_kA[((size_t)loc * NN + j) * CC + c0 + c];
        }
        __syncthreads();

#pragma unroll 4
        for (int c = 0; c < 32; c++) {
            float kv[8];
#pragma unroll
            for (int jj = 0; jj < 8; jj++) kv[jj] = ks[jg + 32 * jj][c];
#pragma unroll
            for (int ii = 0; ii < 8; ii++) {
                float qv = qs[ig + 8 * ii][c];
#pragma unroll
                for (int jj = 0; jj < 8; jj++) acc[ii][jj] += qv * kv[jj];
            }
        }
        __syncthreads();
    }

    const float scale = 0.044194173824159216f;

#pragma unroll
    for (int ii = 0; ii < 8; ii++) {
        const int i  = ib + ig + 8 * ii;
        const int ri = roi_s[i];
        float e[8];
        float m = -CUDART_INF_F;
#pragma unroll
        for (int jj = 0; jj < 8; jj++) {
            const int j = jg + 32 * jj;
            float v = (roi_s[j] == ri) ? acc[ii][jj] * scale : -CUDART_INF_F;
            e[jj] = v;
            m = fmaxf(m, v);
        }
#pragma unroll
        for (int off = 16; off > 0; off >>= 1)
            m = fmaxf(m, __shfl_xor_sync(0xffffffffu, m, off));
        float s = 0.f;
#pragma unroll
        for (int jj = 0; jj < 8; jj++) { float t_ = __expf(e[jj] - m); e[jj] = t_; s += t_; }
#pragma unroll
        for (int off = 16; off > 0; off >>= 1)
            s += __shfl_xor_sync(0xffffffffu, s, off);
        const float inv = 1.f / s;
#pragma unroll
        for (int jj = 0; jj < 8; jj++)
            g_att[((size_t)loc * NN + i) * NN + jg + 32 * jj] = e[jj] * inv;
    }
}

// ---------------------------------------------------------------------------
// virt = att @ v (proven)
// ---------------------------------------------------------------------------
__global__ __launch_bounds__(256) void att_apply_kernel()
{
    __shared__ float as[32][33];
    __shared__ float vs[32][256];

    const int loc = blockIdx.x;
    const int it  = blockIdx.y >> 1;
    const int ct  = blockIdx.y & 1;
    const int ib  = it * 32;
    const int cb  = ct * 256;
    const int tid = threadIdx.x;
    const int ig  = tid >> 5;
    const int cg  = tid & 31;

    float acc[4][8];
#pragma unroll
    for (int ii = 0; ii < 4; ii++)
#pragma unroll
        for (int cc = 0; cc < 8; cc++) acc[ii][cc] = 0.f;

    for (int j0 = 0; j0 < NN; j0 += 32) {
        for (int idx = tid; idx < 32 * 32; idx += 256) {
            int i = idx >> 5, j = idx & 31;
            as[i][j] = g_att[((size_t)loc * NN + ib + i) * NN + j0 + j];
        }
        for (int idx = tid; idx < 32 * 256; idx += 256) {
            int j = idx >> 8, c = idx & 255;
            vs[j][c] = g_vA[((size_t)loc * NN + j0 + j) * CC + cb + c];
        }
        __syncthreads();

#pragma unroll 4
        for (int j = 0; j < 32; j++) {
            float vv[8];
#pragma unroll
            for (int cc = 0; cc < 8; cc++) vv[cc] = vs[j][cg + 32 * cc];
#pragma unroll
            for (int ii = 0; ii < 4; ii++) {
                float av = as[ig + 8 * ii][j];
#pragma unroll
                for (int cc = 0; cc < 8; cc++) acc[ii][cc] += av * vv[cc];
            }
        }
        __syncthreads();
    }

#pragma unroll
    for (int ii = 0; ii < 4; ii++) {
        const int i = ib + ig + 8 * ii;
#pragma unroll
        for (int cc = 0; cc < 8; cc++) {
            const int c = cb + cg + 32 * cc;
            g_virt[((size_t)i * CC + c) * THW + loc] = acc[ii][cc];
        }
    }
}

// ---------------------------------------------------------------------------
// GroupNorm reduce
// ---------------------------------------------------------------------------
__global__ __launch_bounds__(256) void gn_reduce_kernel()
{
    __shared__ float red[16];
    const int n   = blockIdx.x;
    const int tid = threadIdx.x;
    const float* __restrict__ src = g_virt + (size_t)n * CC * THW;

    float s = 0.f, s2 = 0.f;
    for (int idx = tid; idx < CC * THW; idx += 256) {
        float v = src[idx];
        s += v; s2 += v * v;
    }
#pragma unroll
    for (int off = 16; off > 0; off >>= 1) {
        s  += __shfl_xor_sync(0xffffffffu, s,  off);
        s2 += __shfl_xor_sync(0xffffffffu, s2, off);
    }
    const int wid = tid >> 5, lane = tid & 31;
    if (lane == 0) { red[wid] = s; red[8 + wid] = s2; }
    __syncthreads();
    if (tid == 0) {
        float S = 0.f, S2 = 0.f;
#pragma unroll
        for (int w = 0; w < 8; w++) { S += red[w]; S2 += red[8 + w]; }
        const float M = (float)(CC * THW);
        float mu  = S / M;
        float var = S2 / M - mu * mu;
        g_mu[n]   = mu;
        g_rinv[n] = rsqrtf(var + 1e-5f);
    }
}

// ---------------------------------------------------------------------------
extern "C" void kernel_launch(void* const* d_in, const int* in_sizes, int n_in,
                              void* d_out, int out_size)
{
    const float* x     = (const float*)d_in[0];
    const int*   roi   = (const int*)  d_in[1];
    const float* Wq    = (const float*)d_in[2];
    const float* Wk    = (const float*)d_in[3];
    const float* Wv    = (const float*)d_in[4];
    const float* Wc    = (const float*)d_in[5];
    const float* gamma = (const float*)d_in[6];
    const float* beta  = (const float*)d_in[7];
    float* out = (float*)d_out;

    cudaFuncSetAttribute(gemm_wino_kernel,
                         cudaFuncAttributeMaxDynamicSharedMemorySize, WSMEM);

    wtrans_kernel<<<4096, 256>>>(Wq, Wk, Wv, Wc);
    vtransx_kernel<<<dim3(1024, 16), 256>>>(x);
    gemm_wino_kernel<<<dim3(12, 128, 16), 256, WSMEM>>>(0);
    outtrans_qkv_kernel<<<dim3(1024, 48), 256>>>();
    att_scores_kernel<<<dim3(256, 4), 256>>>(roi);
    att_apply_kernel<<<dim3(256, 16), 256>>>();
    gn_reduce_kernel<<<256, 256>>>();
    vtransc_kernel<<<dim3(1024, 16), 256>>>(gamma, beta);
    gemm_wino_kernel<<<dim3(4, 128, 16), 256, WSMEM>>>(1);
    outtrans_c_kernel<<<dim3(1024, 16), 256>>>(x, out);
}

// round 9
// speedup vs baseline: 7.2934x; 1.3697x over previous
#include <cuda_runtime.h>
#include <cuda_bf16.h>
#include <math_constants.h>
#include <cstdint>

// Problem constants
#define NN     256
#define CC     512
#define THW    256
#define NT4    4096            // 256 n * 4 t * 4 tiles(4x4)
#define PTS    36              // 6x6 Winograd F(4x4,3x3) points
#define NCTHW  33554432

// ---------------------------------------------------------------------------
// Scratch (static __device__ arrays — allocation is forbidden)
// ---------------------------------------------------------------------------
__device__ float g_qA[NCTHW];                 // [(loc*256+n)*512+c]
__device__ float g_kA[NCTHW];
__device__ float g_vA[NCTHW];
__device__ float g_att[THW * NN * NN];
__device__ float g_virt[NCTHW];               // [n][c][loc]
__device__ float g_mu[NN];
__device__ float g_rinv[NN];

// Winograd operands. U: [pt][co][ci], V: [pt][tile][ci], M: [pt][tile][co]
__device__ __nv_bfloat16 g_Ux_hi[(size_t)PTS * 1536 * 512];
__device__ __nv_bfloat16 g_Ux_lo[(size_t)PTS * 1536 * 512];
__device__ __nv_bfloat16 g_Uc_hi[(size_t)PTS * 512 * 512];
__device__ __nv_bfloat16 g_Uc_lo[(size_t)PTS * 512 * 512];
__device__ __nv_bfloat16 g_Vx_hi[(size_t)PTS * NT4 * 512];
__device__ __nv_bfloat16 g_Vx_lo[(size_t)PTS * NT4 * 512];
__device__ __nv_bfloat16 g_Vc_hi[(size_t)PTS * NT4 * 512];
__device__ __nv_bfloat16 g_Vc_lo[(size_t)PTS * NT4 * 512];
__device__ float g_M[(size_t)PTS * NT4 * 1536];   // [pt][tile][co]

// ---------------------------------------------------------------------------
// Portable-ISA helpers
// ---------------------------------------------------------------------------
__device__ __forceinline__ uint32_t smem_u32(const void* p) {
    uint32_t a;
    asm("{ .reg .u64 t; cvta.to.shared.u64 t, %1; cvt.u32.u64 %0, t; }"
        : "=r"(a) : "l"(p));
    return a;
}
__device__ __forceinline__ void cp16(uint32_t dst, const void* src) {
    asm volatile("cp.async.cg.shared.global [%0], [%1], 16;" :: "r"(dst), "l"(src));
}
__device__ __forceinline__ void cp_commit() { asm volatile("cp.async.commit_group;"); }
__device__ __forceinline__ void cp_wait1()  { asm volatile("cp.async.wait_group 1;" ::: "memory"); }

__device__ __forceinline__ void ldsm4(uint32_t& r0, uint32_t& r1, uint32_t& r2,
                                      uint32_t& r3, uint32_t addr) {
    asm volatile("ldmatrix.sync.aligned.m8n8.x4.shared.b16 {%0,%1,%2,%3}, [%4];"
        : "=r"(r0), "=r"(r1), "=r"(r2), "=r"(r3) : "r"(addr));
}
__device__ __forceinline__ void sts32f(uint32_t a, float v) {
    asm volatile("st.shared.f32 [%0], %1;" :: "r"(a), "f"(v));
}
__device__ __forceinline__ float lds32f(uint32_t a) {
    float v; asm volatile("ld.shared.f32 %0, [%1];" : "=f"(v) : "r"(a)); return v;
}
__device__ __forceinline__ void mma16816(float* c,
    uint32_t a0, uint32_t a1, uint32_t a2, uint32_t a3, uint32_t b0, uint32_t b1) {
    asm volatile("mma.sync.aligned.m16n8k16.row.col.f32.bf16.bf16.f32 "
        "{%0,%1,%2,%3}, {%4,%5,%6,%7}, {%8,%9}, {%0,%1,%2,%3};"
        : "+f"(c[0]), "+f"(c[1]), "+f"(c[2]), "+f"(c[3])
        : "r"(a0), "r"(a1), "r"(a2), "r"(a3), "r"(b0), "r"(b1));
}
__device__ __forceinline__ void bfsplit(float v, __nv_bfloat16& hi, __nv_bfloat16& lo) {
    hi = __float2bfloat16_rn(v);
    lo = __float2bfloat16_rn(v - __bfloat162float(hi));
}

// ---------------------------------------------------------------------------
// Weight transform F(4x4,3x3): U = G g G^T (6x6) per (co2, ci).
// G = [[1/4,0,0],[-1/6,-1/6,-1/6],[-1/6,1/6,-1/6],
//      [1/24,1/12,1/6],[1/24,-1/12,1/6],[0,0,1]]
// ---------------------------------------------------------------------------
__global__ __launch_bounds__(256) void wtrans_kernel(
    const float* __restrict__ Wq, const float* __restrict__ Wk,
    const float* __restrict__ Wv, const float* __restrict__ Wc)
{
    const int idx = blockIdx.x * 256 + threadIdx.x;   // 2048*512
    const int ci  = idx & 511;
    const int co2 = idx >> 9;
    const float* Wp;
    int co;
    if (co2 < 512)       { Wp = Wq; co = co2; }
    else if (co2 < 1024) { Wp = Wk; co = co2 - 512; }
    else if (co2 < 1536) { Wp = Wv; co = co2 - 1024; }
    else                 { Wp = Wc; co = co2 - 1536; }

    float g[3][3];
#pragma unroll
    for (int r = 0; r < 3; r++)
#pragma unroll
        for (int c = 0; c < 3; c++)
            g[r][c] = Wp[((size_t)co * 512 + ci) * 9 + r * 3 + c];

    const float c6 = 1.f / 6.f, c12 = 1.f / 12.f, c24 = 1.f / 24.f;
    float gg[6][3];
#pragma unroll
    for (int c = 0; c < 3; c++) {
        gg[0][c] = 0.25f * g[0][c];
        gg[1][c] = -c6 * (g[0][c] + g[1][c] + g[2][c]);
        gg[2][c] =  c6 * (-g[0][c] + g[1][c] - g[2][c]);
        gg[3][c] = c24 * g[0][c] + c12 * g[1][c] + c6 * g[2][c];
        gg[4][c] = c24 * g[0][c] - c12 * g[1][c] + c6 * g[2][c];
        gg[5][c] = g[2][c];
    }
#pragma unroll
    for (int r = 0; r < 6; r++) {
        float u[6];
        u[0] = 0.25f * gg[r][0];
        u[1] = -c6 * (gg[r][0] + gg[r][1] + gg[r][2]);
        u[2] =  c6 * (-gg[r][0] + gg[r][1] - gg[r][2]);
        u[3] = c24 * gg[r][0] + c12 * gg[r][1] + c6 * gg[r][2];
        u[4] = c24 * gg[r][0] - c12 * gg[r][1] + c6 * gg[r][2];
        u[5] = gg[r][2];
#pragma unroll
        for (int c = 0; c < 6; c++) {
            const int pt = r * 6 + c;
            __nv_bfloat16 hi, lo;
            bfsplit(u[c], hi, lo);
            if (co2 < 1536) {
                const size_t o = ((size_t)pt * 1536 + co2) * 512 + ci;
                g_Ux_hi[o] = hi; g_Ux_lo[o] = lo;
            } else {
                const size_t o = ((size_t)pt * 512 + co) * 512 + ci;
                g_Uc_hi[o] = hi; g_Uc_lo[o] = lo;
            }
        }
    }
}

// ---------------------------------------------------------------------------
// Input transform core: V = B^T d B (6x6). Thread = (ci 0..63, tile 0..3).
// B^T rows: [4,0,-5,0,1,0],[0,-4,-4,1,1,0],[0,4,-4,-1,1,0],
//           [0,-2,-1,2,1,0],[0,2,-1,-2,1,0],[0,4,0,-5,0,1]
// ---------------------------------------------------------------------------
__device__ __forceinline__ void vtrans6(const float d[6][6], float v[6][6])
{
    float t[6][6];
#pragma unroll
    for (int j = 0; j < 6; j++) {
        t[0][j] = 4.f * d[0][j] - 5.f * d[2][j] + d[4][j];
        t[1][j] = -4.f * d[1][j] - 4.f * d[2][j] + d[3][j] + d[4][j];
        t[2][j] =  4.f * d[1][j] - 4.f * d[2][j] - d[3][j] + d[4][j];
        t[3][j] = -2.f * d[1][j] - d[2][j] + 2.f * d[3][j] + d[4][j];
        t[4][j] =  2.f * d[1][j] - d[2][j] - 2.f * d[3][j] + d[4][j];
        t[5][j] =  4.f * d[1][j] - 5.f * d[3][j] + d[5][j];
    }
#pragma unroll
    for (int i = 0; i < 6; i++) {
        v[i][0] = 4.f * t[i][0] - 5.f * t[i][2] + t[i][4];
        v[i][1] = -4.f * t[i][1] - 4.f * t[i][2] + t[i][3] + t[i][4];
        v[i][2] =  4.f * t[i][1] - 4.f * t[i][2] - t[i][3] + t[i][4];
        v[i][3] = -2.f * t[i][1] - t[i][2] + 2.f * t[i][3] + t[i][4];
        v[i][4] =  2.f * t[i][1] - t[i][2] - 2.f * t[i][3] + t[i][4];
        v[i][5] =  4.f * t[i][1] - 5.f * t[i][3] + t[i][5];
    }
}

__device__ __forceinline__ void vtrans_body(
    const float* xs, int ci0, int tb,
    __nv_bfloat16* __restrict__ Vh, __nv_bfloat16* __restrict__ Vl)
{
    const int tid = threadIdx.x;
    const int ci = tid & 63;
    const int tile = tid >> 6;          // 0..3
    const int ty = tile >> 1, tx = tile & 1;

    float d[6][6];
#pragma unroll
    for (int r = 0; r < 6; r++)
#pragma unroll
        for (int c = 0; c < 6; c++)
            d[r][c] = xs[ci * 101 + (ty * 4 + r) * 10 + (tx * 4 + c)];

    float v[6][6];
    vtrans6(d, v);

#pragma unroll
    for (int i = 0; i < 6; i++)
#pragma unroll
        for (int j = 0; j < 6; j++) {
            const int pt = i * 6 + j;
            __nv_bfloat16 hi, lo;
            bfsplit(v[i][j], hi, lo);
            const size_t o = ((size_t)pt * NT4 + tb + tile) * 512 + ci0 + ci;
            Vh[o] = hi; Vl[o] = lo;
        }
}

// Input transform of x. grid (1024 = n*t, 8 ci-chunks of 64), block 256.
__global__ __launch_bounds__(256) void vtransx_kernel(const float* __restrict__ x)
{
    __shared__ float xs[64 * 101];
    const int nt = blockIdx.x;
    const int n  = nt >> 2;
    const int t  = nt & 3;
    const int ci0 = blockIdx.y * 64;
    const int tid = threadIdx.x;

    for (int idx = tid; idx < 6400; idx += 256) {
        const int i = idx / 100;
        const int rc = idx % 100;
        const int r = rc / 10, c = rc % 10;
        const int hh = r - 1, ww = c - 1;
        float v = 0.f;
        if (hh >= 0 && hh < 8 && ww >= 0 && ww < 8)
            v = x[((size_t)(n * 512 + ci0 + i)) * 256 + t * 64 + hh * 8 + ww];
        xs[i * 101 + r * 10 + c] = v;
    }
    __syncthreads();
    vtrans_body(xs, ci0, nt * 4, g_Vx_hi, g_Vx_lo);
}

// Input transform of GN(virt)+ReLU. grid (1024, 8), block 256.
__global__ __launch_bounds__(256) void vtransc_kernel(
    const float* __restrict__ gamma, const float* __restrict__ beta)
{
    __shared__ float xs[64 * 101];
    const int nt = blockIdx.x;
    const int n  = nt >> 2;
    const int t  = nt & 3;
    const int ci0 = blockIdx.y * 64;
    const int tid = threadIdx.x;
    const float mu = g_mu[n], ri = g_rinv[n];

    for (int idx = tid; idx < 6400; idx += 256) {
        const int i = idx / 100;
        const int rc = idx % 100;
        const int r = rc / 10, c = rc % 10;
        const int hh = r - 1, ww = c - 1;
        float v = 0.f;
        if (hh >= 0 && hh < 8 && ww >= 0 && ww < 8) {
            float u = g_virt[((size_t)(n * 512 + ci0 + i)) * 256 + t * 64 + hh * 8 + ww];
            u = (u - mu) * ri * gamma[ci0 + i] + beta[ci0 + i];
            v = fmaxf(u, 0.f);
        }
        xs[i * 101 + r * 10 + c] = v;
    }
    __syncthreads();
    vtrans_body(xs, ci0, nt * 4, g_Vc_hi, g_Vc_lo);
}

// ---------------------------------------------------------------------------
// Winograd point GEMM: M[pt][tile][co] = V[pt] x U[pt] (K=512).
// Block 128m(co) x 128n(tile), 256 threads (warps 4m x 2n), K-chunk 32,
// 2-stage cp.async, stride-80 rows (ldmatrix conflict-free). 2 CTAs/SM.
// ---------------------------------------------------------------------------
#define WROWB   80
#define WA_LO   10240
#define WB_HI   20480
#define WB_LO   30720
#define WSTAGE  40960
#define WSMEM   81920
#define WKCH    16            // 512 / 32

__device__ __forceinline__ void wload_stage(
    uint32_t sb, int s, int chunk,
    const __nv_bfloat16* __restrict__ Ah, const __nv_bfloat16* __restrict__ Al,
    const __nv_bfloat16* __restrict__ Bh, const __nv_bfloat16* __restrict__ Bl,
    int tid)
{
    const int k0 = chunk * 32;
    const uint32_t base = sb + s * WSTAGE;
#pragma unroll
    for (int it = 0; it < 2; ++it) {
        const int idx = tid + it * 256;          // 512 = 128 rows x 4 parts
        const int row = idx >> 2, part = idx & 3;
        const uint32_t so = row * WROWB + part * 16;
        const size_t g = (size_t)row * 512 + k0 + part * 8;
        cp16(base + so,          Ah + g);
        cp16(base + WA_LO + so,  Al + g);
        cp16(base + WB_HI + so,  Bh + g);
        cp16(base + WB_LO + so,  Bl + g);
    }
}

__device__ __forceinline__ void wcompute_stage(uint32_t sb, int s,
                                               float acc[2][8][4], int tid)
{
    const int wid = tid >> 5, lane = tid & 31;
    const int wm = wid >> 1, wn = wid & 1;       // 4m x 2n
    const uint32_t stage = sb + s * WSTAGE;

    const int a_moff = ((lane >> 3) & 1) * 8 + (lane & 7);
    const int a_kb   = ((lane >> 4) & 1) * 16;
    const int b_noff = ((lane >> 4) & 1) * 8 + (lane & 7);
    const int b_kb   = ((lane >> 3) & 1) * 16;

    const uint32_t aBase = stage + (uint32_t)(wm * 32 + a_moff) * WROWB + a_kb;
    const uint32_t bBase = stage + WB_HI + (uint32_t)(wn * 64 + b_noff) * WROWB + b_kb;

#pragma unroll
    for (int ks = 0; ks < 2; ++ks) {
        const uint32_t ko = ks * 32;
        uint32_t ah[2][4], al[2][4];
#pragma unroll
        for (int mt = 0; mt < 2; ++mt) {
            const uint32_t a0 = aBase + mt * (16 * WROWB) + ko;
            ldsm4(ah[mt][0], ah[mt][1], ah[mt][2], ah[mt][3], a0);
            ldsm4(al[mt][0], al[mt][1], al[mt][2], al[mt][3], a0 + WA_LO);
        }
#pragma unroll
        for (int p = 0; p < 4; ++p) {
            uint32_t bh0, bh1, bh2, bh3, bl0, bl1, bl2, bl3;
            const uint32_t b0 = bBase + p * (16 * WROWB) + ko;
            ldsm4(bh0, bh1, bh2, bh3, b0);
            ldsm4(bl0, bl1, bl2, bl3, b0 + (WB_LO - WB_HI));
#pragma unroll
            for (int mt = 0; mt < 2; ++mt) {
                mma16816(acc[mt][2*p],   ah[mt][0], ah[mt][1], ah[mt][2], ah[mt][3], bh0, bh1);
                mma16816(acc[mt][2*p],   ah[mt][0], ah[mt][1], ah[mt][2], ah[mt][3], bl0, bl1);
                mma16816(acc[mt][2*p],   al[mt][0], al[mt][1], al[mt][2], al[mt][3], bh0, bh1);
                mma16816(acc[mt][2*p+1], ah[mt][0], ah[mt][1], ah[mt][2], ah[mt][3], bh2, bh3);
                mma16816(acc[mt][2*p+1], ah[mt][0], ah[mt][1], ah[mt][2], ah[mt][3], bl2, bl3);
                mma16816(acc[mt][2*p+1], al[mt][0], al[mt][1], al[mt][2], al[mt][3], bh2, bh3);
            }
        }
    }
}

__global__ __launch_bounds__(256, 2) void gemm_wino_kernel(int which)
{
    extern __shared__ char smem[];
    const uint32_t sb = smem_u32(smem);
    const int tid = threadIdx.x;
    const int mt = blockIdx.x;
    const int nb = blockIdx.y * 128;
    const int pt = blockIdx.z;

    const __nv_bfloat16 *Uh, *Ul, *Vh, *Vl;
    int mrows;
    if (which == 0) {
        Uh = g_Ux_hi; Ul = g_Ux_lo; Vh = g_Vx_hi; Vl = g_Vx_lo; mrows = 1536;
    } else {
        Uh = g_Uc_hi; Ul = g_Uc_lo; Vh = g_Vc_hi; Vl = g_Vc_lo; mrows = 512;
    }

    const __nv_bfloat16* Ah = Uh + ((size_t)pt * mrows + mt * 128) * 512;
    const __nv_bfloat16* Al = Ul + ((size_t)pt * mrows + mt * 128) * 512;
    const __nv_bfloat16* Bh = Vh + ((size_t)pt * NT4 + nb) * 512;
    const __nv_bfloat16* Bl = Vl + ((size_t)pt * NT4 + nb) * 512;

    float acc[2][8][4];
#pragma unroll
    for (int a = 0; a < 2; a++)
#pragma unroll
        for (int b = 0; b < 8; b++)
#pragma unroll
            for (int c = 0; c < 4; c++) acc[a][b][c] = 0.f;

    wload_stage(sb, 0, 0, Ah, Al, Bh, Bl, tid); cp_commit();
    wload_stage(sb, 1, 1, Ah, Al, Bh, Bl, tid); cp_commit();
    for (int c = 0; c < WKCH; ++c) {
        cp_wait1();
        __syncthreads();
        wcompute_stage(sb, c & 1, acc, tid);
        __syncthreads();
        if (c + 2 < WKCH)
            wload_stage(sb, c & 1, c + 2, Ah, Al, Bh, Bl, tid);
        cp_commit();
    }
    __syncthreads();

    // epilogue: stage transposed buf[tile][co] ([128][132]) then coalesced
    // write to M[pt][tile][co] (co contiguous).
    const int wid = tid >> 5, lane = tid & 31;
    const int wm = wid >> 1, wn = wid & 1;
    const int g = lane >> 2, q2 = (lane & 3) * 2;
#pragma unroll
    for (int m2 = 0; m2 < 2; m2++)
#pragma unroll
        for (int nt = 0; nt < 8; nt++) {
            const int row = wm * 32 + m2 * 16 + g;          // co local
            const int col = wn * 64 + nt * 8 + q2;          // tile local
            const float* c = acc[m2][nt];
            sts32f(sb + (uint32_t)((col)     * 132 + row)     * 4, c[0]);
            sts32f(sb + (uint32_t)((col + 1) * 132 + row)     * 4, c[1]);
            sts32f(sb + (uint32_t)((col)     * 132 + row + 8) * 4, c[2]);
            sts32f(sb + (uint32_t)((col + 1) * 132 + row + 8) * 4, c[3]);
        }
    __syncthreads();

    for (int idx = tid; idx < 16384; idx += 256) {
        const int col = idx >> 7, m = idx & 127;
        g_M[((size_t)pt * NT4 + nb + col) * mrows + mt * 128 + m] =
            lds32f(sb + (uint32_t)(col * 132 + m) * 4);
    }
}

// ---------------------------------------------------------------------------
// Output transform (qkv): Y = A^T M A -> q/k/v [(loc*256+n)*512+co].
// A^T = [[1,1,1,1,1,0],[0,1,-1,2,-2,0],[0,1,1,4,4,0],[0,1,-1,8,-8,1]]
// grid (1024 = n*t, 48 co-chunks of 32), block 256 = 32co x (4tile x 2half).
// ---------------------------------------------------------------------------
__device__ __forceinline__ void at_rows(const float m[6][6], int i, float s[6])
{
#pragma unroll
    for (int j = 0; j < 6; j++) {
        if (i == 0)      s[j] = m[0][j] + m[1][j] + m[2][j] + m[3][j] + m[4][j];
        else if (i == 1) s[j] = m[1][j] - m[2][j] + 2.f * (m[3][j] - m[4][j]);
        else if (i == 2) s[j] = m[1][j] + m[2][j] + 4.f * (m[3][j] + m[4][j]);
        else             s[j] = m[1][j] - m[2][j] + 8.f * (m[3][j] - m[4][j]) + m[5][j];
    }
}
__device__ __forceinline__ void at_cols(const float s[6], float y[4])
{
    y[0] = s[0] + s[1] + s[2] + s[3] + s[4];
    y[1] = s[1] - s[2] + 2.f * (s[3] - s[4]);
    y[2] = s[1] + s[2] + 4.f * (s[3] + s[4]);
    y[3] = s[1] - s[2] + 8.f * (s[3] - s[4]) + s[5];
}

__global__ __launch_bounds__(256) void outtrans_qkv_kernel()
{
    __shared__ float ms[PTS][32][5];
    const int nt = blockIdx.x;
    const int n  = nt >> 2;
    const int t  = nt & 3;
    const int cobase = blockIdx.y * 32;
    const int tid = threadIdx.x;

    for (int idx = tid; idx < PTS * 128; idx += 256) {
        const int pt = idx >> 7;
        const int rem = idx & 127;
        const int tile = rem >> 5, co = rem & 31;
        ms[pt][co][tile] = g_M[((size_t)pt * NT4 + nt * 4 + tile) * 1536 + cobase + co];
    }
    __syncthreads();

    const int co = tid & 31;
    const int tg = tid >> 5;
    const int tile = tg & 3, half = tg >> 2;
    const int ty = tile >> 1, tx = tile & 1;
    const int co2 = cobase + co;
    float* arr = (co2 < 512) ? g_qA : (co2 < 1024) ? g_kA : g_vA;
    const int co_in = co2 & 511;

    float m[6][6];
#pragma unroll
    for (int i = 0; i < 6; i++)
#pragma unroll
        for (int j = 0; j < 6; j++)
            m[i][j] = ms[i * 6 + j][co][tile];

#pragma unroll
    for (int ii = 0; ii < 2; ii++) {
        const int i = half * 2 + ii;
        float s[6], y[4];
        at_rows(m, i, s);
        at_cols(s, y);
        const int loc0 = t * 64 + (ty * 4 + i) * 8 + tx * 4;
#pragma unroll
        for (int k = 0; k < 4; k++)
            arr[((size_t)(loc0 + k) * 256 + n) * 512 + co_in] = y[k];
    }
}

// ---------------------------------------------------------------------------
// Output transform (conv_c) + residual -> d_out [n][co][loc].
// grid (1024, 16 co-chunks of 32), block 256.
// ---------------------------------------------------------------------------
__global__ __launch_bounds__(256) void outtrans_c_kernel(
    const float* __restrict__ x, float* __restrict__ out)
{
    __shared__ float ms[PTS][32][5];
    __shared__ float ys[32][65];
    const int nt = blockIdx.x;
    const int n  = nt >> 2;
    const int t  = nt & 3;
    const int cobase = blockIdx.y * 32;
    const int tid = threadIdx.x;

    for (int idx = tid; idx < PTS * 128; idx += 256) {
        const int pt = idx >> 7;
        const int rem = idx & 127;
        const int tile = rem >> 5, co = rem & 31;
        ms[pt][co][tile] = g_M[((size_t)pt * NT4 + nt * 4 + tile) * 512 + cobase + co];
    }
    __syncthreads();

    const int co = tid & 31;
    const int tg = tid >> 5;
    const int tile = tg & 3, half = tg >> 2;
    const int ty = tile >> 1, tx = tile & 1;

    float m[6][6];
#pragma unroll
    for (int i = 0; i < 6; i++)
#pragma unroll
        for (int j = 0; j < 6; j++)
            m[i][j] = ms[i * 6 + j][co][tile];

#pragma unroll
    for (int ii = 0; ii < 2; ii++) {
        const int i = half * 2 + ii;
        float s[6], y[4];
        at_rows(m, i, s);
        at_cols(s, y);
        const int p0 = (ty * 4 + i) * 8 + tx * 4;
#pragma unroll
        for (int k = 0; k < 4; k++)
            ys[co][p0 + k] = y[k];
    }
    __syncthreads();

    for (int idx = tid; idx < 2048; idx += 256) {
        const int c = idx >> 6, l = idx & 63;
        const size_t o = ((size_t)(n * 512 + cobase + c)) * 256 + t * 64 + l;
        out[o] = x[o] + ys[c][l];
    }
}

// ---------------------------------------------------------------------------
// Attention scores + mask + softmax (proven)
// ---------------------------------------------------------------------------
__global__ __launch_bounds__(256) void att_scores_kernel(const int* __restrict__ roi)
{
    __shared__ float qs[64][33];
    __shared__ float ks[256][33];
    __shared__ int   roi_s[256];

    const int loc = blockIdx.x;
    const int ib  = blockIdx.y * 64;
    const int tid = threadIdx.x;
    const int ig  = tid >> 5;
    const int jg  = tid & 31;

    if (tid < 256) roi_s[tid] = roi[tid];

    float acc[8][8];
#pragma unroll
    for (int ii = 0; ii < 8; ii++)
#pragma unroll
        for (int jj = 0; jj < 8; jj++) acc[ii][jj] = 0.f;

    for (int c0 = 0; c0 < CC; c0 += 32) {
        for (int idx = tid; idx < 64 * 32; idx += 256) {
            int i = idx >> 5, c = idx & 31;
            qs[i][c] = g_qA[((size_t)loc * NN + ib + i) * CC + c0 + c];
        }
        for (int idx = tid; idx < 256 * 32; idx += 256) {
            int j = idx >> 5, c = idx & 31;
            ks[j][c] = g_kA[((size_t)loc * NN + j) * CC + c0 + c];
        }
        __syncthreads();

#pragma unroll 4
        for (int c = 0; c < 32; c++) {
            float kv[8];
#pragma unroll
            for (int jj = 0; jj < 8; jj++) kv[jj] = ks[jg + 32 * jj][c];
#pragma unroll
            for (int ii = 0; ii < 8; ii++) {
                float qv = qs[ig + 8 * ii][c];
#pragma unroll
                for (int jj = 0; jj < 8; jj++) acc[ii][jj] += qv * kv[jj];
            }
        }
        __syncthreads();
    }

    const float scale = 0.044194173824159216f;

#pragma unroll
    for (int ii = 0; ii < 8; ii++) {
        const int i  = ib + ig + 8 * ii;
        const int ri = roi_s[i];
        float e[8];
        float m = -CUDART_INF_F;
#pragma unroll
        for (int jj = 0; jj < 8; jj++) {
            const int j = jg + 32 * jj;
            float v = (roi_s[j] == ri) ? acc[ii][jj] * scale : -CUDART_INF_F;
            e[jj] = v;
            m = fmaxf(m, v);
        }
#pragma unroll
        for (int off = 16; off > 0; off >>= 1)
            m = fmaxf(m, __shfl_xor_sync(0xffffffffu, m, off));
        float s = 0.f;
#pragma unroll
        for (int jj = 0; jj < 8; jj++) { float t_ = __expf(e[jj] - m); e[jj] = t_; s += t_; }
#pragma unroll
        for (int off = 16; off > 0; off >>= 1)
            s += __shfl_xor_sync(0xffffffffu, s, off);
        const float inv = 1.f / s;
#pragma unroll
        for (int jj = 0; jj < 8; jj++)
            g_att[((size_t)loc * NN + i) * NN + jg + 32 * jj] = e[jj] * inv;
    }
}

// ---------------------------------------------------------------------------
// virt = att @ v (proven)
// ---------------------------------------------------------------------------
__global__ __launch_bounds__(256) void att_apply_kernel()
{
    __shared__ float as[32][33];
    __shared__ float vs[32][256];

    const int loc = blockIdx.x;
    const int it  = blockIdx.y >> 1;
    const int ct  = blockIdx.y & 1;
    const int ib  = it * 32;
    const int cb  = ct * 256;
    const int tid = threadIdx.x;
    const int ig  = tid >> 5;
    const int cg  = tid & 31;

    float acc[4][8];
#pragma unroll
    for (int ii = 0; ii < 4; ii++)
#pragma unroll
        for (int cc = 0; cc < 8; cc++) acc[ii][cc] = 0.f;

    for (int j0 = 0; j0 < NN; j0 += 32) {
        for (int idx = tid; idx < 32 * 32; idx += 256) {
            int i = idx >> 5, j = idx & 31;
            as[i][j] = g_att[((size_t)loc * NN + ib + i) * NN + j0 + j];
        }
        for (int idx = tid; idx < 32 * 256; idx += 256) {
            int j = idx >> 8, c = idx & 255;
            vs[j][c] = g_vA[((size_t)loc * NN + j0 + j) * CC + cb + c];
        }
        __syncthreads();

#pragma unroll 4
        for (int j = 0; j < 32; j++) {
            float vv[8];
#pragma unroll
            for (int cc = 0; cc < 8; cc++) vv[cc] = vs[j][cg + 32 * cc];
#pragma unroll
            for (int ii = 0; ii < 4; ii++) {
                float av = as[ig + 8 * ii][j];
#pragma unroll
                for (int cc = 0; cc < 8; cc++) acc[ii][cc] += av * vv[cc];
            }
        }
        __syncthreads();
    }

#pragma unroll
    for (int ii = 0; ii < 4; ii++) {
        const int i = ib + ig + 8 * ii;
#pragma unroll
        for (int cc = 0; cc < 8; cc++) {
            const int c = cb + cg + 32 * cc;
            g_virt[((size_t)i * CC + c) * THW + loc] = acc[ii][cc];
        }
    }
}

// ---------------------------------------------------------------------------
// GroupNorm reduce
// ---------------------------------------------------------------------------
__global__ __launch_bounds__(256) void gn_reduce_kernel()
{
    __shared__ float red[16];
    const int n   = blockIdx.x;
    const int tid = threadIdx.x;
    const float* __restrict__ src = g_virt + (size_t)n * CC * THW;

    float s = 0.f, s2 = 0.f;
    for (int idx = tid; idx < CC * THW; idx += 256) {
        float v = src[idx];
        s += v; s2 += v * v;
    }
#pragma unroll
    for (int off = 16; off > 0; off >>= 1) {
        s  += __shfl_xor_sync(0xffffffffu, s,  off);
        s2 += __shfl_xor_sync(0xffffffffu, s2, off);
    }
    const int wid = tid >> 5, lane = tid & 31;
    if (lane == 0) { red[wid] = s; red[8 + wid] = s2; }
    __syncthreads();
    if (tid == 0) {
        float S = 0.f, S2 = 0.f;
#pragma unroll
        for (int w = 0; w < 8; w++) { S += red[w]; S2 += red[8 + w]; }
        const float M = (float)(CC * THW);
        float mu  = S / M;
        float var = S2 / M - mu * mu;
        g_mu[n]   = mu;
        g_rinv[n] = rsqrtf(var + 1e-5f);
    }
}

// ---------------------------------------------------------------------------
extern "C" void kernel_launch(void* const* d_in, const int* in_sizes, int n_in,
                              void* d_out, int out_size)
{
    const float* x     = (const float*)d_in[0];
    const int*   roi   = (const int*)  d_in[1];
    const float* Wq    = (const float*)d_in[2];
    const float* Wk    = (const float*)d_in[3];
    const float* Wv    = (const float*)d_in[4];
    const float* Wc    = (const float*)d_in[5];
    const float* gamma = (const float*)d_in[6];
    const float* beta  = (const float*)d_in[7];
    float* out = (float*)d_out;

    cudaFuncSetAttribute(gemm_wino_kernel,
                         cudaFuncAttributeMaxDynamicSharedMemorySize, WSMEM);

    wtrans_kernel<<<4096, 256>>>(Wq, Wk, Wv, Wc);
    vtransx_kernel<<<dim3(1024, 8), 256>>>(x);
    gemm_wino_kernel<<<dim3(12, 32, PTS), 256, WSMEM>>>(0);
    outtrans_qkv_kernel<<<dim3(1024, 48), 256>>>();
    att_scores_kernel<<<dim3(256, 4), 256>>>(roi);
    att_apply_kernel<<<dim3(256, 16), 256>>>();
    gn_reduce_kernel<<<256, 256>>>();
    vtransc_kernel<<<dim3(1024, 8), 256>>>(gamma, beta);
    gemm_wino_kernel<<<dim3(4, 32, PTS), 256, WSMEM>>>(1);
    outtrans_c_kernel<<<dim3(1024, 16), 256>>>(x, out);
}

// round 12
// speedup vs baseline: 7.6323x; 1.0465x over previous
#include <cuda_runtime.h>
#include <cuda_bf16.h>
#include <math_constants.h>
#include <cstdint>

// Problem constants
#define NN     256
#define CC     512
#define THW    256
#define NT4    4096            // 256 n * 4 t * 4 tiles(4x4)
#define PTS    36              // 6x6 Winograd F(4x4,3x3) points
#define NCTHW  33554432

// ---------------------------------------------------------------------------
// Scratch (static __device__ arrays — allocation is forbidden)
// ---------------------------------------------------------------------------
__device__ __nv_bfloat16 g_qh[NCTHW], g_ql[NCTHW];   // [(loc*256+n)*512+c]
__device__ __nv_bfloat16 g_kh[NCTHW], g_kl[NCTHW];
__device__ float g_vA[NCTHW];                        // [(loc*256+n)*512+c]  (R8)
__device__ float g_att[THW * NN * NN];               // [loc][i][j]          (R8)
__device__ float g_virt[NCTHW];                      // [n][c][loc]          (R8)
__device__ float g_psum[NN][8], g_psum2[NN][8];
__device__ float g_mu[NN], g_rinv[NN];

// Winograd operands. U: [pt][co][ci], V: [pt][tile][ci], M: [pt][tile][co]
__device__ __nv_bfloat16 g_Ux_hi[(size_t)PTS * 1536 * 512];
__device__ __nv_bfloat16 g_Ux_lo[(size_t)PTS * 1536 * 512];
__device__ __nv_bfloat16 g_Uc_hi[(size_t)PTS * 512 * 512];
__device__ __nv_bfloat16 g_Uc_lo[(size_t)PTS * 512 * 512];
__device__ __nv_bfloat16 g_Vx_hi[(size_t)PTS * NT4 * 512];
__device__ __nv_bfloat16 g_Vx_lo[(size_t)PTS * NT4 * 512];
__device__ __nv_bfloat16 g_Vc_hi[(size_t)PTS * NT4 * 512];
__device__ __nv_bfloat16 g_Vc_lo[(size_t)PTS * NT4 * 512];
__device__ float g_M[(size_t)PTS * NT4 * 1536];      // [pt][tile][co]

// ---------------------------------------------------------------------------
// Portable-ISA helpers
// ---------------------------------------------------------------------------
__device__ __forceinline__ uint32_t smem_u32(const void* p) {
    uint32_t a;
    asm("{ .reg .u64 t; cvta.to.shared.u64 t, %1; cvt.u32.u64 %0, t; }"
        : "=r"(a) : "l"(p));
    return a;
}
__device__ __forceinline__ void cp16(uint32_t dst, const void* src) {
    asm volatile("cp.async.cg.shared.global [%0], [%1], 16;" :: "r"(dst), "l"(src));
}
__device__ __forceinline__ void cp_commit() { asm volatile("cp.async.commit_group;"); }
__device__ __forceinline__ void cp_wait1()  { asm volatile("cp.async.wait_group 1;" ::: "memory"); }

__device__ __forceinline__ void ldsm4(uint32_t& r0, uint32_t& r1, uint32_t& r2,
                                      uint32_t& r3, uint32_t addr) {
    asm volatile("ldmatrix.sync.aligned.m8n8.x4.shared.b16 {%0,%1,%2,%3}, [%4];"
        : "=r"(r0), "=r"(r1), "=r"(r2), "=r"(r3) : "r"(addr));
}
__device__ __forceinline__ void sts32f(uint32_t a, float v) {
    asm volatile("st.shared.f32 [%0], %1;" :: "r"(a), "f"(v));
}
__device__ __forceinline__ float lds32f(uint32_t a) {
    float v; asm volatile("ld.shared.f32 %0, [%1];" : "=f"(v) : "r"(a)); return v;
}
__device__ __forceinline__ void mma16816(float* c,
    uint32_t a0, uint32_t a1, uint32_t a2, uint32_t a3, uint32_t b0, uint32_t b1) {
    asm volatile("mma.sync.aligned.m16n8k16.row.col.f32.bf16.bf16.f32 "
        "{%0,%1,%2,%3}, {%4,%5,%6,%7}, {%8,%9}, {%0,%1,%2,%3};"
        : "+f"(c[0]), "+f"(c[1]), "+f"(c[2]), "+f"(c[3])
        : "r"(a0), "r"(a1), "r"(a2), "r"(a3), "r"(b0), "r"(b1));
}
__device__ __forceinline__ void bfsplit(float v, __nv_bfloat16& hi, __nv_bfloat16& lo) {
    hi = __float2bfloat16_rn(v);
    lo = __float2bfloat16_rn(v - __bfloat162float(hi));
}

// ---------------------------------------------------------------------------
// Weight transform F(4x4,3x3): U = G g G^T (6x6) per (co2, ci).
// ---------------------------------------------------------------------------
__global__ __launch_bounds__(256) void wtrans_kernel(
    const float* __restrict__ Wq, const float* __restrict__ Wk,
    const float* __restrict__ Wv, const float* __restrict__ Wc)
{
    const int idx = blockIdx.x * 256 + threadIdx.x;   // 2048*512
    const int ci  = idx & 511;
    const int co2 = idx >> 9;
    const float* Wp;
    int co;
    if (co2 < 512)       { Wp = Wq; co = co2; }
    else if (co2 < 1024) { Wp = Wk; co = co2 - 512; }
    else if (co2 < 1536) { Wp = Wv; co = co2 - 1024; }
    else                 { Wp = Wc; co = co2 - 1536; }

    float g[3][3];
#pragma unroll
    for (int r = 0; r < 3; r++)
#pragma unroll
        for (int c = 0; c < 3; c++)
            g[r][c] = Wp[((size_t)co * 512 + ci) * 9 + r * 3 + c];

    const float c6 = 1.f / 6.f, c12 = 1.f / 12.f, c24 = 1.f / 24.f;
    float gg[6][3];
#pragma unroll
    for (int c = 0; c < 3; c++) {
        gg[0][c] = 0.25f * g[0][c];
        gg[1][c] = -c6 * (g[0][c] + g[1][c] + g[2][c]);
        gg[2][c] =  c6 * (-g[0][c] + g[1][c] - g[2][c]);
        gg[3][c] = c24 * g[0][c] + c12 * g[1][c] + c6 * g[2][c];
        gg[4][c] = c24 * g[0][c] - c12 * g[1][c] + c6 * g[2][c];
        gg[5][c] = g[2][c];
    }
#pragma unroll
    for (int r = 0; r < 6; r++) {
        float u[6];
        u[0] = 0.25f * gg[r][0];
        u[1] = -c6 * (gg[r][0] + gg[r][1] + gg[r][2]);
        u[2] =  c6 * (-gg[r][0] + gg[r][1] - gg[r][2]);
        u[3] = c24 * gg[r][0] + c12 * gg[r][1] + c6 * gg[r][2];
        u[4] = c24 * gg[r][0] - c12 * gg[r][1] + c6 * gg[r][2];
        u[5] = gg[r][2];
#pragma unroll
        for (int c = 0; c < 6; c++) {
            const int pt = r * 6 + c;
            __nv_bfloat16 hi, lo;
            bfsplit(u[c], hi, lo);
            if (co2 < 1536) {
                const size_t o = ((size_t)pt * 1536 + co2) * 512 + ci;
                g_Ux_hi[o] = hi; g_Ux_lo[o] = lo;
            } else {
                const size_t o = ((size_t)pt * 512 + co) * 512 + ci;
                g_Uc_hi[o] = hi; g_Uc_lo[o] = lo;
            }
        }
    }
}

// ---------------------------------------------------------------------------
// Input transform core: V = B^T d B (6x6).
// ---------------------------------------------------------------------------
__device__ __forceinline__ void vtrans6(const float d[6][6], float v[6][6])
{
    float t[6][6];
#pragma unroll
    for (int j = 0; j < 6; j++) {
        t[0][j] = 4.f * d[0][j] - 5.f * d[2][j] + d[4][j];
        t[1][j] = -4.f * d[1][j] - 4.f * d[2][j] + d[3][j] + d[4][j];
        t[2][j] =  4.f * d[1][j] - 4.f * d[2][j] - d[3][j] + d[4][j];
        t[3][j] = -2.f * d[1][j] - d[2][j] + 2.f * d[3][j] + d[4][j];
        t[4][j] =  2.f * d[1][j] - d[2][j] - 2.f * d[3][j] + d[4][j];
        t[5][j] =  4.f * d[1][j] - 5.f * d[3][j] + d[5][j];
    }
#pragma unroll
    for (int i = 0; i < 6; i++) {
        v[i][0] = 4.f * t[i][0] - 5.f * t[i][2] + t[i][4];
        v[i][1] = -4.f * t[i][1] - 4.f * t[i][2] + t[i][3] + t[i][4];
        v[i][2] =  4.f * t[i][1] - 4.f * t[i][2] - t[i][3] + t[i][4];
        v[i][3] = -2.f * t[i][1] - t[i][2] + 2.f * t[i][3] + t[i][4];
        v[i][4] =  2.f * t[i][1] - t[i][2] - 2.f * t[i][3] + t[i][4];
        v[i][5] =  4.f * t[i][1] - 5.f * t[i][3] + t[i][5];
    }
}

__device__ __forceinline__ void vtrans_body(
    const float* xs, int ci0, int tb,
    __nv_bfloat16* __restrict__ Vh, __nv_bfloat16* __restrict__ Vl)
{
    const int tid = threadIdx.x;
    const int ci = tid & 63;
    const int tile = tid >> 6;          // 0..3
    const int ty = tile >> 1, tx = tile & 1;

    float d[6][6];
#pragma unroll
    for (int r = 0; r < 6; r++)
#pragma unroll
        for (int c = 0; c < 6; c++)
            d[r][c] = xs[ci * 101 + (ty * 4 + r) * 10 + (tx * 4 + c)];

    float v[6][6];
    vtrans6(d, v);

#pragma unroll
    for (int i = 0; i < 6; i++)
#pragma unroll
        for (int j = 0; j < 6; j++) {
            const int pt = i * 6 + j;
            __nv_bfloat16 hi, lo;
            bfsplit(v[i][j], hi, lo);
            const size_t o = ((size_t)pt * NT4 + tb + tile) * 512 + ci0 + ci;
            Vh[o] = hi; Vl[o] = lo;
        }
}

// Input transform of x. grid (1024 = n*t, 8 ci-chunks of 64), block 256.
__global__ __launch_bounds__(256) void vtransx_kernel(const float* __restrict__ x)
{
    __shared__ float xs[64 * 101];
    const int nt = blockIdx.x;
    const int n  = nt >> 2;
    const int t  = nt & 3;
    const int ci0 = blockIdx.y * 64;
    const int tid = threadIdx.x;

    for (int idx = tid; idx < 6400; idx += 256) {
        const int i = idx / 100;
        const int rc = idx % 100;
        const int r = rc / 10, c = rc % 10;
        const int hh = r - 1, ww = c - 1;
        float v = 0.f;
        if (hh >= 0 && hh < 8 && ww >= 0 && ww < 8)
            v = x[((size_t)(n * 512 + ci0 + i)) * 256 + t * 64 + hh * 8 + ww];
        xs[i * 101 + r * 10 + c] = v;
    }
    __syncthreads();
    vtrans_body(xs, ci0, nt * 4, g_Vx_hi, g_Vx_lo);
}

// Input transform of GN(virt)+ReLU. virt is [n][c][loc] (R8). grid (1024, 8).
__global__ __launch_bounds__(256) void vtransc_kernel(
    const float* __restrict__ gamma, const float* __restrict__ beta)
{
    __shared__ float xs[64 * 101];
    const int nt = blockIdx.x;
    const int n  = nt >> 2;
    const int t  = nt & 3;
    const int ci0 = blockIdx.y * 64;
    const int tid = threadIdx.x;
    const float mu = g_mu[n], ri = g_rinv[n];

    for (int idx = tid; idx < 6400; idx += 256) {
        const int i = idx / 100;
        const int rc = idx % 100;
        const int r = rc / 10, c = rc % 10;
        const int hh = r - 1, ww = c - 1;
        float v = 0.f;
        if (hh >= 0 && hh < 8 && ww >= 0 && ww < 8) {
            float u = g_virt[((size_t)(n * 512 + ci0 + i)) * 256 + t * 64 + hh * 8 + ww];
            u = (u - mu) * ri * gamma[ci0 + i] + beta[ci0 + i];
            v = fmaxf(u, 0.f);
        }
        xs[i * 101 + r * 10 + c] = v;
    }
    __syncthreads();
    vtrans_body(xs, ci0, nt * 4, g_Vc_hi, g_Vc_lo);
}

// ---------------------------------------------------------------------------
// Winograd point GEMM (proven): M[pt][tile][co] = V[pt] x U[pt] (K=512).
// ---------------------------------------------------------------------------
#define WROWB   80
#define WA_LO   10240
#define WB_HI   20480
#define WB_LO   30720
#define WSTAGE  40960
#define WSMEM   81920
#define WKCH    16

__device__ __forceinline__ void wload_stage(
    uint32_t sb, int s, int chunk,
    const __nv_bfloat16* __restrict__ Ah, const __nv_bfloat16* __restrict__ Al,
    const __nv_bfloat16* __restrict__ Bh, const __nv_bfloat16* __restrict__ Bl,
    int tid)
{
    const int k0 = chunk * 32;
    const uint32_t base = sb + s * WSTAGE;
#pragma unroll
    for (int it = 0; it < 2; ++it) {
        const int idx = tid + it * 256;
        const int row = idx >> 2, part = idx & 3;
        const uint32_t so = row * WROWB + part * 16;
        const size_t g = (size_t)row * 512 + k0 + part * 8;
        cp16(base + so,          Ah + g);
        cp16(base + WA_LO + so,  Al + g);
        cp16(base + WB_HI + so,  Bh + g);
        cp16(base + WB_LO + so,  Bl + g);
    }
}

__device__ __forceinline__ void wcompute_stage(uint32_t sb, int s,
                                               float acc[2][8][4], int tid)
{
    const int wid = tid >> 5, lane = tid & 31;
    const int wm = wid >> 1, wn = wid & 1;
    const uint32_t stage = sb + s * WSTAGE;

    const int a_moff = ((lane >> 3) & 1) * 8 + (lane & 7);
    const int a_kb   = ((lane >> 4) & 1) * 16;
    const int b_noff = ((lane >> 4) & 1) * 8 + (lane & 7);
    const int b_kb   = ((lane >> 3) & 1) * 16;

    const uint32_t aBase = stage + (uint32_t)(wm * 32 + a_moff) * WROWB + a_kb;
    const uint32_t bBase = stage + WB_HI + (uint32_t)(wn * 64 + b_noff) * WROWB + b_kb;

#pragma unroll
    for (int ks = 0; ks < 2; ++ks) {
        const uint32_t ko = ks * 32;
        uint32_t ah[2][4], al[2][4];
#pragma unroll
        for (int mt = 0; mt < 2; ++mt) {
            const uint32_t a0 = aBase + mt * (16 * WROWB) + ko;
            ldsm4(ah[mt][0], ah[mt][1], ah[mt][2], ah[mt][3], a0);
            ldsm4(al[mt][0], al[mt][1], al[mt][2], al[mt][3], a0 + WA_LO);
        }
#pragma unroll
        for (int p = 0; p < 4; ++p) {
            uint32_t bh0, bh1, bh2, bh3, bl0, bl1, bl2, bl3;
            const uint32_t b0 = bBase + p * (16 * WROWB) + ko;
            ldsm4(bh0, bh1, bh2, bh3, b0);
            ldsm4(bl0, bl1, bl2, bl3, b0 + (WB_LO - WB_HI));
#pragma unroll
            for (int mt = 0; mt < 2; ++mt) {
                mma16816(acc[mt][2*p],   ah[mt][0], ah[mt][1], ah[mt][2], ah[mt][3], bh0, bh1);
                mma16816(acc[mt][2*p],   ah[mt][0], ah[mt][1], ah[mt][2], ah[mt][3], bl0, bl1);
                mma16816(acc[mt][2*p],   al[mt][0], al[mt][1], al[mt][2], al[mt][3], bh0, bh1);
                mma16816(acc[mt][2*p+1], ah[mt][0], ah[mt][1], ah[mt][2], ah[mt][3], bh2, bh3);
                mma16816(acc[mt][2*p+1], ah[mt][0], ah[mt][1], ah[mt][2], ah[mt][3], bl2, bl3);
                mma16816(acc[mt][2*p+1], al[mt][0], al[mt][1], al[mt][2], al[mt][3], bh2, bh3);
            }
        }
    }
}

__global__ __launch_bounds__(256, 2) void gemm_wino_kernel(int which)
{
    extern __shared__ char smem[];
    const uint32_t sb = smem_u32(smem);
    const int tid = threadIdx.x;
    const int mt = blockIdx.x;
    const int nb = blockIdx.y * 128;
    const int pt = blockIdx.z;

    const __nv_bfloat16 *Uh, *Ul, *Vh, *Vl;
    int mrows;
    if (which == 0) {
        Uh = g_Ux_hi; Ul = g_Ux_lo; Vh = g_Vx_hi; Vl = g_Vx_lo; mrows = 1536;
    } else {
        Uh = g_Uc_hi; Ul = g_Uc_lo; Vh = g_Vc_hi; Vl = g_Vc_lo; mrows = 512;
    }

    const __nv_bfloat16* Ah = Uh + ((size_t)pt * mrows + mt * 128) * 512;
    const __nv_bfloat16* Al = Ul + ((size_t)pt * mrows + mt * 128) * 512;
    const __nv_bfloat16* Bh = Vh + ((size_t)pt * NT4 + nb) * 512;
    const __nv_bfloat16* Bl = Vl + ((size_t)pt * NT4 + nb) * 512;

    float acc[2][8][4];
#pragma unroll
    for (int a = 0; a < 2; a++)
#pragma unroll
        for (int b = 0; b < 8; b++)
#pragma unroll
            for (int c = 0; c < 4; c++) acc[a][b][c] = 0.f;

    wload_stage(sb, 0, 0, Ah, Al, Bh, Bl, tid); cp_commit();
    wload_stage(sb, 1, 1, Ah, Al, Bh, Bl, tid); cp_commit();
    for (int c = 0; c < WKCH; ++c) {
        cp_wait1();
        __syncthreads();
        wcompute_stage(sb, c & 1, acc, tid);
        __syncthreads();
        if (c + 2 < WKCH)
            wload_stage(sb, c & 1, c + 2, Ah, Al, Bh, Bl, tid);
        cp_commit();
    }
    __syncthreads();

    const int wid = tid >> 5, lane = tid & 31;
    const int wm = wid >> 1, wn = wid & 1;
    const int g = lane >> 2, q2 = (lane & 3) * 2;
#pragma unroll
    for (int m2 = 0; m2 < 2; m2++)
#pragma unroll
        for (int nt = 0; nt < 8; nt++) {
            const int row = wm * 32 + m2 * 16 + g;          // co local
            const int col = wn * 64 + nt * 8 + q2;          // tile local
            const float* c = acc[m2][nt];
            sts32f(sb + (uint32_t)((col)     * 132 + row)     * 4, c[0]);
            sts32f(sb + (uint32_t)((col + 1) * 132 + row)     * 4, c[1]);
            sts32f(sb + (uint32_t)((col)     * 132 + row + 8) * 4, c[2]);
            sts32f(sb + (uint32_t)((col + 1) * 132 + row + 8) * 4, c[3]);
        }
    __syncthreads();

    for (int idx = tid; idx < 16384; idx += 256) {
        const int col = idx >> 7, m = idx & 127;
        g_M[((size_t)pt * NT4 + nb + col) * mrows + mt * 128 + m] =
            lds32f(sb + (uint32_t)(col * 132 + m) * 4);
    }
}

// ---------------------------------------------------------------------------
// Output transform (qkv): Y = A^T M A. q/k -> bf16 hi/lo; v -> float (R8 layout)
// ---------------------------------------------------------------------------
__device__ __forceinline__ void at_rows(const float m[6][6], int i, float s[6])
{
#pragma unroll
    for (int j = 0; j < 6; j++) {
        if (i == 0)      s[j] = m[0][j] + m[1][j] + m[2][j] + m[3][j] + m[4][j];
        else if (i == 1) s[j] = m[1][j] - m[2][j] + 2.f * (m[3][j] - m[4][j]);
        else if (i == 2) s[j] = m[1][j] + m[2][j] + 4.f * (m[3][j] + m[4][j]);
        else             s[j] = m[1][j] - m[2][j] + 8.f * (m[3][j] - m[4][j]) + m[5][j];
    }
}
__device__ __forceinline__ void at_cols(const float s[6], float y[4])
{
    y[0] = s[0] + s[1] + s[2] + s[3] + s[4];
    y[1] = s[1] - s[2] + 2.f * (s[3] - s[4]);
    y[2] = s[1] + s[2] + 4.f * (s[3] + s[4]);
    y[3] = s[1] - s[2] + 8.f * (s[3] - s[4]) + s[5];
}

__global__ __launch_bounds__(256) void outtrans_qkv_kernel()
{
    __shared__ float ms[PTS][32][5];
    const int nt = blockIdx.x;
    const int n  = nt >> 2;
    const int t  = nt & 3;
    const int cobase = blockIdx.y * 32;
    const int tid = threadIdx.x;

    for (int idx = tid; idx < PTS * 128; idx += 256) {
        const int pt = idx >> 7;
        const int rem = idx & 127;
        const int tile = rem >> 5, co = rem & 31;
        ms[pt][co][tile] = g_M[((size_t)pt * NT4 + nt * 4 + tile) * 1536 + cobase + co];
    }
    __syncthreads();

    const int co = tid & 31;
    const int tg = tid >> 5;
    const int tile = tg & 3, half = tg >> 2;
    const int ty = tile >> 1, tx = tile & 1;
    const int co2 = cobase + co;
    const int co_in = co2 & 511;

    float m[6][6];
#pragma unroll
    for (int i = 0; i < 6; i++)
#pragma unroll
        for (int j = 0; j < 6; j++)
            m[i][j] = ms[i * 6 + j][co][tile];

#pragma unroll
    for (int ii = 0; ii < 2; ii++) {
        const int i = half * 2 + ii;
        float s[6], y[4];
        at_rows(m, i, s);
        at_cols(s, y);
        const int loc0 = t * 64 + (ty * 4 + i) * 8 + tx * 4;
#pragma unroll
        for (int k = 0; k < 4; k++) {
            const size_t o = ((size_t)(loc0 + k) * 256 + n) * 512 + co_in;
            if (co2 < 1024) {
                __nv_bfloat16 hi, lo;
                bfsplit(y[k], hi, lo);
                if (co2 < 512) { g_qh[o] = hi; g_ql[o] = lo; }
                else           { g_kh[o] = hi; g_kl[o] = lo; }
            } else {
                g_vA[o] = y[k];
            }
        }
    }
}

// ---------------------------------------------------------------------------
// Output transform (conv_c) + residual -> d_out [n][co][loc].  (R8 verbatim)
// ---------------------------------------------------------------------------
__global__ __launch_bounds__(256) void outtrans_c_kernel(
    const float* __restrict__ x, float* __restrict__ out)
{
    __shared__ float ms[PTS][32][5];
    __shared__ float ys[32][65];
    const int nt = blockIdx.x;
    const int n  = nt >> 2;
    const int t  = nt & 3;
    const int cobase = blockIdx.y * 32;
    const int tid = threadIdx.x;

    for (int idx = tid; idx < PTS * 128; idx += 256) {
        const int pt = idx >> 7;
        const int rem = idx & 127;
        const int tile = rem >> 5, co = rem & 31;
        ms[pt][co][tile] = g_M[((size_t)pt * NT4 + nt * 4 + tile) * 512 + cobase + co];
    }
    __syncthreads();

    const int co = tid & 31;
    const int tg = tid >> 5;
    const int tile = tg & 3, half = tg >> 2;
    const int ty = tile >> 1, tx = tile & 1;

    float m[6][6];
#pragma unroll
    for (int i = 0; i < 6; i++)
#pragma unroll
        for (int j = 0; j < 6; j++)
            m[i][j] = ms[i * 6 + j][co][tile];

#pragma unroll
    for (int ii = 0; ii < 2; ii++) {
        const int i = half * 2 + ii;
        float s[6], y[4];
        at_rows(m, i, s);
        at_cols(s, y);
        const int p0 = (ty * 4 + i) * 8 + tx * 4;
#pragma unroll
        for (int k = 0; k < 4; k++)
            ys[co][p0 + k] = y[k];
    }
    __syncthreads();

    for (int idx = tid; idx < 2048; idx += 256) {
        const int c = idx >> 6, l = idx & 63;
        const size_t o = ((size_t)(n * 512 + cobase + c)) * 256 + t * 64 + l;
        out[o] = x[o] + ys[c][l];
    }
}

// ---------------------------------------------------------------------------
// Attention scores on tensor pipe (THE SINGLE NEW COMPONENT).
// Block = (i-half, loc): M=128, N=256, K=512. Writes FLOAT g_att (R8 format).
// ---------------------------------------------------------------------------
#define S_ALO  10240
#define S_BHI  20480
#define S_BLO  40960
#define SSTAGE 61440
#define SSMEM  133120

__device__ __forceinline__ void sload_stage(uint32_t sb, int s, int chunk,
                                            int loc, int ib, int tid)
{
    const int k0 = chunk * 32;
    const uint32_t base = sb + s * SSTAGE;
#pragma unroll
    for (int it = 0; it < 2; ++it) {
        const int idx = tid + it * 256;
        const int row = idx >> 2, part = idx & 3;
        const uint32_t so = row * WROWB + part * 16;
        const size_t g = ((size_t)(loc * 256 + ib + row)) * 512 + k0 + part * 8;
        cp16(base + so,         g_qh + g);
        cp16(base + S_ALO + so, g_ql + g);
    }
#pragma unroll
    for (int it = 0; it < 4; ++it) {
        const int idx = tid + it * 256;
        const int row = idx >> 2, part = idx & 3;
        const uint32_t so = row * WROWB + part * 16;
        const size_t g = ((size_t)(loc * 256 + row)) * 512 + k0 + part * 8;
        cp16(base + S_BHI + so, g_kh + g);
        cp16(base + S_BLO + so, g_kl + g);
    }
}

__device__ __forceinline__ void scompute_stage(uint32_t sb, int s,
                                               float acc[2][16][4], int tid)
{
    const int wid = tid >> 5, lane = tid & 31;
    const int wm = wid >> 1, wn = wid & 1;
    const uint32_t stage = sb + s * SSTAGE;

    const int a_moff = ((lane >> 3) & 1) * 8 + (lane & 7);
    const int a_kb   = ((lane >> 4) & 1) * 16;
    const int b_noff = ((lane >> 4) & 1) * 8 + (lane & 7);
    const int b_kb   = ((lane >> 3) & 1) * 16;

    const uint32_t aBase = stage + (uint32_t)(wm * 32 + a_moff) * WROWB + a_kb;
    const uint32_t bBase = stage + S_BHI + (uint32_t)(wn * 128 + b_noff) * WROWB + b_kb;

#pragma unroll
    for (int ks = 0; ks < 2; ++ks) {
        const uint32_t ko = ks * 32;
        uint32_t ah[2][4], al[2][4];
#pragma unroll
        for (int mt = 0; mt < 2; ++mt) {
            const uint32_t a0 = aBase + mt * (16 * WROWB) + ko;
            ldsm4(ah[mt][0], ah[mt][1], ah[mt][2], ah[mt][3], a0);
            ldsm4(al[mt][0], al[mt][1], al[mt][2], al[mt][3], a0 + S_ALO);
        }
#pragma unroll
        for (int p = 0; p < 8; ++p) {
            uint32_t bh0, bh1, bh2, bh3, bl0, bl1, bl2, bl3;
            const uint32_t b0 = bBase + p * (16 * WROWB) + ko;
            ldsm4(bh0, bh1, bh2, bh3, b0);
            ldsm4(bl0, bl1, bl2, bl3, b0 + (S_BLO - S_BHI));
#pragma unroll
            for (int mt = 0; mt < 2; ++mt) {
                mma16816(acc[mt][2*p],   ah[mt][0], ah[mt][1], ah[mt][2], ah[mt][3], bh0, bh1);
                mma16816(acc[mt][2*p],   ah[mt][0], ah[mt][1], ah[mt][2], ah[mt][3], bl0, bl1);
                mma16816(acc[mt][2*p],   al[mt][0], al[mt][1], al[mt][2], al[mt][3], bh0, bh1);
                mma16816(acc[mt][2*p+1], ah[mt][0], ah[mt][1], ah[mt][2], ah[mt][3], bh2, bh3);
                mma16816(acc[mt][2*p+1], ah[mt][0], ah[mt][1], ah[mt][2], ah[mt][3], bl2, bl3);
                mma16816(acc[mt][2*p+1], al[mt][0], al[mt][1], al[mt][2], al[mt][3], bh2, bh3);
            }
        }
    }
}

__global__ __launch_bounds__(256, 1) void att_scores_mma(const int* __restrict__ roi)
{
    extern __shared__ char smem[];
    __shared__ int roi_s[256];
    const uint32_t sb = smem_u32(smem);
    const int tid = threadIdx.x;
    const int ib  = blockIdx.x * 128;
    const int loc = blockIdx.y;

    if (tid < 256) roi_s[tid] = roi[tid];

    float acc[2][16][4];
#pragma unroll
    for (int a = 0; a < 2; a++)
#pragma unroll
        for (int b = 0; b < 16; b++)
#pragma unroll
            for (int c = 0; c < 4; c++) acc[a][b][c] = 0.f;

    sload_stage(sb, 0, 0, loc, ib, tid); cp_commit();
    sload_stage(sb, 1, 1, loc, ib, tid); cp_commit();
    for (int c = 0; c < 16; ++c) {
        cp_wait1();
        __syncthreads();
        scompute_stage(sb, c & 1, acc, tid);
        __syncthreads();
        if (c + 2 < 16)
            sload_stage(sb, c & 1, c + 2, loc, ib, tid);
        cp_commit();
    }
    __syncthreads();

    const int wid = tid >> 5, lane = tid & 31;
    const int wm = wid >> 1, wn = wid & 1;
    const int g = lane >> 2, q2 = (lane & 3) * 2;
#pragma unroll
    for (int m2 = 0; m2 < 2; m2++)
#pragma unroll
        for (int f = 0; f < 16; f++) {
            const int row = wm * 32 + m2 * 16 + g;
            const int col = wn * 128 + f * 8 + q2;
            const float* c = acc[m2][f];
            sts32f(sb + (uint32_t)((row)     * 260 + col)     * 4, c[0]);
            sts32f(sb + (uint32_t)((row)     * 260 + col + 1) * 4, c[1]);
            sts32f(sb + (uint32_t)((row + 8) * 260 + col)     * 4, c[2]);
            sts32f(sb + (uint32_t)((row + 8) * 260 + col + 1) * 4, c[3]);
        }
    __syncthreads();

    const float scale = 0.044194173824159216f;
#pragma unroll 1
    for (int rr = 0; rr < 16; rr++) {
        const int i = wid * 16 + rr;
        const int ri = roi_s[ib + i];
        float e[8];
        float m = -CUDART_INF_F;
#pragma unroll
        for (int jj = 0; jj < 8; jj++) {
            const int j = jj * 32 + lane;
            float v = (roi_s[j] == ri)
                    ? lds32f(sb + (uint32_t)(i * 260 + j) * 4) * scale
                    : -CUDART_INF_F;
            e[jj] = v;
            m = fmaxf(m, v);
        }
#pragma unroll
        for (int off = 16; off > 0; off >>= 1)
            m = fmaxf(m, __shfl_xor_sync(0xffffffffu, m, off));
        float s = 0.f;
#pragma unroll
        for (int jj = 0; jj < 8; jj++) { float t_ = __expf(e[jj] - m); e[jj] = t_; s += t_; }
#pragma unroll
        for (int off = 16; off > 0; off >>= 1)
            s += __shfl_xor_sync(0xffffffffu, s, off);
        const float inv = 1.f / s;
#pragma unroll
        for (int jj = 0; jj < 8; jj++) {
            const int j = jj * 32 + lane;
            g_att[((size_t)loc * NN + ib + i) * NN + j] = e[jj] * inv;
        }
    }
}

// ---------------------------------------------------------------------------
// virt = att @ v  (R8 FFMA version, PROVEN; reads float g_att, g_vA)
// ---------------------------------------------------------------------------
__global__ __launch_bounds__(256) void att_apply_kernel()
{
    __shared__ float as[32][33];
    __shared__ float vs[32][256];

    const int loc = blockIdx.x;
    const int it  = blockIdx.y >> 1;
    const int ct  = blockIdx.y & 1;
    const int ib  = it * 32;
    const int cb  = ct * 256;
    const int tid = threadIdx.x;
    const int ig  = tid >> 5;
    const int cg  = tid & 31;

    float acc[4][8];
#pragma unroll
    for (int ii = 0; ii < 4; ii++)
#pragma unroll
        for (int cc = 0; cc < 8; cc++) acc[ii][cc] = 0.f;

    for (int j0 = 0; j0 < NN; j0 += 32) {
        for (int idx = tid; idx < 32 * 32; idx += 256) {
            int i = idx >> 5, j = idx & 31;
            as[i][j] = g_att[((size_t)loc * NN + ib + i) * NN + j0 + j];
        }
        for (int idx = tid; idx < 32 * 256; idx += 256) {
            int j = idx >> 8, c = idx & 255;
            vs[j][c] = g_vA[((size_t)loc * NN + j0 + j) * CC + cb + c];
        }
        __syncthreads();

#pragma unroll 4
        for (int j = 0; j < 32; j++) {
            float vv[8];
#pragma unroll
            for (int cc = 0; cc < 8; cc++) vv[cc] = vs[j][cg + 32 * cc];
#pragma unroll
            for (int ii = 0; ii < 4; ii++) {
                float av = as[ig + 8 * ii][j];
#pragma unroll
                for (int cc = 0; cc < 8; cc++) acc[ii][cc] += av * vv[cc];
            }
        }
        __syncthreads();
    }

#pragma unroll
    for (int ii = 0; ii < 4; ii++) {
        const int i = ib + ig + 8 * ii;
#pragma unroll
        for (int cc = 0; cc < 8; cc++) {
            const int c = cb + cg + 32 * cc;
            g_virt[((size_t)i * CC + c) * THW + loc] = acc[ii][cc];
        }
    }
}

// ---------------------------------------------------------------------------
// GroupNorm: 8-way partial + finalize, on R8 layout [n][c][loc].
// ---------------------------------------------------------------------------
__global__ __launch_bounds__(256) void gn_partial_kernel()
{
    __shared__ float red[16];
    const int n  = blockIdx.x;
    const int ch = blockIdx.y;
    const int tid = threadIdx.x;
    const float* __restrict__ src = g_virt + (size_t)n * CC * THW + (size_t)ch * 16384;

    float s = 0.f, s2 = 0.f;
    for (int idx = tid; idx < 16384; idx += 256) {
        float v = src[idx];
        s += v; s2 += v * v;
    }
#pragma unroll
    for (int off = 16; off > 0; off >>= 1) {
        s  += __shfl_xor_sync(0xffffffffu, s,  off);
        s2 += __shfl_xor_sync(0xffffffffu, s2, off);
    }
    const int wid = tid >> 5, lane = tid & 31;
    if (lane == 0) { red[wid] = s; red[8 + wid] = s2; }
    __syncthreads();
    if (tid == 0) {
        float S = 0.f, S2 = 0.f;
#pragma unroll
        for (int w = 0; w < 8; w++) { S += red[w]; S2 += red[8 + w]; }
        g_psum[n][ch] = S;
        g_psum2[n][ch] = S2;
    }
}

__global__ void gn_final_kernel()
{
    const int n = threadIdx.x;
    float S = 0.f, S2 = 0.f;
#pragma unroll
    for (int w = 0; w < 8; w++) { S += g_psum[n][w]; S2 += g_psum2[n][w]; }
    const float M = (float)(CC * THW);
    float mu  = S / M;
    float var = S2 / M - mu * mu;
    g_mu[n]   = mu;
    g_rinv[n] = rsqrtf(var + 1e-5f);
}

// ---------------------------------------------------------------------------
extern "C" void kernel_launch(void* const* d_in, const int* in_sizes, int n_in,
                              void* d_out, int out_size)
{
    const float* x     = (const float*)d_in[0];
    const int*   roi   = (const int*)  d_in[1];
    const float* Wq    = (const float*)d_in[2];
    const float* Wk    = (const float*)d_in[3];
    const float* Wv    = (const float*)d_in[4];
    const float* Wc    = (const float*)d_in[5];
    const float* gamma = (const float*)d_in[6];
    const float* beta  = (const float*)d_in[7];
    float* out = (float*)d_out;

    cudaFuncSetAttribute(gemm_wino_kernel,
                         cudaFuncAttributeMaxDynamicSharedMemorySize, WSMEM);
    cudaFuncSetAttribute(att_scores_mma,
                         cudaFuncAttributeMaxDynamicSharedMemorySize, SSMEM);

    wtrans_kernel<<<4096, 256>>>(Wq, Wk, Wv, Wc);
    vtransx_kernel<<<dim3(1024, 8), 256>>>(x);
    gemm_wino_kernel<<<dim3(12, 32, PTS), 256, WSMEM>>>(0);
    outtrans_qkv_kernel<<<dim3(1024, 48), 256>>>();
    att_scores_mma<<<dim3(2, 256), 256, SSMEM>>>(roi);
    att_apply_kernel<<<dim3(256, 16), 256>>>();
    gn_partial_kernel<<<dim3(256, 8), 256>>>();
    gn_final_kernel<<<1, 256>>>();
    vtransc_kernel<<<dim3(1024, 8), 256>>>(gamma, beta);
    gemm_wino_kernel<<<dim3(4, 32, PTS), 256, WSMEM>>>(1);
    outtrans_c_kernel<<<dim3(1024, 16), 256>>>(x, out);
}

// round 14
// speedup vs baseline: 7.8425x; 1.0275x over previous
#include <cuda_runtime.h>
#include <cuda_bf16.h>
#include <math_constants.h>
#include <cstdint>

// Problem constants
#define NN     256
#define CC     512
#define THW    256
#define NT4    4096            // 256 n * 4 t * 4 tiles(4x4)
#define PTS    36              // 6x6 Winograd F(4x4,3x3) points
#define NCTHW  33554432

// ---------------------------------------------------------------------------
// Scratch (static __device__ arrays — allocation is forbidden)
// ---------------------------------------------------------------------------
__device__ __nv_bfloat16 g_qh[NCTHW], g_ql[NCTHW];   // [(loc*256+n)*512+c]
__device__ __nv_bfloat16 g_kh[NCTHW], g_kl[NCTHW];
__device__ float g_vA[NCTHW];                        // [(loc*256+n)*512+c]
__device__ float g_att[THW * NN * NN];               // [loc][i][j]
__device__ float g_virt[NCTHW];                      // [n][c][loc]
__device__ float g_psum[NN][8], g_psum2[NN][8];
__device__ float g_mu[NN], g_rinv[NN];

// Winograd operands. U: [pt][co][ci], V: [pt][tile][ci], M: [pt][tile][co]
__device__ __nv_bfloat16 g_Ux_hi[(size_t)PTS * 1536 * 512];
__device__ __nv_bfloat16 g_Ux_lo[(size_t)PTS * 1536 * 512];
__device__ __nv_bfloat16 g_Uc_hi[(size_t)PTS * 512 * 512];
__device__ __nv_bfloat16 g_Uc_lo[(size_t)PTS * 512 * 512];
__device__ __nv_bfloat16 g_Vx_hi[(size_t)PTS * NT4 * 512];
__device__ __nv_bfloat16 g_Vx_lo[(size_t)PTS * NT4 * 512];
__device__ __nv_bfloat16 g_Vc_hi[(size_t)PTS * NT4 * 512];
__device__ __nv_bfloat16 g_Vc_lo[(size_t)PTS * NT4 * 512];
__device__ float g_M[(size_t)PTS * NT4 * 1536];      // [pt][tile][co]

// ---------------------------------------------------------------------------
// Portable-ISA helpers
// ---------------------------------------------------------------------------
__device__ __forceinline__ uint32_t smem_u32(const void* p) {
    uint32_t a;
    asm("{ .reg .u64 t; cvta.to.shared.u64 t, %1; cvt.u32.u64 %0, t; }"
        : "=r"(a) : "l"(p));
    return a;
}
__device__ __forceinline__ void cp16(uint32_t dst, const void* src) {
    asm volatile("cp.async.cg.shared.global [%0], [%1], 16;" :: "r"(dst), "l"(src));
}
__device__ __forceinline__ void cp_commit() { asm volatile("cp.async.commit_group;"); }
__device__ __forceinline__ void cp_wait1()  { asm volatile("cp.async.wait_group 1;" ::: "memory"); }

__device__ __forceinline__ void ldsm4(uint32_t& r0, uint32_t& r1, uint32_t& r2,
                                      uint32_t& r3, uint32_t addr) {
    asm volatile("ldmatrix.sync.aligned.m8n8.x4.shared.b16 {%0,%1,%2,%3}, [%4];"
        : "=r"(r0), "=r"(r1), "=r"(r2), "=r"(r3) : "r"(addr));
}
__device__ __forceinline__ void sts32f(uint32_t a, float v) {
    asm volatile("st.shared.f32 [%0], %1;" :: "r"(a), "f"(v));
}
__device__ __forceinline__ float lds32f(uint32_t a) {
    float v; asm volatile("ld.shared.f32 %0, [%1];" : "=f"(v) : "r"(a)); return v;
}
__device__ __forceinline__ void mma16816(float* c,
    uint32_t a0, uint32_t a1, uint32_t a2, uint32_t a3, uint32_t b0, uint32_t b1) {
    asm volatile("mma.sync.aligned.m16n8k16.row.col.f32.bf16.bf16.f32 "
        "{%0,%1,%2,%3}, {%4,%5,%6,%7}, {%8,%9}, {%0,%1,%2,%3};"
        : "+f"(c[0]), "+f"(c[1]), "+f"(c[2]), "+f"(c[3])
        : "r"(a0), "r"(a1), "r"(a2), "r"(a3), "r"(b0), "r"(b1));
}
__device__ __forceinline__ void bfsplit(float v, __nv_bfloat16& hi, __nv_bfloat16& lo) {
    hi = __float2bfloat16_rn(v);
    lo = __float2bfloat16_rn(v - __bfloat162float(hi));
}

// ---------------------------------------------------------------------------
// Weight transform F(4x4,3x3): U = G g G^T (6x6) per (co2, ci).
// ---------------------------------------------------------------------------
__global__ __launch_bounds__(256) void wtrans_kernel(
    const float* __restrict__ Wq, const float* __restrict__ Wk,
    const float* __restrict__ Wv, const float* __restrict__ Wc)
{
    const int idx = blockIdx.x * 256 + threadIdx.x;   // 2048*512
    const int ci  = idx & 511;
    const int co2 = idx >> 9;
    const float* Wp;
    int co;
    if (co2 < 512)       { Wp = Wq; co = co2; }
    else if (co2 < 1024) { Wp = Wk; co = co2 - 512; }
    else if (co2 < 1536) { Wp = Wv; co = co2 - 1024; }
    else                 { Wp = Wc; co = co2 - 1536; }

    float g[3][3];
#pragma unroll
    for (int r = 0; r < 3; r++)
#pragma unroll
        for (int c = 0; c < 3; c++)
            g[r][c] = Wp[((size_t)co * 512 + ci) * 9 + r * 3 + c];

    const float c6 = 1.f / 6.f, c12 = 1.f / 12.f, c24 = 1.f / 24.f;
    float gg[6][3];
#pragma unroll
    for (int c = 0; c < 3; c++) {
        gg[0][c] = 0.25f * g[0][c];
        gg[1][c] = -c6 * (g[0][c] + g[1][c] + g[2][c]);
        gg[2][c] =  c6 * (-g[0][c] + g[1][c] - g[2][c]);
        gg[3][c] = c24 * g[0][c] + c12 * g[1][c] + c6 * g[2][c];
        gg[4][c] = c24 * g[0][c] - c12 * g[1][c] + c6 * g[2][c];
        gg[5][c] = g[2][c];
    }
#pragma unroll
    for (int r = 0; r < 6; r++) {
        float u[6];
        u[0] = 0.25f * gg[r][0];
        u[1] = -c6 * (gg[r][0] + gg[r][1] + gg[r][2]);
        u[2] =  c6 * (-gg[r][0] + gg[r][1] - gg[r][2]);
        u[3] = c24 * gg[r][0] + c12 * gg[r][1] + c6 * gg[r][2];
        u[4] = c24 * gg[r][0] - c12 * gg[r][1] + c6 * gg[r][2];
        u[5] = gg[r][2];
#pragma unroll
        for (int c = 0; c < 6; c++) {
            const int pt = r * 6 + c;
            __nv_bfloat16 hi, lo;
            bfsplit(u[c], hi, lo);
            if (co2 < 1536) {
                const size_t o = ((size_t)pt * 1536 + co2) * 512 + ci;
                g_Ux_hi[o] = hi; g_Ux_lo[o] = lo;
            } else {
                const size_t o = ((size_t)pt * 512 + co) * 512 + ci;
                g_Uc_hi[o] = hi; g_Uc_lo[o] = lo;
            }
        }
    }
}

// ---------------------------------------------------------------------------
// Input transform core: V = B^T d B (6x6).
// ---------------------------------------------------------------------------
__device__ __forceinline__ void vtrans6(const float d[6][6], float v[6][6])
{
    float t[6][6];
#pragma unroll
    for (int j = 0; j < 6; j++) {
        t[0][j] = 4.f * d[0][j] - 5.f * d[2][j] + d[4][j];
        t[1][j] = -4.f * d[1][j] - 4.f * d[2][j] + d[3][j] + d[4][j];
        t[2][j] =  4.f * d[1][j] - 4.f * d[2][j] - d[3][j] + d[4][j];
        t[3][j] = -2.f * d[1][j] - d[2][j] + 2.f * d[3][j] + d[4][j];
        t[4][j] =  2.f * d[1][j] - d[2][j] - 2.f * d[3][j] + d[4][j];
        t[5][j] =  4.f * d[1][j] - 5.f * d[3][j] + d[5][j];
    }
#pragma unroll
    for (int i = 0; i < 6; i++) {
        v[i][0] = 4.f * t[i][0] - 5.f * t[i][2] + t[i][4];
        v[i][1] = -4.f * t[i][1] - 4.f * t[i][2] + t[i][3] + t[i][4];
        v[i][2] =  4.f * t[i][1] - 4.f * t[i][2] - t[i][3] + t[i][4];
        v[i][3] = -2.f * t[i][1] - t[i][2] + 2.f * t[i][3] + t[i][4];
        v[i][4] =  2.f * t[i][1] - t[i][2] - 2.f * t[i][3] + t[i][4];
        v[i][5] =  4.f * t[i][1] - 5.f * t[i][3] + t[i][5];
    }
}

__device__ __forceinline__ void vtrans_body(
    const float* xs, int ci0, int tb,
    __nv_bfloat16* __restrict__ Vh, __nv_bfloat16* __restrict__ Vl)
{
    const int tid = threadIdx.x;
    const int ci = tid & 63;
    const int tile = tid >> 6;          // 0..3
    const int ty = tile >> 1, tx = tile & 1;

    float d[6][6];
#pragma unroll
    for (int r = 0; r < 6; r++)
#pragma unroll
        for (int c = 0; c < 6; c++)
            d[r][c] = xs[ci * 101 + (ty * 4 + r) * 10 + (tx * 4 + c)];

    float v[6][6];
    vtrans6(d, v);

#pragma unroll
    for (int i = 0; i < 6; i++)
#pragma unroll
        for (int j = 0; j < 6; j++) {
            const int pt = i * 6 + j;
            __nv_bfloat16 hi, lo;
            bfsplit(v[i][j], hi, lo);
            const size_t o = ((size_t)pt * NT4 + tb + tile) * 512 + ci0 + ci;
            Vh[o] = hi; Vl[o] = lo;
        }
}

// Input transform of x. grid (1024 = n*t, 8 ci-chunks of 64), block 256.
__global__ __launch_bounds__(256) void vtransx_kernel(const float* __restrict__ x)
{
    __shared__ float xs[64 * 101];
    const int nt = blockIdx.x;
    const int n  = nt >> 2;
    const int t  = nt & 3;
    const int ci0 = blockIdx.y * 64;
    const int tid = threadIdx.x;

    for (int idx = tid; idx < 6400; idx += 256) {
        const int i = idx / 100;
        const int rc = idx % 100;
        const int r = rc / 10, c = rc % 10;
        const int hh = r - 1, ww = c - 1;
        float v = 0.f;
        if (hh >= 0 && hh < 8 && ww >= 0 && ww < 8)
            v = x[((size_t)(n * 512 + ci0 + i)) * 256 + t * 64 + hh * 8 + ww];
        xs[i * 101 + r * 10 + c] = v;
    }
    __syncthreads();
    vtrans_body(xs, ci0, nt * 4, g_Vx_hi, g_Vx_lo);
}

// Input transform of GN(virt)+ReLU. virt is [n][c][loc]. grid (1024, 8).
__global__ __launch_bounds__(256) void vtransc_kernel(
    const float* __restrict__ gamma, const float* __restrict__ beta)
{
    __shared__ float xs[64 * 101];
    const int nt = blockIdx.x;
    const int n  = nt >> 2;
    const int t  = nt & 3;
    const int ci0 = blockIdx.y * 64;
    const int tid = threadIdx.x;
    const float mu = g_mu[n], ri = g_rinv[n];

    for (int idx = tid; idx < 6400; idx += 256) {
        const int i = idx / 100;
        const int rc = idx % 100;
        const int r = rc / 10, c = rc % 10;
        const int hh = r - 1, ww = c - 1;
        float v = 0.f;
        if (hh >= 0 && hh < 8 && ww >= 0 && ww < 8) {
            float u = g_virt[((size_t)(n * 512 + ci0 + i)) * 256 + t * 64 + hh * 8 + ww];
            u = (u - mu) * ri * gamma[ci0 + i] + beta[ci0 + i];
            v = fmaxf(u, 0.f);
        }
        xs[i * 101 + r * 10 + c] = v;
    }
    __syncthreads();
    vtrans_body(xs, ci0, nt * 4, g_Vc_hi, g_Vc_lo);
}

// ---------------------------------------------------------------------------
// Proven 128x128 3-product GEMM machinery.
// ---------------------------------------------------------------------------
#define WROWB   80
#define WA_LO   10240
#define WB_HI   20480
#define WB_LO   30720
#define WSTAGE  40960
#define WSMEM   81920
#define WKCH    16

__device__ __forceinline__ void wload_stage_g(
    uint32_t sb, int s, int chunk, int rowlen,
    const __nv_bfloat16* __restrict__ Ah, const __nv_bfloat16* __restrict__ Al,
    const __nv_bfloat16* __restrict__ Bh, const __nv_bfloat16* __restrict__ Bl,
    int tid)
{
    const int k0 = chunk * 32;
    const uint32_t base = sb + s * WSTAGE;
#pragma unroll
    for (int it = 0; it < 2; ++it) {
        const int idx = tid + it * 256;
        const int row = idx >> 2, part = idx & 3;
        const uint32_t so = row * WROWB + part * 16;
        const size_t g = (size_t)row * rowlen + k0 + part * 8;
        cp16(base + so,          Ah + g);
        cp16(base + WA_LO + so,  Al + g);
        cp16(base + WB_HI + so,  Bh + g);
        cp16(base + WB_LO + so,  Bl + g);
    }
}

__device__ __forceinline__ void wcompute_stage(uint32_t sb, int s,
                                               float acc[2][8][4], int tid)
{
    const int wid = tid >> 5, lane = tid & 31;
    const int wm = wid >> 1, wn = wid & 1;
    const uint32_t stage = sb + s * WSTAGE;

    const int a_moff = ((lane >> 3) & 1) * 8 + (lane & 7);
    const int a_kb   = ((lane >> 4) & 1) * 16;
    const int b_noff = ((lane >> 4) & 1) * 8 + (lane & 7);
    const int b_kb   = ((lane >> 3) & 1) * 16;

    const uint32_t aBase = stage + (uint32_t)(wm * 32 + a_moff) * WROWB + a_kb;
    const uint32_t bBase = stage + WB_HI + (uint32_t)(wn * 64 + b_noff) * WROWB + b_kb;

#pragma unroll
    for (int ks = 0; ks < 2; ++ks) {
        const uint32_t ko = ks * 32;
        uint32_t ah[2][4], al[2][4];
#pragma unroll
        for (int mt = 0; mt < 2; ++mt) {
            const uint32_t a0 = aBase + mt * (16 * WROWB) + ko;
            ldsm4(ah[mt][0], ah[mt][1], ah[mt][2], ah[mt][3], a0);
            ldsm4(al[mt][0], al[mt][1], al[mt][2], al[mt][3], a0 + WA_LO);
        }
#pragma unroll
        for (int p = 0; p < 4; ++p) {
            uint32_t bh0, bh1, bh2, bh3, bl0, bl1, bl2, bl3;
            const uint32_t b0 = bBase + p * (16 * WROWB) + ko;
            ldsm4(bh0, bh1, bh2, bh3, b0);
            ldsm4(bl0, bl1, bl2, bl3, b0 + (WB_LO - WB_HI));
#pragma unroll
            for (int mt = 0; mt < 2; ++mt) {
                mma16816(acc[mt][2*p],   ah[mt][0], ah[mt][1], ah[mt][2], ah[mt][3], bh0, bh1);
                mma16816(acc[mt][2*p],   ah[mt][0], ah[mt][1], ah[mt][2], ah[mt][3], bl0, bl1);
                mma16816(acc[mt][2*p],   al[mt][0], al[mt][1], al[mt][2], al[mt][3], bh0, bh1);
                mma16816(acc[mt][2*p+1], ah[mt][0], ah[mt][1], ah[mt][2], ah[mt][3], bh2, bh3);
                mma16816(acc[mt][2*p+1], ah[mt][0], ah[mt][1], ah[mt][2], ah[mt][3], bl2, bl3);
                mma16816(acc[mt][2*p+1], al[mt][0], al[mt][1], al[mt][2], al[mt][3], bh2, bh3);
            }
        }
    }
}

// ---------------------------------------------------------------------------
// Winograd point GEMM (proven): M[pt][tile][co] = V[pt] x U[pt] (K=512).
// ---------------------------------------------------------------------------
__global__ __launch_bounds__(256, 2) void gemm_wino_kernel(int which)
{
    extern __shared__ char smem[];
    const uint32_t sb = smem_u32(smem);
    const int tid = threadIdx.x;
    const int mt = blockIdx.x;
    const int nb = blockIdx.y * 128;
    const int pt = blockIdx.z;

    const __nv_bfloat16 *Uh, *Ul, *Vh, *Vl;
    int mrows;
    if (which == 0) {
        Uh = g_Ux_hi; Ul = g_Ux_lo; Vh = g_Vx_hi; Vl = g_Vx_lo; mrows = 1536;
    } else {
        Uh = g_Uc_hi; Ul = g_Uc_lo; Vh = g_Vc_hi; Vl = g_Vc_lo; mrows = 512;
    }

    const __nv_bfloat16* Ah = Uh + ((size_t)pt * mrows + mt * 128) * 512;
    const __nv_bfloat16* Al = Ul + ((size_t)pt * mrows + mt * 128) * 512;
    const __nv_bfloat16* Bh = Vh + ((size_t)pt * NT4 + nb) * 512;
    const __nv_bfloat16* Bl = Vl + ((size_t)pt * NT4 + nb) * 512;

    float acc[2][8][4];
#pragma unroll
    for (int a = 0; a < 2; a++)
#pragma unroll
        for (int b = 0; b < 8; b++)
#pragma unroll
            for (int c = 0; c < 4; c++) acc[a][b][c] = 0.f;

    wload_stage_g(sb, 0, 0, 512, Ah, Al, Bh, Bl, tid); cp_commit();
    wload_stage_g(sb, 1, 1, 512, Ah, Al, Bh, Bl, tid); cp_commit();
    for (int c = 0; c < WKCH; ++c) {
        cp_wait1();
        __syncthreads();
        wcompute_stage(sb, c & 1, acc, tid);
        __syncthreads();
        if (c + 2 < WKCH)
            wload_stage_g(sb, c & 1, c + 2, 512, Ah, Al, Bh, Bl, tid);
        cp_commit();
    }
    __syncthreads();

    const int wid = tid >> 5, lane = tid & 31;
    const int wm = wid >> 1, wn = wid & 1;
    const int g = lane >> 2, q2 = (lane & 3) * 2;
#pragma unroll
    for (int m2 = 0; m2 < 2; m2++)
#pragma unroll
        for (int nt = 0; nt < 8; nt++) {
            const int row = wm * 32 + m2 * 16 + g;          // co local
            const int col = wn * 64 + nt * 8 + q2;          // tile local
            const float* c = acc[m2][nt];
            sts32f(sb + (uint32_t)((col)     * 132 + row)     * 4, c[0]);
            sts32f(sb + (uint32_t)((col + 1) * 132 + row)     * 4, c[1]);
            sts32f(sb + (uint32_t)((col)     * 132 + row + 8) * 4, c[2]);
            sts32f(sb + (uint32_t)((col + 1) * 132 + row + 8) * 4, c[3]);
        }
    __syncthreads();

    for (int idx = tid; idx < 16384; idx += 256) {
        const int col = idx >> 7, m = idx & 127;
        g_M[((size_t)pt * NT4 + nb + col) * mrows + mt * 128 + m] =
            lds32f(sb + (uint32_t)(col * 132 + m) * 4);
    }
}

// ---------------------------------------------------------------------------
// Output transform (qkv): Y = A^T M A. Branch on q/k/v hoisted to BLOCK scope
// (uniform: each 32-co chunk lies wholly in q, k, or v). Addresses and data
// identical to the R11-passing version: q/k -> bf16 hi/lo, v -> float g_vA.
// ---------------------------------------------------------------------------
__device__ __forceinline__ void at_rows(const float m[6][6], int i, float s[6])
{
#pragma unroll
    for (int j = 0; j < 6; j++) {
        if (i == 0)      s[j] = m[0][j] + m[1][j] + m[2][j] + m[3][j] + m[4][j];
        else if (i == 1) s[j] = m[1][j] - m[2][j] + 2.f * (m[3][j] - m[4][j]);
        else if (i == 2) s[j] = m[1][j] + m[2][j] + 4.f * (m[3][j] + m[4][j]);
        else             s[j] = m[1][j] - m[2][j] + 8.f * (m[3][j] - m[4][j]) + m[5][j];
    }
}
__device__ __forceinline__ void at_cols(const float s[6], float y[4])
{
    y[0] = s[0] + s[1] + s[2] + s[3] + s[4];
    y[1] = s[1] - s[2] + 2.f * (s[3] - s[4]);
    y[2] = s[1] + s[2] + 4.f * (s[3] + s[4]);
    y[3] = s[1] - s[2] + 8.f * (s[3] - s[4]) + s[5];
}

__global__ __launch_bounds__(256) void outtrans_qkv_kernel()
{
    __shared__ float ms[PTS][32][5];
    const int nt = blockIdx.x;
    const int n  = nt >> 2;
    const int t  = nt & 3;
    const int cobase = blockIdx.y * 32;
    const int which = cobase >> 9;        // 0=q 1=k 2=v, uniform per block
    const int tid = threadIdx.x;

    for (int idx = tid; idx < PTS * 128; idx += 256) {
        const int pt = idx >> 7;
        const int rem = idx & 127;
        const int tile = rem >> 5, co = rem & 31;
        ms[pt][co][tile] = g_M[((size_t)pt * NT4 + nt * 4 + tile) * 1536 + cobase + co];
    }
    __syncthreads();

    const int co = tid & 31;
    const int tg = tid >> 5;
    const int tile = tg & 3, half = tg >> 2;
    const int ty = tile >> 1, tx = tile & 1;
    const int co_in = (cobase + co) & 511;

    float m[6][6];
#pragma unroll
    for (int i = 0; i < 6; i++)
#pragma unroll
        for (int j = 0; j < 6; j++)
            m[i][j] = ms[i * 6 + j][co][tile];

    if (which < 2) {
        __nv_bfloat16* dh = which ? g_kh : g_qh;
        __nv_bfloat16* dl = which ? g_kl : g_ql;
#pragma unroll
        for (int ii = 0; ii < 2; ii++) {
            const int i = half * 2 + ii;
            float s[6], y[4];
            at_rows(m, i, s);
            at_cols(s, y);
            const int loc0 = t * 64 + (ty * 4 + i) * 8 + tx * 4;
#pragma unroll
            for (int k = 0; k < 4; k++) {
                __nv_bfloat16 hi, lo;
                bfsplit(y[k], hi, lo);
                const size_t o = ((size_t)(loc0 + k) * 256 + n) * 512 + co_in;
                dh[o] = hi; dl[o] = lo;
            }
        }
    } else {
#pragma unroll
        for (int ii = 0; ii < 2; ii++) {
            const int i = half * 2 + ii;
            float s[6], y[4];
            at_rows(m, i, s);
            at_cols(s, y);
            const int loc0 = t * 64 + (ty * 4 + i) * 8 + tx * 4;
#pragma unroll
            for (int k = 0; k < 4; k++) {
                const size_t o = ((size_t)(loc0 + k) * 256 + n) * 512 + co_in;
                g_vA[o] = y[k];
            }
        }
    }
}

// ---------------------------------------------------------------------------
// Output transform (conv_c) + residual -> d_out [n][co][loc].  (proven)
// ---------------------------------------------------------------------------
__global__ __launch_bounds__(256) void outtrans_c_kernel(
    const float* __restrict__ x, float* __restrict__ out)
{
    __shared__ float ms[PTS][32][5];
    __shared__ float ys[32][65];
    const int nt = blockIdx.x;
    const int n  = nt >> 2;
    const int t  = nt & 3;
    const int cobase = blockIdx.y * 32;
    const int tid = threadIdx.x;

    for (int idx = tid; idx < PTS * 128; idx += 256) {
        const int pt = idx >> 7;
        const int rem = idx & 127;
        const int tile = rem >> 5, co = rem & 31;
        ms[pt][co][tile] = g_M[((size_t)pt * NT4 + nt * 4 + tile) * 512 + cobase + co];
    }
    __syncthreads();

    const int co = tid & 31;
    const int tg = tid >> 5;
    const int tile = tg & 3, half = tg >> 2;
    const int ty = tile >> 1, tx = tile & 1;

    float m[6][6];
#pragma unroll
    for (int i = 0; i < 6; i++)
#pragma unroll
        for (int j = 0; j < 6; j++)
            m[i][j] = ms[i * 6 + j][co][tile];

#pragma unroll
    for (int ii = 0; ii < 2; ii++) {
        const int i = half * 2 + ii;
        float s[6], y[4];
        at_rows(m, i, s);
        at_cols(s, y);
        const int p0 = (ty * 4 + i) * 8 + tx * 4;
#pragma unroll
        for (int k = 0; k < 4; k++)
            ys[co][p0 + k] = y[k];
    }
    __syncthreads();

    for (int idx = tid; idx < 2048; idx += 256) {
        const int c = idx >> 6, l = idx & 63;
        const size_t o = ((size_t)(n * 512 + cobase + c)) * 256 + t * 64 + l;
        out[o] = x[o] + ys[c][l];
    }
}

// ---------------------------------------------------------------------------
// Attention scores on tensor pipe (proven). Writes FLOAT g_att.
// Block = (i-half, loc): M=128, N=256, K=512.
// ---------------------------------------------------------------------------
#define S_ALO  10240
#define S_BHI  20480
#define S_BLO  40960
#define SSTAGE 61440
#define SSMEM  133120

__device__ __forceinline__ void sload_stage(uint32_t sb, int s, int chunk,
                                            int loc, int ib, int tid)
{
    const int k0 = chunk * 32;
    const uint32_t base = sb + s * SSTAGE;
#pragma unroll
    for (int it = 0; it < 2; ++it) {
        const int idx = tid + it * 256;
        const int row = idx >> 2, part = idx & 3;
        const uint32_t so = row * WROWB + part * 16;
        const size_t g = ((size_t)(loc * 256 + ib + row)) * 512 + k0 + part * 8;
        cp16(base + so,         g_qh + g);
        cp16(base + S_ALO + so, g_ql + g);
    }
#pragma unroll
    for (int it = 0; it < 4; ++it) {
        const int idx = tid + it * 256;
        const int row = idx >> 2, part = idx & 3;
        const uint32_t so = row * WROWB + part * 16;
        const size_t g = ((size_t)(loc * 256 + row)) * 512 + k0 + part * 8;
        cp16(base + S_BHI + so, g_kh + g);
        cp16(base + S_BLO + so, g_kl + g);
    }
}

__device__ __forceinline__ void scompute_stage(uint32_t sb, int s,
                                               float acc[2][16][4], int tid)
{
    const int wid = tid >> 5, lane = tid & 31;
    const int wm = wid >> 1, wn = wid & 1;
    const uint32_t stage = sb + s * SSTAGE;

    const int a_moff = ((lane >> 3) & 1) * 8 + (lane & 7);
    const int a_kb   = ((lane >> 4) & 1) * 16;
    const int b_noff = ((lane >> 4) & 1) * 8 + (lane & 7);
    const int b_kb   = ((lane >> 3) & 1) * 16;

    const uint32_t aBase = stage + (uint32_t)(wm * 32 + a_moff) * WROWB + a_kb;
    const uint32_t bBase = stage + S_BHI + (uint32_t)(wn * 128 + b_noff) * WROWB + b_kb;

#pragma unroll
    for (int ks = 0; ks < 2; ++ks) {
        const uint32_t ko = ks * 32;
        uint32_t ah[2][4], al[2][4];
#pragma unroll
        for (int mt = 0; mt < 2; ++mt) {
            const uint32_t a0 = aBase + mt * (16 * WROWB) + ko;
            ldsm4(ah[mt][0], ah[mt][1], ah[mt][2], ah[mt][3], a0);
            ldsm4(al[mt][0], al[mt][1], al[mt][2], al[mt][3], a0 + S_ALO);
        }
#pragma unroll
        for (int p = 0; p < 8; ++p) {
            uint32_t bh0, bh1, bh2, bh3, bl0, bl1, bl2, bl3;
            const uint32_t b0 = bBase + p * (16 * WROWB) + ko;
            ldsm4(bh0, bh1, bh2, bh3, b0);
            ldsm4(bl0, bl1, bl2, bl3, b0 + (S_BLO - S_BHI));
#pragma unroll
            for (int mt = 0; mt < 2; ++mt) {
                mma16816(acc[mt][2*p],   ah[mt][0], ah[mt][1], ah[mt][2], ah[mt][3], bh0, bh1);
                mma16816(acc[mt][2*p],   ah[mt][0], ah[mt][1], ah[mt][2], ah[mt][3], bl0, bl1);
                mma16816(acc[mt][2*p],   al[mt][0], al[mt][1], al[mt][2], al[mt][3], bh0, bh1);
                mma16816(acc[mt][2*p+1], ah[mt][0], ah[mt][1], ah[mt][2], ah[mt][3], bh2, bh3);
                mma16816(acc[mt][2*p+1], ah[mt][0], ah[mt][1], ah[mt][2], ah[mt][3], bl2, bl3);
                mma16816(acc[mt][2*p+1], al[mt][0], al[mt][1], al[mt][2], al[mt][3], bh2, bh3);
            }
        }
    }
}

__global__ __launch_bounds__(256, 1) void att_scores_mma(const int* __restrict__ roi)
{
    extern __shared__ char smem[];
    __shared__ int roi_s[256];
    const uint32_t sb = smem_u32(smem);
    const int tid = threadIdx.x;
    const int ib  = blockIdx.x * 128;
    const int loc = blockIdx.y;

    if (tid < 256) roi_s[tid] = roi[tid];

    float acc[2][16][4];
#pragma unroll
    for (int a = 0; a < 2; a++)
#pragma unroll
        for (int b = 0; b < 16; b++)
#pragma unroll
            for (int c = 0; c < 4; c++) acc[a][b][c] = 0.f;

    sload_stage(sb, 0, 0, loc, ib, tid); cp_commit();
    sload_stage(sb, 1, 1, loc, ib, tid); cp_commit();
    for (int c = 0; c < 16; ++c) {
        cp_wait1();
        __syncthreads();
        scompute_stage(sb, c & 1, acc, tid);
        __syncthreads();
        if (c + 2 < 16)
            sload_stage(sb, c & 1, c + 2, loc, ib, tid);
        cp_commit();
    }
    __syncthreads();

    const int wid = tid >> 5, lane = tid & 31;
    const int wm = wid >> 1, wn = wid & 1;
    const int g = lane >> 2, q2 = (lane & 3) * 2;
#pragma unroll
    for (int m2 = 0; m2 < 2; m2++)
#pragma unroll
        for (int f = 0; f < 16; f++) {
            const int row = wm * 32 + m2 * 16 + g;
            const int col = wn * 128 + f * 8 + q2;
            const float* c = acc[m2][f];
            sts32f(sb + (uint32_t)((row)     * 260 + col)     * 4, c[0]);
            sts32f(sb + (uint32_t)((row)     * 260 + col + 1) * 4, c[1]);
            sts32f(sb + (uint32_t)((row + 8) * 260 + col)     * 4, c[2]);
            sts32f(sb + (uint32_t)((row + 8) * 260 + col + 1) * 4, c[3]);
        }
    __syncthreads();

    const float scale = 0.044194173824159216f;
#pragma unroll 1
    for (int rr = 0; rr < 16; rr++) {
        const int i = wid * 16 + rr;
        const int ri = roi_s[ib + i];
        float e[8];
        float m = -CUDART_INF_F;
#pragma unroll
        for (int jj = 0; jj < 8; jj++) {
            const int j = jj * 32 + lane;
            float v = (roi_s[j] == ri)
                    ? lds32f(sb + (uint32_t)(i * 260 + j) * 4) * scale
                    : -CUDART_INF_F;
            e[jj] = v;
            m = fmaxf(m, v);
        }
#pragma unroll
        for (int off = 16; off > 0; off >>= 1)
            m = fmaxf(m, __shfl_xor_sync(0xffffffffu, m, off));
        float s = 0.f;
#pragma unroll
        for (int jj = 0; jj < 8; jj++) { float t_ = __expf(e[jj] - m); e[jj] = t_; s += t_; }
#pragma unroll
        for (int off = 16; off > 0; off >>= 1)
            s += __shfl_xor_sync(0xffffffffu, s, off);
        const float inv = 1.f / s;
#pragma unroll
        for (int jj = 0; jj < 8; jj++) {
            const int j = jj * 32 + lane;
            g_att[((size_t)loc * NN + ib + i) * NN + j] = e[jj] * inv;
        }
    }
}

// ---------------------------------------------------------------------------
// virt = att @ v  (R8 FFMA version, PROVEN; reads float g_att, g_vA)
// ---------------------------------------------------------------------------
__global__ __launch_bounds__(256) void att_apply_kernel()
{
    __shared__ float as[32][33];
    __shared__ float vs[32][256];

    const int loc = blockIdx.x;
    const int it  = blockIdx.y >> 1;
    const int ct  = blockIdx.y & 1;
    const int ib  = it * 32;
    const int cb  = ct * 256;
    const int tid = threadIdx.x;
    const int ig  = tid >> 5;
    const int cg  = tid & 31;

    float acc[4][8];
#pragma unroll
    for (int ii = 0; ii < 4; ii++)
#pragma unroll
        for (int cc = 0; cc < 8; cc++) acc[ii][cc] = 0.f;

    for (int j0 = 0; j0 < NN; j0 += 32) {
        for (int idx = tid; idx < 32 * 32; idx += 256) {
            int i = idx >> 5, j = idx & 31;
            as[i][j] = g_att[((size_t)loc * NN + ib + i) * NN + j0 + j];
        }
        for (int idx = tid; idx < 32 * 256; idx += 256) {
            int j = idx >> 8, c = idx & 255;
            vs[j][c] = g_vA[((size_t)loc * NN + j0 + j) * CC + cb + c];
        }
        __syncthreads();

#pragma unroll 4
        for (int j = 0; j < 32; j++) {
            float vv[8];
#pragma unroll
            for (int cc = 0; cc < 8; cc++) vv[cc] = vs[j][cg + 32 * cc];
#pragma unroll
            for (int ii = 0; ii < 4; ii++) {
                float av = as[ig + 8 * ii][j];
#pragma unroll
                for (int cc = 0; cc < 8; cc++) acc[ii][cc] += av * vv[cc];
            }
        }
        __syncthreads();
    }

#pragma unroll
    for (int ii = 0; ii < 4; ii++) {
        const int i = ib + ig + 8 * ii;
#pragma unroll
        for (int cc = 0; cc < 8; cc++) {
            const int c = cb + cg + 32 * cc;
            g_virt[((size_t)i * CC + c) * THW + loc] = acc[ii][cc];
        }
    }
}

// ---------------------------------------------------------------------------
// GroupNorm: 8-way partial + finalize, on [n][c][loc].  (proven)
// ---------------------------------------------------------------------------
__global__ __launch_bounds__(256) void gn_partial_kernel()
{
    __shared__ float red[16];
    const int n  = blockIdx.x;
    const int ch = blockIdx.y;
    const int tid = threadIdx.x;
    const float* __restrict__ src = g_virt + (size_t)n * CC * THW + (size_t)ch * 16384;

    float s = 0.f, s2 = 0.f;
    for (int idx = tid; idx < 16384; idx += 256) {
        float v = src[idx];
        s += v; s2 += v * v;
    }
#pragma unroll
    for (int off = 16; off > 0; off >>= 1) {
        s  += __shfl_xor_sync(0xffffffffu, s,  off);
        s2 += __shfl_xor_sync(0xffffffffu, s2, off);
    }
    const int wid = tid >> 5, lane = tid & 31;
    if (lane == 0) { red[wid] = s; red[8 + wid] = s2; }
    __syncthreads();
    if (tid == 0) {
        float S = 0.f, S2 = 0.f;
#pragma unroll
        for (int w = 0; w < 8; w++) { S += red[w]; S2 += red[8 + w]; }
        g_psum[n][ch] = S;
        g_psum2[n][ch] = S2;
    }
}

__global__ void gn_final_kernel()
{
    const int n = threadIdx.x;
    float S = 0.f, S2 = 0.f;
#pragma unroll
    for (int w = 0; w < 8; w++) { S += g_psum[n][w]; S2 += g_psum2[n][w]; }
    const float M = (float)(CC * THW);
    float mu  = S / M;
    float var = S2 / M - mu * mu;
    g_mu[n]   = mu;
    g_rinv[n] = rsqrtf(var + 1e-5f);
}

// ---------------------------------------------------------------------------
extern "C" void kernel_launch(void* const* d_in, const int* in_sizes, int n_in,
                              void* d_out, int out_size)
{
    const float* x     = (const float*)d_in[0];
    const int*   roi   = (const int*)  d_in[1];
    const float* Wq    = (const float*)d_in[2];
    const float* Wk    = (const float*)d_in[3];
    const float* Wv    = (const float*)d_in[4];
    const float* Wc    = (const float*)d_in[5];
    const float* gamma = (const float*)d_in[6];
    const float* beta  = (const float*)d_in[7];
    float* out = (float*)d_out;

    cudaFuncSetAttribute(gemm_wino_kernel,
                         cudaFuncAttributeMaxDynamicSharedMemorySize, WSMEM);
    cudaFuncSetAttribute(att_scores_mma,
                         cudaFuncAttributeMaxDynamicSharedMemorySize, SSMEM);

    wtrans_kernel<<<4096, 256>>>(Wq, Wk, Wv, Wc);
    vtransx_kernel<<<dim3(1024, 8), 256>>>(x);
    gemm_wino_kernel<<<dim3(12, 32, PTS), 256, WSMEM>>>(0);
    outtrans_qkv_kernel<<<dim3(1024, 48), 256>>>();
    att_scores_mma<<<dim3(2, 256), 256, SSMEM>>>(roi);
    att_apply_kernel<<<dim3(256, 16), 256>>>();
    gn_partial_kernel<<<dim3(256, 8), 256>>>();
    gn_final_kernel<<<1, 256>>>();
    vtransc_kernel<<<dim3(1024, 8), 256>>>(gamma, beta);
    gemm_wino_kernel<<<dim3(4, 32, PTS), 256, WSMEM>>>(1);
    outtrans_c_kernel<<<dim3(1024, 16), 256>>>(x, out);
}

// round 16
// speedup vs baseline: 9.1368x; 1.1650x over previous
#include <cuda_runtime.h>
#include <cuda_bf16.h>
#include <math_constants.h>
#include <cstdint>

// Problem constants
#define NN     256
#define CC     512
#define THW    256
#define NT4    4096            // 256 n * 4 t * 4 tiles(4x4)
#define PTS    36              // 6x6 Winograd F(4x4,3x3) points
#define NCTHW  33554432

// ---------------------------------------------------------------------------
// Scratch (static __device__ arrays — allocation is forbidden)
// ---------------------------------------------------------------------------
__device__ __nv_bfloat16 g_qh[NCTHW], g_ql[NCTHW];   // [(loc*256+n)*512+c]
__device__ __nv_bfloat16 g_kh[NCTHW], g_kl[NCTHW];
__device__ float g_vA[NCTHW];                        // [(loc*256+n)*512+c]
__device__ float g_att[THW * NN * NN];               // [loc][i][j]
__device__ float g_virt[NCTHW];                      // [n][c][loc]
__device__ float g_psum[NN][8], g_psum2[NN][8];
__device__ float g_mu[NN], g_rinv[NN];

// Winograd operands. U: [pt][co][ci], V: [pt][tile][ci], M: [pt][tile][co]
__device__ __nv_bfloat16 g_Ux_hi[(size_t)PTS * 1536 * 512];
__device__ __nv_bfloat16 g_Ux_lo[(size_t)PTS * 1536 * 512];
__device__ __nv_bfloat16 g_Uc_hi[(size_t)PTS * 512 * 512];
__device__ __nv_bfloat16 g_Uc_lo[(size_t)PTS * 512 * 512];
__device__ __nv_bfloat16 g_Vx_hi[(size_t)PTS * NT4 * 512];
__device__ __nv_bfloat16 g_Vx_lo[(size_t)PTS * NT4 * 512];
__device__ __nv_bfloat16 g_Vc_hi[(size_t)PTS * NT4 * 512];
__device__ __nv_bfloat16 g_Vc_lo[(size_t)PTS * NT4 * 512];
__device__ float g_M[(size_t)PTS * NT4 * 1536];      // [pt][tile][co]

// ---------------------------------------------------------------------------
// Portable-ISA helpers
// ---------------------------------------------------------------------------
__device__ __forceinline__ uint32_t smem_u32(const void* p) {
    uint32_t a;
    asm("{ .reg .u64 t; cvta.to.shared.u64 t, %1; cvt.u32.u64 %0, t; }"
        : "=r"(a) : "l"(p));
    return a;
}
__device__ __forceinline__ void cp16(uint32_t dst, const void* src) {
    asm volatile("cp.async.cg.shared.global [%0], [%1], 16;" :: "r"(dst), "l"(src));
}
__device__ __forceinline__ void cp_commit() { asm volatile("cp.async.commit_group;"); }
__device__ __forceinline__ void cp_wait1()  { asm volatile("cp.async.wait_group 1;" ::: "memory"); }

__device__ __forceinline__ void ldsm4(uint32_t& r0, uint32_t& r1, uint32_t& r2,
                                      uint32_t& r3, uint32_t addr) {
    asm volatile("ldmatrix.sync.aligned.m8n8.x4.shared.b16 {%0,%1,%2,%3}, [%4];"
        : "=r"(r0), "=r"(r1), "=r"(r2), "=r"(r3) : "r"(addr));
}
__device__ __forceinline__ void sts32f(uint32_t a, float v) {
    asm volatile("st.shared.f32 [%0], %1;" :: "r"(a), "f"(v));
}
__device__ __forceinline__ float lds32f(uint32_t a) {
    float v; asm volatile("ld.shared.f32 %0, [%1];" : "=f"(v) : "r"(a)); return v;
}
__device__ __forceinline__ void mma16816(float* c,
    uint32_t a0, uint32_t a1, uint32_t a2, uint32_t a3, uint32_t b0, uint32_t b1) {
    asm volatile("mma.sync.aligned.m16n8k16.row.col.f32.bf16.bf16.f32 "
        "{%0,%1,%2,%3}, {%4,%5,%6,%7}, {%8,%9}, {%0,%1,%2,%3};"
        : "+f"(c[0]), "+f"(c[1]), "+f"(c[2]), "+f"(c[3])
        : "r"(a0), "r"(a1), "r"(a2), "r"(a3), "r"(b0), "r"(b1));
}
__device__ __forceinline__ void bfsplit(float v, __nv_bfloat16& hi, __nv_bfloat16& lo) {
    hi = __float2bfloat16_rn(v);
    lo = __float2bfloat16_rn(v - __bfloat162float(hi));
}

// ---------------------------------------------------------------------------
// Weight transform F(4x4,3x3): U = G g G^T (6x6) per (co2, ci).
// ---------------------------------------------------------------------------
__global__ __launch_bounds__(256) void wtrans_kernel(
    const float* __restrict__ Wq, const float* __restrict__ Wk,
    const float* __restrict__ Wv, const float* __restrict__ Wc)
{
    const int idx = blockIdx.x * 256 + threadIdx.x;   // 2048*512
    const int ci  = idx & 511;
    const int co2 = idx >> 9;
    const float* Wp;
    int co;
    if (co2 < 512)       { Wp = Wq; co = co2; }
    else if (co2 < 1024) { Wp = Wk; co = co2 - 512; }
    else if (co2 < 1536) { Wp = Wv; co = co2 - 1024; }
    else                 { Wp = Wc; co = co2 - 1536; }

    float g[3][3];
#pragma unroll
    for (int r = 0; r < 3; r++)
#pragma unroll
        for (int c = 0; c < 3; c++)
            g[r][c] = Wp[((size_t)co * 512 + ci) * 9 + r * 3 + c];

    const float c6 = 1.f / 6.f, c12 = 1.f / 12.f, c24 = 1.f / 24.f;
    float gg[6][3];
#pragma unroll
    for (int c = 0; c < 3; c++) {
        gg[0][c] = 0.25f * g[0][c];
        gg[1][c] = -c6 * (g[0][c] + g[1][c] + g[2][c]);
        gg[2][c] =  c6 * (-g[0][c] + g[1][c] - g[2][c]);
        gg[3][c] = c24 * g[0][c] + c12 * g[1][c] + c6 * g[2][c];
        gg[4][c] = c24 * g[0][c] - c12 * g[1][c] + c6 * g[2][c];
        gg[5][c] = g[2][c];
    }
#pragma unroll
    for (int r = 0; r < 6; r++) {
        float u[6];
        u[0] = 0.25f * gg[r][0];
        u[1] = -c6 * (gg[r][0] + gg[r][1] + gg[r][2]);
        u[2] =  c6 * (-gg[r][0] + gg[r][1] - gg[r][2]);
        u[3] = c24 * gg[r][0] + c12 * gg[r][1] + c6 * gg[r][2];
        u[4] = c24 * gg[r][0] - c12 * gg[r][1] + c6 * gg[r][2];
        u[5] = gg[r][2];
#pragma unroll
        for (int c = 0; c < 6; c++) {
            const int pt = r * 6 + c;
            __nv_bfloat16 hi, lo;
            bfsplit(u[c], hi, lo);
            if (co2 < 1536) {
                const size_t o = ((size_t)pt * 1536 + co2) * 512 + ci;
                g_Ux_hi[o] = hi; g_Ux_lo[o] = lo;
            } else {
                const size_t o = ((size_t)pt * 512 + co) * 512 + ci;
                g_Uc_hi[o] = hi; g_Uc_lo[o] = lo;
            }
        }
    }
}

// ---------------------------------------------------------------------------
// Input transform core: V = B^T d B (6x6).
// ---------------------------------------------------------------------------
__device__ __forceinline__ void vtrans6(const float d[6][6], float v[6][6])
{
    float t[6][6];
#pragma unroll
    for (int j = 0; j < 6; j++) {
        t[0][j] = 4.f * d[0][j] - 5.f * d[2][j] + d[4][j];
        t[1][j] = -4.f * d[1][j] - 4.f * d[2][j] + d[3][j] + d[4][j];
        t[2][j] =  4.f * d[1][j] - 4.f * d[2][j] - d[3][j] + d[4][j];
        t[3][j] = -2.f * d[1][j] - d[2][j] + 2.f * d[3][j] + d[4][j];
        t[4][j] =  2.f * d[1][j] - d[2][j] - 2.f * d[3][j] + d[4][j];
        t[5][j] =  4.f * d[1][j] - 5.f * d[3][j] + d[5][j];
    }
#pragma unroll
    for (int i = 0; i < 6; i++) {
        v[i][0] = 4.f * t[i][0] - 5.f * t[i][2] + t[i][4];
        v[i][1] = -4.f * t[i][1] - 4.f * t[i][2] + t[i][3] + t[i][4];
        v[i][2] =  4.f * t[i][1] - 4.f * t[i][2] - t[i][3] + t[i][4];
        v[i][3] = -2.f * t[i][1] - t[i][2] + 2.f * t[i][3] + t[i][4];
        v[i][4] =  2.f * t[i][1] - t[i][2] - 2.f * t[i][3] + t[i][4];
        v[i][5] =  4.f * t[i][1] - 5.f * t[i][3] + t[i][5];
    }
}

__device__ __forceinline__ void vtrans_body(
    const float* xs, int ci0, int tb,
    __nv_bfloat16* __restrict__ Vh, __nv_bfloat16* __restrict__ Vl)
{
    const int tid = threadIdx.x;
    const int ci = tid & 63;
    const int tile = tid >> 6;          // 0..3
    const int ty = tile >> 1, tx = tile & 1;

    float d[6][6];
#pragma unroll
    for (int r = 0; r < 6; r++)
#pragma unroll
        for (int c = 0; c < 6; c++)
            d[r][c] = xs[ci * 101 + (ty * 4 + r) * 10 + (tx * 4 + c)];

    float v[6][6];
    vtrans6(d, v);

#pragma unroll
    for (int i = 0; i < 6; i++)
#pragma unroll
        for (int j = 0; j < 6; j++) {
            const int pt = i * 6 + j;
            __nv_bfloat16 hi, lo;
            bfsplit(v[i][j], hi, lo);
            const size_t o = ((size_t)pt * NT4 + tb + tile) * 512 + ci0 + ci;
            Vh[o] = hi; Vl[o] = lo;
        }
}

// Input transform of x. grid (1024 = n*t, 8 ci-chunks of 64), block 256.
__global__ __launch_bounds__(256) void vtransx_kernel(const float* __restrict__ x)
{
    __shared__ float xs[64 * 101];
    const int nt = blockIdx.x;
    const int n  = nt >> 2;
    const int t  = nt & 3;
    const int ci0 = blockIdx.y * 64;
    const int tid = threadIdx.x;

    for (int idx = tid; idx < 6400; idx += 256) {
        const int i = idx / 100;
        const int rc = idx % 100;
        const int r = rc / 10, c = rc % 10;
        const int hh = r - 1, ww = c - 1;
        float v = 0.f;
        if (hh >= 0 && hh < 8 && ww >= 0 && ww < 8)
            v = x[((size_t)(n * 512 + ci0 + i)) * 256 + t * 64 + hh * 8 + ww];
        xs[i * 101 + r * 10 + c] = v;
    }
    __syncthreads();
    vtrans_body(xs, ci0, nt * 4, g_Vx_hi, g_Vx_lo);
}

// Input transform of GN(virt)+ReLU. virt is [n][c][loc]. grid (1024, 8).
__global__ __launch_bounds__(256) void vtransc_kernel(
    const float* __restrict__ gamma, const float* __restrict__ beta)
{
    __shared__ float xs[64 * 101];
    const int nt = blockIdx.x;
    const int n  = nt >> 2;
    const int t  = nt & 3;
    const int ci0 = blockIdx.y * 64;
    const int tid = threadIdx.x;
    const float mu = g_mu[n], ri = g_rinv[n];

    for (int idx = tid; idx < 6400; idx += 256) {
        const int i = idx / 100;
        const int rc = idx % 100;
        const int r = rc / 10, c = rc % 10;
        const int hh = r - 1, ww = c - 1;
        float v = 0.f;
        if (hh >= 0 && hh < 8 && ww >= 0 && ww < 8) {
            float u = g_virt[((size_t)(n * 512 + ci0 + i)) * 256 + t * 64 + hh * 8 + ww];
            u = (u - mu) * ri * gamma[ci0 + i] + beta[ci0 + i];
            v = fmaxf(u, 0.f);
        }
        xs[i * 101 + r * 10 + c] = v;
    }
    __syncthreads();
    vtrans_body(xs, ci0, nt * 4, g_Vc_hi, g_Vc_lo);
}

// ---------------------------------------------------------------------------
// Proven 128x128 3-product GEMM machinery.
// ---------------------------------------------------------------------------
#define WROWB   80
#define WA_LO   10240
#define WB_HI   20480
#define WB_LO   30720
#define WSTAGE  40960
#define WSMEM   81920
#define WKCH    16

__device__ __forceinline__ void wload_stage_g(
    uint32_t sb, int s, int chunk, int rowlen,
    const __nv_bfloat16* __restrict__ Ah, const __nv_bfloat16* __restrict__ Al,
    const __nv_bfloat16* __restrict__ Bh, const __nv_bfloat16* __restrict__ Bl,
    int tid)
{
    const int k0 = chunk * 32;
    const uint32_t base = sb + s * WSTAGE;
#pragma unroll
    for (int it = 0; it < 2; ++it) {
        const int idx = tid + it * 256;
        const int row = idx >> 2, part = idx & 3;
        const uint32_t so = row * WROWB + part * 16;
        const size_t g = (size_t)row * rowlen + k0 + part * 8;
        cp16(base + so,          Ah + g);
        cp16(base + WA_LO + so,  Al + g);
        cp16(base + WB_HI + so,  Bh + g);
        cp16(base + WB_LO + so,  Bl + g);
    }
}

__device__ __forceinline__ void wcompute_stage(uint32_t sb, int s,
                                               float acc[2][8][4], int tid)
{
    const int wid = tid >> 5, lane = tid & 31;
    const int wm = wid >> 1, wn = wid & 1;
    const uint32_t stage = sb + s * WSTAGE;

    const int a_moff = ((lane >> 3) & 1) * 8 + (lane & 7);
    const int a_kb   = ((lane >> 4) & 1) * 16;
    const int b_noff = ((lane >> 4) & 1) * 8 + (lane & 7);
    const int b_kb   = ((lane >> 3) & 1) * 16;

    const uint32_t aBase = stage + (uint32_t)(wm * 32 + a_moff) * WROWB + a_kb;
    const uint32_t bBase = stage + WB_HI + (uint32_t)(wn * 64 + b_noff) * WROWB + b_kb;

#pragma unroll
    for (int ks = 0; ks < 2; ++ks) {
        const uint32_t ko = ks * 32;
        uint32_t ah[2][4], al[2][4];
#pragma unroll
        for (int mt = 0; mt < 2; ++mt) {
            const uint32_t a0 = aBase + mt * (16 * WROWB) + ko;
            ldsm4(ah[mt][0], ah[mt][1], ah[mt][2], ah[mt][3], a0);
            ldsm4(al[mt][0], al[mt][1], al[mt][2], al[mt][3], a0 + WA_LO);
        }
#pragma unroll
        for (int p = 0; p < 4; ++p) {
            uint32_t bh0, bh1, bh2, bh3, bl0, bl1, bl2, bl3;
            const uint32_t b0 = bBase + p * (16 * WROWB) + ko;
            ldsm4(bh0, bh1, bh2, bh3, b0);
            ldsm4(bl0, bl1, bl2, bl3, b0 + (WB_LO - WB_HI));
#pragma unroll
            for (int mt = 0; mt < 2; ++mt) {
                mma16816(acc[mt][2*p],   ah[mt][0], ah[mt][1], ah[mt][2], ah[mt][3], bh0, bh1);
                mma16816(acc[mt][2*p],   ah[mt][0], ah[mt][1], ah[mt][2], ah[mt][3], bl0, bl1);
                mma16816(acc[mt][2*p],   al[mt][0], al[mt][1], al[mt][2], al[mt][3], bh0, bh1);
                mma16816(acc[mt][2*p+1], ah[mt][0], ah[mt][1], ah[mt][2], ah[mt][3], bh2, bh3);
                mma16816(acc[mt][2*p+1], ah[mt][0], ah[mt][1], ah[mt][2], ah[mt][3], bl2, bl3);
                mma16816(acc[mt][2*p+1], al[mt][0], al[mt][1], al[mt][2], al[mt][3], bh2, bh3);
            }
        }
    }
}

// ---------------------------------------------------------------------------
// Winograd point GEMM (proven): M[pt][tile][co] = V[pt] x U[pt] (K=512).
// ---------------------------------------------------------------------------
__global__ __launch_bounds__(256, 2) void gemm_wino_kernel(int which)
{
    extern __shared__ char smem[];
    const uint32_t sb = smem_u32(smem);
    const int tid = threadIdx.x;
    const int mt = blockIdx.x;
    const int nb = blockIdx.y * 128;
    const int pt = blockIdx.z;

    const __nv_bfloat16 *Uh, *Ul, *Vh, *Vl;
    int mrows;
    if (which == 0) {
        Uh = g_Ux_hi; Ul = g_Ux_lo; Vh = g_Vx_hi; Vl = g_Vx_lo; mrows = 1536;
    } else {
        Uh = g_Uc_hi; Ul = g_Uc_lo; Vh = g_Vc_hi; Vl = g_Vc_lo; mrows = 512;
    }

    const __nv_bfloat16* Ah = Uh + ((size_t)pt * mrows + mt * 128) * 512;
    const __nv_bfloat16* Al = Ul + ((size_t)pt * mrows + mt * 128) * 512;
    const __nv_bfloat16* Bh = Vh + ((size_t)pt * NT4 + nb) * 512;
    const __nv_bfloat16* Bl = Vl + ((size_t)pt * NT4 + nb) * 512;

    float acc[2][8][4];
#pragma unroll
    for (int a = 0; a < 2; a++)
#pragma unroll
        for (int b = 0; b < 8; b++)
#pragma unroll
            for (int c = 0; c < 4; c++) acc[a][b][c] = 0.f;

    wload_stage_g(sb, 0, 0, 512, Ah, Al, Bh, Bl, tid); cp_commit();
    wload_stage_g(sb, 1, 1, 512, Ah, Al, Bh, Bl, tid); cp_commit();
    for (int c = 0; c < WKCH; ++c) {
        cp_wait1();
        __syncthreads();
        wcompute_stage(sb, c & 1, acc, tid);
        __syncthreads();
        if (c + 2 < WKCH)
            wload_stage_g(sb, c & 1, c + 2, 512, Ah, Al, Bh, Bl, tid);
        cp_commit();
    }
    __syncthreads();

    const int wid = tid >> 5, lane = tid & 31;
    const int wm = wid >> 1, wn = wid & 1;
    const int g = lane >> 2, q2 = (lane & 3) * 2;
#pragma unroll
    for (int m2 = 0; m2 < 2; m2++)
#pragma unroll
        for (int nt = 0; nt < 8; nt++) {
            const int row = wm * 32 + m2 * 16 + g;          // co local
            const int col = wn * 64 + nt * 8 + q2;          // tile local
            const float* c = acc[m2][nt];
            sts32f(sb + (uint32_t)((col)     * 132 + row)     * 4, c[0]);
            sts32f(sb + (uint32_t)((col + 1) * 132 + row)     * 4, c[1]);
            sts32f(sb + (uint32_t)((col)     * 132 + row + 8) * 4, c[2]);
            sts32f(sb + (uint32_t)((col + 1) * 132 + row + 8) * 4, c[3]);
        }
    __syncthreads();

    for (int idx = tid; idx < 16384; idx += 256) {
        const int col = idx >> 7, m = idx & 127;
        g_M[((size_t)pt * NT4 + nb + col) * mrows + mt * 128 + m] =
            lds32f(sb + (uint32_t)(col * 132 + m) * 4);
    }
}

// ---------------------------------------------------------------------------
// Output transform (qkv): Y = A^T M A. No smem staging: each thread loads its
// 36 M values directly (warp: co 0..31 consecutive -> one 128B line per pt,
// 36 independent loads in flight). Branch uniform per block. Bit-identical
// arithmetic to the R13-passing version.
// ---------------------------------------------------------------------------
__device__ __forceinline__ void at_rows(const float m[6][6], int i, float s[6])
{
#pragma unroll
    for (int j = 0; j < 6; j++) {
        if (i == 0)      s[j] = m[0][j] + m[1][j] + m[2][j] + m[3][j] + m[4][j];
        else if (i == 1) s[j] = m[1][j] - m[2][j] + 2.f * (m[3][j] - m[4][j]);
        else if (i == 2) s[j] = m[1][j] + m[2][j] + 4.f * (m[3][j] + m[4][j]);
        else             s[j] = m[1][j] - m[2][j] + 8.f * (m[3][j] - m[4][j]) + m[5][j];
    }
}
__device__ __forceinline__ void at_cols(const float s[6], float y[4])
{
    y[0] = s[0] + s[1] + s[2] + s[3] + s[4];
    y[1] = s[1] - s[2] + 2.f * (s[3] - s[4]);
    y[2] = s[1] + s[2] + 4.f * (s[3] + s[4]);
    y[3] = s[1] - s[2] + 8.f * (s[3] - s[4]) + s[5];
}

__global__ __launch_bounds__(256) void outtrans_qkv_kernel()
{
    const int nt = blockIdx.x;
    const int n  = nt >> 2;
    const int t  = nt & 3;
    const int cobase = blockIdx.y * 32;
    const int which = cobase >> 9;        // 0=q 1=k 2=v, uniform per block
    const int tid = threadIdx.x;

    const int co = tid & 31;
    const int tg = tid >> 5;
    const int tile = tg & 3, half = tg >> 2;
    const int ty = tile >> 1, tx = tile & 1;
    const int co_in = (cobase + co) & 511;

    // direct coalesced loads: 36 independent 128B warp-lines
    float m[6][6];
#pragma unroll
    for (int pt = 0; pt < PTS; pt++)
        m[pt / 6][pt % 6] =
            g_M[((size_t)pt * NT4 + nt * 4 + tile) * 1536 + cobase + co];

    if (which < 2) {
        __nv_bfloat16* dh = which ? g_kh : g_qh;
        __nv_bfloat16* dl = which ? g_kl : g_ql;
#pragma unroll
        for (int ii = 0; ii < 2; ii++) {
            const int i = half * 2 + ii;
            float s[6], y[4];
            at_rows(m, i, s);
            at_cols(s, y);
            const int loc0 = t * 64 + (ty * 4 + i) * 8 + tx * 4;
#pragma unroll
            for (int k = 0; k < 4; k++) {
                __nv_bfloat16 hi, lo;
                bfsplit(y[k], hi, lo);
                const size_t o = ((size_t)(loc0 + k) * 256 + n) * 512 + co_in;
                dh[o] = hi; dl[o] = lo;
            }
        }
    } else {
#pragma unroll
        for (int ii = 0; ii < 2; ii++) {
            const int i = half * 2 + ii;
            float s[6], y[4];
            at_rows(m, i, s);
            at_cols(s, y);
            const int loc0 = t * 64 + (ty * 4 + i) * 8 + tx * 4;
#pragma unroll
            for (int k = 0; k < 4; k++) {
                const size_t o = ((size_t)(loc0 + k) * 256 + n) * 512 + co_in;
                g_vA[o] = y[k];
            }
        }
    }
}

// ---------------------------------------------------------------------------
// Output transform (conv_c) + residual -> d_out [n][co][loc].
// Same direct-load treatment; keeps ys staging for the coalesced final write.
// ---------------------------------------------------------------------------
__global__ __launch_bounds__(256) void outtrans_c_kernel(
    const float* __restrict__ x, float* __restrict__ out)
{
    __shared__ float ys[32][65];
    const int nt = blockIdx.x;
    const int n  = nt >> 2;
    const int t  = nt & 3;
    const int cobase = blockIdx.y * 32;
    const int tid = threadIdx.x;

    const int co = tid & 31;
    const int tg = tid >> 5;
    const int tile = tg & 3, half = tg >> 2;
    const int ty = tile >> 1, tx = tile & 1;

    float m[6][6];
#pragma unroll
    for (int pt = 0; pt < PTS; pt++)
        m[pt / 6][pt % 6] =
            g_M[((size_t)pt * NT4 + nt * 4 + tile) * 512 + cobase + co];

#pragma unroll
    for (int ii = 0; ii < 2; ii++) {
        const int i = half * 2 + ii;
        float s[6], y[4];
        at_rows(m, i, s);
        at_cols(s, y);
        const int p0 = (ty * 4 + i) * 8 + tx * 4;
#pragma unroll
        for (int k = 0; k < 4; k++)
            ys[co][p0 + k] = y[k];
    }
    __syncthreads();

    for (int idx = tid; idx < 2048; idx += 256) {
        const int c = idx >> 6, l = idx & 63;
        const size_t o = ((size_t)(n * 512 + cobase + c)) * 256 + t * 64 + l;
        out[o] = x[o] + ys[c][l];
    }
}

// ---------------------------------------------------------------------------
// Attention scores on tensor pipe (proven). Writes FLOAT g_att.
// Block = (i-half, loc): M=128, N=256, K=512.
// ---------------------------------------------------------------------------
#define S_ALO  10240
#define S_BHI  20480
#define S_BLO  40960
#define SSTAGE 61440
#define SSMEM  133120

__device__ __forceinline__ void sload_stage(uint32_t sb, int s, int chunk,
                                            int loc, int ib, int tid)
{
    const int k0 = chunk * 32;
    const uint32_t base = sb + s * SSTAGE;
#pragma unroll
    for (int it = 0; it < 2; ++it) {
        const int idx = tid + it * 256;
        const int row = idx >> 2, part = idx & 3;
        const uint32_t so = row * WROWB + part * 16;
        const size_t g = ((size_t)(loc * 256 + ib + row)) * 512 + k0 + part * 8;
        cp16(base + so,         g_qh + g);
        cp16(base + S_ALO + so, g_ql + g);
    }
#pragma unroll
    for (int it = 0; it < 4; ++it) {
        const int idx = tid + it * 256;
        const int row = idx >> 2, part = idx & 3;
        const uint32_t so = row * WROWB + part * 16;
        const size_t g = ((size_t)(loc * 256 + row)) * 512 + k0 + part * 8;
        cp16(base + S_BHI + so, g_kh + g);
        cp16(base + S_BLO + so, g_kl + g);
    }
}

__device__ __forceinline__ void scompute_stage(uint32_t sb, int s,
                                               float acc[2][16][4], int tid)
{
    const int wid = tid >> 5, lane = tid & 31;
    const int wm = wid >> 1, wn = wid & 1;
    const uint32_t stage = sb + s * SSTAGE;

    const int a_moff = ((lane >> 3) & 1) * 8 + (lane & 7);
    const int a_kb   = ((lane >> 4) & 1) * 16;
    const int b_noff = ((lane >> 4) & 1) * 8 + (lane & 7);
    const int b_kb   = ((lane >> 3) & 1) * 16;

    const uint32_t aBase = stage + (uint32_t)(wm * 32 + a_moff) * WROWB + a_kb;
    const uint32_t bBase = stage + S_BHI + (uint32_t)(wn * 128 + b_noff) * WROWB + b_kb;

#pragma unroll
    for (int ks = 0; ks < 2; ++ks) {
        const uint32_t ko = ks * 32;
        uint32_t ah[2][4], al[2][4];
#pragma unroll
        for (int mt = 0; mt < 2; ++mt) {
            const uint32_t a0 = aBase + mt * (16 * WROWB) + ko;
            ldsm4(ah[mt][0], ah[mt][1], ah[mt][2], ah[mt][3], a0);
            ldsm4(al[mt][0], al[mt][1], al[mt][2], al[mt][3], a0 + S_ALO);
        }
#pragma unroll
        for (int p = 0; p < 8; ++p) {
            uint32_t bh0, bh1, bh2, bh3, bl0, bl1, bl2, bl3;
            const uint32_t b0 = bBase + p * (16 * WROWB) + ko;
            ldsm4(bh0, bh1, bh2, bh3, b0);
            ldsm4(bl0, bl1, bl2, bl3, b0 + (S_BLO - S_BHI));
#pragma unroll
            for (int mt = 0; mt < 2; ++mt) {
                mma16816(acc[mt][2*p],   ah[mt][0], ah[mt][1], ah[mt][2], ah[mt][3], bh0, bh1);
                mma16816(acc[mt][2*p],   ah[mt][0], ah[mt][1], ah[mt][2], ah[mt][3], bl0, bl1);
                mma16816(acc[mt][2*p],   al[mt][0], al[mt][1], al[mt][2], al[mt][3], bh0, bh1);
                mma16816(acc[mt][2*p+1], ah[mt][0], ah[mt][1], ah[mt][2], ah[mt][3], bh2, bh3);
                mma16816(acc[mt][2*p+1], ah[mt][0], ah[mt][1], ah[mt][2], ah[mt][3], bl2, bl3);
                mma16816(acc[mt][2*p+1], al[mt][0], al[mt][1], al[mt][2], al[mt][3], bh2, bh3);
            }
        }
    }
}

__global__ __launch_bounds__(256, 1) void att_scores_mma(const int* __restrict__ roi)
{
    extern __shared__ char smem[];
    __shared__ int roi_s[256];
    const uint32_t sb = smem_u32(smem);
    const int tid = threadIdx.x;
    const int ib  = blockIdx.x * 128;
    const int loc = blockIdx.y;

    if (tid < 256) roi_s[tid] = roi[tid];

    float acc[2][16][4];
#pragma unroll
    for (int a = 0; a < 2; a++)
#pragma unroll
        for (int b = 0; b < 16; b++)
#pragma unroll
            for (int c = 0; c < 4; c++) acc[a][b][c] = 0.f;

    sload_stage(sb, 0, 0, loc, ib, tid); cp_commit();
    sload_stage(sb, 1, 1, loc, ib, tid); cp_commit();
    for (int c = 0; c < 16; ++c) {
        cp_wait1();
        __syncthreads();
        scompute_stage(sb, c & 1, acc, tid);
        __syncthreads();
        if (c + 2 < 16)
            sload_stage(sb, c & 1, c + 2, loc, ib, tid);
        cp_commit();
    }
    __syncthreads();

    const int wid = tid >> 5, lane = tid & 31;
    const int wm = wid >> 1, wn = wid & 1;
    const int g = lane >> 2, q2 = (lane & 3) * 2;
#pragma unroll
    for (int m2 = 0; m2 < 2; m2++)
#pragma unroll
        for (int f = 0; f < 16; f++) {
            const int row = wm * 32 + m2 * 16 + g;
            const int col = wn * 128 + f * 8 + q2;
            const float* c = acc[m2][f];
            sts32f(sb + (uint32_t)((row)     * 260 + col)     * 4, c[0]);
            sts32f(sb + (uint32_t)((row)     * 260 + col + 1) * 4, c[1]);
            sts32f(sb + (uint32_t)((row + 8) * 260 + col)     * 4, c[2]);
            sts32f(sb + (uint32_t)((row + 8) * 260 + col + 1) * 4, c[3]);
        }
    __syncthreads();

    const float scale = 0.044194173824159216f;
#pragma unroll 1
    for (int rr = 0; rr < 16; rr++) {
        const int i = wid * 16 + rr;
        const int ri = roi_s[ib + i];
        float e[8];
        float m = -CUDART_INF_F;
#pragma unroll
        for (int jj = 0; jj < 8; jj++) {
            const int j = jj * 32 + lane;
            float v = (roi_s[j] == ri)
                    ? lds32f(sb + (uint32_t)(i * 260 + j) * 4) * scale
                    : -CUDART_INF_F;
            e[jj] = v;
            m = fmaxf(m, v);
        }
#pragma unroll
        for (int off = 16; off > 0; off >>= 1)
            m = fmaxf(m, __shfl_xor_sync(0xffffffffu, m, off));
        float s = 0.f;
#pragma unroll
        for (int jj = 0; jj < 8; jj++) { float t_ = __expf(e[jj] - m); e[jj] = t_; s += t_; }
#pragma unroll
        for (int off = 16; off > 0; off >>= 1)
            s += __shfl_xor_sync(0xffffffffu, s, off);
        const float inv = 1.f / s;
#pragma unroll
        for (int jj = 0; jj < 8; jj++) {
            const int j = jj * 32 + lane;
            g_att[((size_t)loc * NN + ib + i) * NN + j] = e[jj] * inv;
        }
    }
}

// ---------------------------------------------------------------------------
// virt = att @ v  (R8 FFMA version, PROVEN; reads float g_att, g_vA)
// ---------------------------------------------------------------------------
__global__ __launch_bounds__(256) void att_apply_kernel()
{
    __shared__ float as[32][33];
    __shared__ float vs[32][256];

    const int loc = blockIdx.x;
    const int it  = blockIdx.y >> 1;
    const int ct  = blockIdx.y & 1;
    const int ib  = it * 32;
    const int cb  = ct * 256;
    const int tid = threadIdx.x;
    const int ig  = tid >> 5;
    const int cg  = tid & 31;

    float acc[4][8];
#pragma unroll
    for (int ii = 0; ii < 4; ii++)
#pragma unroll
        for (int cc = 0; cc < 8; cc++) acc[ii][cc] = 0.f;

    for (int j0 = 0; j0 < NN; j0 += 32) {
        for (int idx = tid; idx < 32 * 32; idx += 256) {
            int i = idx >> 5, j = idx & 31;
            as[i][j] = g_att[((size_t)loc * NN + ib + i) * NN + j0 + j];
        }
        for (int idx = tid; idx < 32 * 256; idx += 256) {
            int j = idx >> 8, c = idx & 255;
            vs[j][c] = g_vA[((size_t)loc * NN + j0 + j) * CC + cb + c];
        }
        __syncthreads();

#pragma unroll 4
        for (int j = 0; j < 32; j++) {
            float vv[8];
#pragma unroll
            for (int cc = 0; cc < 8; cc++) vv[cc] = vs[j][cg + 32 * cc];
#pragma unroll
            for (int ii = 0; ii < 4; ii++) {
                float av = as[ig + 8 * ii][j];
#pragma unroll
                for (int cc = 0; cc < 8; cc++) acc[ii][cc] += av * vv[cc];
            }
        }
        __syncthreads();
    }

#pragma unroll
    for (int ii = 0; ii < 4; ii++) {
        const int i = ib + ig + 8 * ii;
#pragma unroll
        for (int cc = 0; cc < 8; cc++) {
            const int c = cb + cg + 32 * cc;
            g_virt[((size_t)i * CC + c) * THW + loc] = acc[ii][cc];
        }
    }
}

// ---------------------------------------------------------------------------
// GroupNorm: 8-way partial + finalize, on [n][c][loc].  (proven)
// ---------------------------------------------------------------------------
__global__ __launch_bounds__(256) void gn_partial_kernel()
{
    __shared__ float red[16];
    const int n  = blockIdx.x;
    const int ch = blockIdx.y;
    const int tid = threadIdx.x;
    const float* __restrict__ src = g_virt + (size_t)n * CC * THW + (size_t)ch * 16384;

    float s = 0.f, s2 = 0.f;
    for (int idx = tid; idx < 16384; idx += 256) {
        float v = src[idx];
        s += v; s2 += v * v;
    }
#pragma unroll
    for (int off = 16; off > 0; off >>= 1) {
        s  += __shfl_xor_sync(0xffffffffu, s,  off);
        s2 += __shfl_xor_sync(0xffffffffu, s2, off);
    }
    const int wid = tid >> 5, lane = tid & 31;
    if (lane == 0) { red[wid] = s; red[8 + wid] = s2; }
    __syncthreads();
    if (tid == 0) {
        float S = 0.f, S2 = 0.f;
#pragma unroll
        for (int w = 0; w < 8; w++) { S += red[w]; S2 += red[8 + w]; }
        g_psum[n][ch] = S;
        g_psum2[n][ch] = S2;
    }
}

__global__ void gn_final_kernel()
{
    const int n = threadIdx.x;
    float S = 0.f, S2 = 0.f;
#pragma unroll
    for (int w = 0; w < 8; w++) { S += g_psum[n][w]; S2 += g_psum2[n][w]; }
    const float M = (float)(CC * THW);
    float mu  = S / M;
    float var = S2 / M - mu * mu;
    g_mu[n]   = mu;
    g_rinv[n] = rsqrtf(var + 1e-5f);
}

// ---------------------------------------------------------------------------
extern "C" void kernel_launch(void* const* d_in, const int* in_sizes, int n_in,
                              void* d_out, int out_size)
{
    const float* x     = (const float*)d_in[0];
    const int*   roi   = (const int*)  d_in[1];
    const float* Wq    = (const float*)d_in[2];
    const float* Wk    = (const float*)d_in[3];
    const float* Wv    = (const float*)d_in[4];
    const float* Wc    = (const float*)d_in[5];
    const float* gamma = (const float*)d_in[6];
    const float* beta  = (const float*)d_in[7];
    float* out = (float*)d_out;

    cudaFuncSetAttribute(gemm_wino_kernel,
                         cudaFuncAttributeMaxDynamicSharedMemorySize, WSMEM);
    cudaFuncSetAttribute(att_scores_mma,
                         cudaFuncAttributeMaxDynamicSharedMemorySize, SSMEM);

    wtrans_kernel<<<4096, 256>>>(Wq, Wk, Wv, Wc);
    vtransx_kernel<<<dim3(1024, 8), 256>>>(x);
    gemm_wino_kernel<<<dim3(12, 32, PTS), 256, WSMEM>>>(0);
    outtrans_qkv_kernel<<<dim3(1024, 48), 256>>>();
    att_scores_mma<<<dim3(2, 256), 256, SSMEM>>>(roi);
    att_apply_kernel<<<dim3(256, 16), 256>>>();
    gn_partial_kernel<<<dim3(256, 8), 256>>>();
    gn_final_kernel<<<1, 256>>>();
    vtransc_kernel<<<dim3(1024, 8), 256>>>(gamma, beta);
    gemm_wino_kernel<<<dim3(4, 32, PTS), 256, WSMEM>>>(1);
    outtrans_c_kernel<<<dim3(1024, 16), 256>>>(x, out);
}